// round 5
// baseline (speedup 1.0000x reference)
#include <cuda_runtime.h>
#include <math.h>
#include <stdint.h>

// ---------------- problem constants ----------------
#define T_TOK   32768
#define D_DIM   1024
#define E_EXP   16
#define I_DIM   2816
#define TWO_I   5632
#define TK_SLOTS 65536
#define CAP     5120
#define NB      64
#define SPB     1024

// ---------------- scratch (device globals; no allocs) ----------------
__device__ float g_expert_in[(size_t)E_EXP * CAP * D_DIM];   // tf32-rounded
__device__ float g_h[(size_t)E_EXP * CAP * TWO_I];           // fp32
__device__ float g_eout[(size_t)E_EXP * CAP * D_DIM];
__device__ float g_wug_t[(size_t)E_EXP * TWO_I * D_DIM];     // tf32-rounded, [E][2I][D]
__device__ float g_wdn_t[(size_t)E_EXP * D_DIM * I_DIM];     // tf32-rounded, [E][D][I]
__device__ int   g_sel[TK_SLOTS];
__device__ float g_comb[TK_SLOTS];
__device__ int   g_poslocal[TK_SLOTS];
__device__ int   g_slot[TK_SLOTS];
__device__ int   g_blkCnt[NB][E_EXP];
__device__ int   g_blkOff[NB][E_EXP];
__device__ int   g_cnt[E_EXP];
__device__ float g_sumprobs[E_EXP];
__device__ float g_z2;

// ---------------- helpers ----------------
__device__ __forceinline__ uint32_t f2tf32(float f) {
    uint32_t r;
    asm("cvt.rna.tf32.f32 %0, %1;" : "=r"(r) : "f"(f));
    return r;
}
__device__ __forceinline__ float tf32r(float f) { return __uint_as_float(f2tf32(f)); }

__device__ __forceinline__ void mma_tf32(float* c,
                                         uint32_t a0, uint32_t a1, uint32_t a2, uint32_t a3,
                                         uint32_t b0, uint32_t b1) {
    asm volatile("mma.sync.aligned.m16n8k8.row.col.f32.tf32.tf32.f32 "
                 "{%0,%1,%2,%3}, {%4,%5,%6,%7}, {%8,%9}, {%0,%1,%2,%3};"
                 : "+f"(c[0]), "+f"(c[1]), "+f"(c[2]), "+f"(c[3])
                 : "r"(a0), "r"(a1), "r"(a2), "r"(a3), "r"(b0), "r"(b1));
}
__device__ __forceinline__ uint32_t smem_u32(const void* p) {
    uint32_t a;
    asm("{ .reg .u64 t; cvta.to.shared.u64 t, %1; cvt.u32.u64 %0, t; }" : "=r"(a) : "l"(p));
    return a;
}
#define CP_ASYNC16(dst_u32, src_ptr) \
    asm volatile("cp.async.cg.shared.global [%0], [%1], 16;" :: "r"(dst_u32), "l"(src_ptr))
#define CP_COMMIT() asm volatile("cp.async.commit_group;")
#define CP_WAIT1()  asm volatile("cp.async.wait_group 1;")

// ---------------- stats zeroing ----------------
__global__ void zero_stats_kernel() {
    if (threadIdx.x < E_EXP) g_sumprobs[threadIdx.x] = 0.f;
    if (threadIdx.x == 0)    g_z2 = 0.f;
}

// ---------------- router: SMEM-cached weights, 32 tokens/block ----------------
#define R_PAD 20
#define R_SMEM_BYTES (D_DIM * R_PAD * 4)
__global__ __launch_bounds__(256) void router_kernel(const float* __restrict__ x,
                                                     const float* __restrict__ router) {
    extern __shared__ float rs[];          // [D_DIM][R_PAD]
    __shared__ float s_p[E_EXP];
    __shared__ float s_z2;
    const int tid  = threadIdx.x;
    const int wid  = tid >> 5;
    const int lane = tid & 31;
    if (tid < E_EXP) s_p[tid] = 0.f;
    if (tid == 0)    s_z2 = 0.f;
    for (int t = tid; t < D_DIM * E_EXP; t += 256)
        rs[(t >> 4) * R_PAD + (t & 15)] = router[t];
    __syncthreads();

    #pragma unroll
    for (int j = 0; j < 4; j++) {
        const int tok = blockIdx.x * 32 + wid * 4 + j;
        const float* xr = x + (size_t)tok * D_DIM;
        float acc[E_EXP];
        #pragma unroll
        for (int e = 0; e < E_EXP; e++) acc[e] = 0.f;
        for (int i = lane; i < D_DIM; i += 32) {
            const float xv = xr[i];
            const float4* rp = (const float4*)&rs[i * R_PAD];
            float4 r0 = rp[0], r1 = rp[1], r2 = rp[2], r3 = rp[3];
            acc[0]  += xv * r0.x; acc[1]  += xv * r0.y; acc[2]  += xv * r0.z; acc[3]  += xv * r0.w;
            acc[4]  += xv * r1.x; acc[5]  += xv * r1.y; acc[6]  += xv * r1.z; acc[7]  += xv * r1.w;
            acc[8]  += xv * r2.x; acc[9]  += xv * r2.y; acc[10] += xv * r2.z; acc[11] += xv * r2.w;
            acc[12] += xv * r3.x; acc[13] += xv * r3.y; acc[14] += xv * r3.z; acc[15] += xv * r3.w;
        }
        #pragma unroll
        for (int off = 16; off; off >>= 1) {
            #pragma unroll
            for (int e = 0; e < E_EXP; e++)
                acc[e] += __shfl_xor_sync(0xffffffffu, acc[e], off);
        }
        float m = acc[0];
        #pragma unroll
        for (int e = 1; e < E_EXP; e++) m = fmaxf(m, acc[e]);
        float se = 0.f;
        #pragma unroll
        for (int e = 0; e < E_EXP; e++) se += expf(acc[e] - m);
        const float z = m + logf(se);

        int i1 = 0; float l1 = acc[0];
        #pragma unroll
        for (int e = 1; e < E_EXP; e++) if (acc[e] > l1) { l1 = acc[e]; i1 = e; }
        int i2 = -1; float l2 = -1e30f;
        #pragma unroll
        for (int e = 0; e < E_EXP; e++)
            if (e != i1 && acc[e] > l2) { l2 = acc[e]; i2 = e; }

        const float q  = expf(l2 - l1);
        if (lane == 0) {
            g_sel[2 * tok]     = i1;
            g_sel[2 * tok + 1] = i2;
            g_comb[2 * tok]     = 1.f / (1.f + q);
            g_comb[2 * tok + 1] = q / (1.f + q);
            atomicAdd(&s_z2, z * z);
        }
        if (lane < E_EXP) atomicAdd(&s_p[lane], expf(acc[lane] - m) / se);
    }
    __syncthreads();
    if (tid < E_EXP) atomicAdd(&g_sumprobs[tid], s_p[tid]);
    if (tid == 0)    atomicAdd(&g_z2, s_z2);
}

// ---------------- ordered per-expert rank ----------------
__global__ void pos_kernel() {
    __shared__ int warpCnt[8][E_EXP];
    __shared__ int running[E_EXP];
    const int tid  = threadIdx.x;
    const int wid  = tid >> 5;
    const int lane = tid & 31;
    if (tid < E_EXP) running[tid] = 0;
    __syncthreads();

    const int base = blockIdx.x * SPB;
    for (int it = 0; it < SPB / 256; it++) {
        const int s = base + it * 256 + tid;
        const int e = g_sel[s];
        unsigned peers = __match_any_sync(0xffffffffu, e);
        const int rank = __popc(peers & ((1u << lane) - 1u));
        if (lane < E_EXP) warpCnt[wid][lane] = 0;
        __syncwarp();
        if (rank == 0) warpCnt[wid][e] = __popc(peers);
        __syncthreads();
        int off = running[e] + rank;
        for (int w = 0; w < wid; w++) off += warpCnt[w][e];
        g_poslocal[s] = off;
        __syncthreads();
        if (tid < E_EXP) {
            int tot = 0;
            #pragma unroll
            for (int w = 0; w < 8; w++) tot += warpCnt[w][tid];
            running[tid] += tot;
        }
        __syncthreads();
    }
    if (tid < E_EXP) g_blkCnt[blockIdx.x][tid] = running[tid];
}

__global__ void scan_kernel() {
    const int e = threadIdx.x;
    if (e >= E_EXP) return;
    int run = 0;
    for (int b = 0; b < NB; b++) {
        g_blkOff[b][e] = run;
        run += g_blkCnt[b][e];
    }
    g_cnt[e] = run;
}

// ---------------- scatter (pre-rounds x to tf32) ----------------
__global__ void scatter_kernel(const float* __restrict__ x) {
    const int gwarp = (blockIdx.x * blockDim.x + threadIdx.x) >> 5;
    const int lane  = threadIdx.x & 31;
    if (gwarp >= TK_SLOTS) return;
    const int e   = g_sel[gwarp];
    const int pos = g_poslocal[gwarp] + g_blkOff[gwarp / SPB][e];
    int slot = -1;
    if (pos < CAP) {
        slot = e * CAP + pos;
        const float4* src = (const float4*)(x + (size_t)(gwarp >> 1) * D_DIM);
        float4* dst = (float4*)(g_expert_in + (size_t)slot * D_DIM);
        #pragma unroll
        for (int i = 0; i < 8; i++) {
            float4 v = src[lane + 32 * i];
            dst[lane + 32 * i] = make_float4(tf32r(v.x), tf32r(v.y), tf32r(v.z), tf32r(v.w));
        }
    }
    if (lane == 0) g_slot[gwarp] = slot;
}

// ---------------- weight transpose + tf32 pre-round ----------------
__global__ void transpose_kernel(const float* __restrict__ src, float* __restrict__ dst,
                                 int R, int Cd) {
    __shared__ float tile[32][33];
    const size_t eoff = (size_t)blockIdx.z * R * Cd;
    const float* S = src + eoff;
    float* Dp = dst + eoff;
    const int c0 = blockIdx.x * 32, r0 = blockIdx.y * 32;
    const int tx = threadIdx.x, ty = threadIdx.y;
    #pragma unroll
    for (int i = 0; i < 32; i += 8)
        tile[ty + i][tx] = tf32r(S[(size_t)(r0 + ty + i) * Cd + (c0 + tx)]);
    __syncthreads();
    #pragma unroll
    for (int i = 0; i < 32; i += 8)
        Dp[(size_t)(c0 + ty + i) * R + (r0 + tx)] = tile[tx][ty + i];
}

// ---------------- GEMM1: expert_in[128,1024] x wug_t -> g_h, cp.async 3-stage ----------------
#define SM_STRIDE 36
#define TILE_F (128 * SM_STRIDE)          // 4608 floats
#define G1_SMEM (3 * 2 * TILE_F * 4)      // 110592 B

__global__ __launch_bounds__(256) void g1_kernel(const float* __restrict__ Wt) {
    const int e   = blockIdx.z;
    const int cnt = g_cnt[e];
    const int m0  = blockIdx.y * 128;
    if (m0 >= cnt) return;
    const int n0  = blockIdx.x * 128;

    const float* __restrict__ A = g_expert_in + (size_t)e * CAP * D_DIM + (size_t)m0 * D_DIM;
    const float* __restrict__ B = Wt + (size_t)e * TWO_I * D_DIM + (size_t)n0 * D_DIM;
    float*       __restrict__ C = g_h + (size_t)e * CAP * TWO_I + (size_t)m0 * TWO_I + n0;

    extern __shared__ float sm[];
    const int tid  = threadIdx.x;
    const int lane = tid & 31;
    const int wid  = tid >> 5;
    const int warp_m = (wid >> 2) * 64;
    const int warp_n = (wid & 3) * 32;
    const int g  = lane >> 2;
    const int t4 = lane & 3;
    const int lrow = tid >> 3;
    const int lc4  = (tid & 7) * 4;
    const int NC = D_DIM / 32;            // 32

    float acc[4][4][4];
    #pragma unroll
    for (int i = 0; i < 4; i++)
        #pragma unroll
        for (int j = 0; j < 4; j++)
            #pragma unroll
            for (int q = 0; q < 4; q++) acc[i][j][q] = 0.f;

    // issue chunk c into stage c%3 (always commits a group)
    #define G1_ISSUE(c_) do {                                                     \
        if ((c_) < NC) {                                                          \
            float* As_ = sm + ((c_) % 3) * (2 * TILE_F);                          \
            float* Bs_ = As_ + TILE_F;                                            \
            const int k0_ = (c_) * 32;                                            \
            _Pragma("unroll")                                                     \
            for (int i_ = 0; i_ < 4; i_++) {                                      \
                const int r_ = lrow + 32 * i_;                                    \
                CP_ASYNC16(smem_u32(&As_[r_ * SM_STRIDE + lc4]),                  \
                           A + (size_t)r_ * D_DIM + k0_ + lc4);                   \
                CP_ASYNC16(smem_u32(&Bs_[r_ * SM_STRIDE + lc4]),                  \
                           B + (size_t)r_ * D_DIM + k0_ + lc4);                   \
            }                                                                     \
        }                                                                         \
        CP_COMMIT();                                                              \
    } while (0)

    G1_ISSUE(0);
    G1_ISSUE(1);

    for (int c = 0; c < NC; c++) {
        CP_WAIT1();
        __syncthreads();
        G1_ISSUE(c + 2);
        const float* As = sm + (c % 3) * (2 * TILE_F);
        const float* Bs = As + TILE_F;
        #pragma unroll
        for (int ks = 0; ks < 4; ks++) {
            uint32_t bf[4][2];
            #pragma unroll
            for (int nf = 0; nf < 4; nf++) {
                const int n = warp_n + nf * 8 + g;
                bf[nf][0] = __float_as_uint(Bs[n * SM_STRIDE + ks * 8 + t4]);
                bf[nf][1] = __float_as_uint(Bs[n * SM_STRIDE + ks * 8 + 4 + t4]);
            }
            #pragma unroll
            for (int mf = 0; mf < 4; mf++) {
                const int m = warp_m + mf * 16 + g;
                const uint32_t a0 = __float_as_uint(As[m * SM_STRIDE + ks * 8 + t4]);
                const uint32_t a1 = __float_as_uint(As[(m + 8) * SM_STRIDE + ks * 8 + t4]);
                const uint32_t a2 = __float_as_uint(As[m * SM_STRIDE + ks * 8 + 4 + t4]);
                const uint32_t a3 = __float_as_uint(As[(m + 8) * SM_STRIDE + ks * 8 + 4 + t4]);
                #pragma unroll
                for (int nf = 0; nf < 4; nf++)
                    mma_tf32(acc[mf][nf], a0, a1, a2, a3, bf[nf][0], bf[nf][1]);
            }
        }
    }

    #pragma unroll
    for (int mf = 0; mf < 4; mf++) {
        const int row = warp_m + mf * 16 + g;
        #pragma unroll
        for (int nf = 0; nf < 4; nf++) {
            const int col = warp_n + nf * 8 + t4 * 2;
            *(float2*)(C + (size_t)row * TWO_I + col) =
                make_float2(acc[mf][nf][0], acc[mf][nf][1]);
            *(float2*)(C + (size_t)(row + 8) * TWO_I + col) =
                make_float2(acc[mf][nf][2], acc[mf][nf][3]);
        }
    }
}

// ---------------- GEMM2: fused silu(gate)*up from g_h, x wdn_t -> g_eout ----------------
__global__ __launch_bounds__(256) void g2_kernel(const float* __restrict__ Wt) {
    const int e   = blockIdx.z;
    const int cnt = g_cnt[e];
    const int m0  = blockIdx.y * 128;
    if (m0 >= cnt) return;
    const int n0  = blockIdx.x * 128;

    const float* __restrict__ H = g_h + (size_t)(e * CAP + m0) * TWO_I;
    const float* __restrict__ B = Wt + (size_t)e * D_DIM * I_DIM + (size_t)n0 * I_DIM;
    float*       __restrict__ C = g_eout + (size_t)(e * CAP + m0) * D_DIM + n0;

    __shared__ float As[TILE_F];
    __shared__ float Bs[TILE_F];

    const int tid  = threadIdx.x;
    const int lane = tid & 31;
    const int wid  = tid >> 5;
    const int warp_m = (wid >> 2) * 64;
    const int warp_n = (wid & 3) * 32;
    const int g  = lane >> 2;
    const int t4 = lane & 3;
    const int lrow = tid >> 3;
    const int lc4  = (tid & 7) * 4;
    const int NC = I_DIM / 32;            // 88

    float acc[4][4][4];
    #pragma unroll
    for (int i = 0; i < 4; i++)
        #pragma unroll
        for (int j = 0; j < 4; j++)
            #pragma unroll
            for (int q = 0; q < 4; q++) acc[i][j][q] = 0.f;

    float4 rg[4], ru[4], rb[4];

    #define G2_LOAD(k0_) do {                                                     \
        _Pragma("unroll")                                                         \
        for (int i_ = 0; i_ < 4; i_++) {                                          \
            const int r_ = lrow + 32 * i_;                                        \
            rg[i_] = *(const float4*)(H + (size_t)r_ * TWO_I + (k0_) + lc4);      \
            ru[i_] = *(const float4*)(H + (size_t)r_ * TWO_I + I_DIM + (k0_) + lc4); \
            rb[i_] = *(const float4*)(B + (size_t)r_ * I_DIM + (k0_) + lc4);      \
        }                                                                         \
    } while (0)

    #define G2_STORE() do {                                                       \
        _Pragma("unroll")                                                         \
        for (int i_ = 0; i_ < 4; i_++) {                                          \
            const int r_ = lrow + 32 * i_;                                        \
            float4 gg = rg[i_], uu = ru[i_], bb = rb[i_];                         \
            float* pa = &As[r_ * SM_STRIDE + lc4];                                \
            float* pb = &Bs[r_ * SM_STRIDE + lc4];                                \
            pa[0] = tf32r(gg.x / (1.f + expf(-gg.x)) * uu.x);                     \
            pa[1] = tf32r(gg.y / (1.f + expf(-gg.y)) * uu.y);                     \
            pa[2] = tf32r(gg.z / (1.f + expf(-gg.z)) * uu.z);                     \
            pa[3] = tf32r(gg.w / (1.f + expf(-gg.w)) * uu.w);                     \
            pb[0] = bb.x; pb[1] = bb.y; pb[2] = bb.z; pb[3] = bb.w;               \
        }                                                                         \
    } while (0)

    G2_LOAD(0);
    G2_STORE();
    __syncthreads();

    for (int c = 0; c < NC; c++) {
        if (c + 1 < NC) G2_LOAD((c + 1) * 32);
        #pragma unroll
        for (int ks = 0; ks < 4; ks++) {
            uint32_t bf[4][2];
            #pragma unroll
            for (int nf = 0; nf < 4; nf++) {
                const int n = warp_n + nf * 8 + g;
                bf[nf][0] = __float_as_uint(Bs[n * SM_STRIDE + ks * 8 + t4]);
                bf[nf][1] = __float_as_uint(Bs[n * SM_STRIDE + ks * 8 + 4 + t4]);
            }
            #pragma unroll
            for (int mf = 0; mf < 4; mf++) {
                const int m = warp_m + mf * 16 + g;
                const uint32_t a0 = __float_as_uint(As[m * SM_STRIDE + ks * 8 + t4]);
                const uint32_t a1 = __float_as_uint(As[(m + 8) * SM_STRIDE + ks * 8 + t4]);
                const uint32_t a2 = __float_as_uint(As[m * SM_STRIDE + ks * 8 + 4 + t4]);
                const uint32_t a3 = __float_as_uint(As[(m + 8) * SM_STRIDE + ks * 8 + 4 + t4]);
                #pragma unroll
                for (int nf = 0; nf < 4; nf++)
                    mma_tf32(acc[mf][nf], a0, a1, a2, a3, bf[nf][0], bf[nf][1]);
            }
        }
        __syncthreads();
        if (c + 1 < NC) {
            G2_STORE();
            __syncthreads();
        }
    }

    #pragma unroll
    for (int mf = 0; mf < 4; mf++) {
        const int row = warp_m + mf * 16 + g;
        #pragma unroll
        for (int nf = 0; nf < 4; nf++) {
            const int col = warp_n + nf * 8 + t4 * 2;
            *(float2*)(C + (size_t)row * D_DIM + col) =
                make_float2(acc[mf][nf][0], acc[mf][nf][1]);
            *(float2*)(C + (size_t)(row + 8) * D_DIM + col) =
                make_float2(acc[mf][nf][2], acc[mf][nf][3]);
        }
    }
}

// ---------------- gather + combine ----------------
__global__ void gather_kernel(float* __restrict__ out) {
    const int t    = (blockIdx.x * blockDim.x + threadIdx.x) >> 5;
    const int lane = threadIdx.x & 31;
    if (t >= T_TOK) return;
    const int s0 = 2 * t, s1 = s0 + 1;
    const int sl0 = g_slot[s0], sl1 = g_slot[s1];
    const float w0 = g_comb[s0], w1 = g_comb[s1];
    const float4* r0 = (sl0 >= 0) ? (const float4*)(g_eout + (size_t)sl0 * D_DIM) : nullptr;
    const float4* r1 = (sl1 >= 0) ? (const float4*)(g_eout + (size_t)sl1 * D_DIM) : nullptr;
    float4* orow = (float4*)(out + (size_t)t * D_DIM);
    #pragma unroll
    for (int ii = 0; ii < 8; ii++) {
        const int i = lane + 32 * ii;
        float4 a = make_float4(0.f, 0.f, 0.f, 0.f);
        if (r0) { float4 v = r0[i]; a.x += w0 * v.x; a.y += w0 * v.y; a.z += w0 * v.z; a.w += w0 * v.w; }
        if (r1) { float4 v = r1[i]; a.x += w1 * v.x; a.y += w1 * v.y; a.z += w1 * v.z; a.w += w1 * v.w; }
        orow[i] = a;
    }
}

// ---------------- final scalars ----------------
__global__ void finalize_kernel(float* __restrict__ out) {
    __shared__ float cnts[E_EXP];
    const size_t base = (size_t)T_TOK * D_DIM;
    if (threadIdx.x < E_EXP) {
        float c = (float)g_cnt[threadIdx.x];
        cnts[threadIdx.x] = c;
        out[base + threadIdx.x] = c;
    }
    __syncthreads();
    if (threadIdx.x == 0) {
        float total = 0.f;
        #pragma unroll
        for (int e = 0; e < E_EXP; e++) total += cnts[e];
        total = fmaxf(total, 1.f);
        float ent = 0.f, lb = 0.f;
        #pragma unroll
        for (int e = 0; e < E_EXP; e++) {
            float f = cnts[e] / total;
            ent -= f * logf(f + 1e-6f);
            lb  += (f * 2.0f) * (g_sumprobs[e] / (float)T_TOK);
        }
        lb *= (float)E_EXP;
        out[base + 16] = ent;
        out[base + 17] = lb;
        out[base + 18] = g_z2 / (float)T_TOK;
    }
}

// ---------------- launch ----------------
extern "C" void kernel_launch(void* const* d_in, const int* in_sizes, int n_in,
                              void* d_out, int out_size) {
    const float* x      = (const float*)d_in[0];
    const float* router = (const float*)d_in[1];
    const float* w_ug   = (const float*)d_in[2];
    const float* w_dn   = (const float*)d_in[3];
    float* out = (float*)d_out;

    float *wug_t = nullptr, *wdn_t = nullptr;
    cudaGetSymbolAddress((void**)&wug_t, g_wug_t);
    cudaGetSymbolAddress((void**)&wdn_t, g_wdn_t);

    static bool attr_done = false;
    if (!attr_done) {
        cudaFuncSetAttribute(router_kernel, cudaFuncAttributeMaxDynamicSharedMemorySize, R_SMEM_BYTES);
        cudaFuncSetAttribute(g1_kernel, cudaFuncAttributeMaxDynamicSharedMemorySize, G1_SMEM);
        attr_done = true;
    }

    transpose_kernel<<<dim3(TWO_I / 32, D_DIM / 32, E_EXP), dim3(32, 8)>>>(w_ug, wug_t, D_DIM, TWO_I);
    transpose_kernel<<<dim3(D_DIM / 32, I_DIM / 32, E_EXP), dim3(32, 8)>>>(w_dn, wdn_t, I_DIM, D_DIM);

    zero_stats_kernel<<<1, 32>>>();
    router_kernel<<<T_TOK / 32, 256, R_SMEM_BYTES>>>(x, router);
    pos_kernel<<<NB, 256>>>();
    scan_kernel<<<1, 32>>>();
    scatter_kernel<<<TK_SLOTS / 8, 256>>>(x);

    g1_kernel<<<dim3(TWO_I / 128, CAP / 128, E_EXP), 256, G1_SMEM>>>(wug_t);
    g2_kernel<<<dim3(D_DIM / 128, CAP / 128, E_EXP), 256>>>(wdn_t);

    gather_kernel<<<T_TOK / 8, 256>>>(out);
    finalize_kernel<<<1, 32>>>(out);
}

// round 6
// speedup vs baseline: 1.3803x; 1.3803x over previous
#include <cuda_runtime.h>
#include <math.h>
#include <stdint.h>

// ---------------- problem constants ----------------
#define T_TOK   32768
#define D_DIM   1024
#define E_EXP   16
#define I_DIM   2816
#define TWO_I   5632
#define TK_SLOTS 65536
#define CAP     5120
#define NB      64
#define SPB     1024

// ---------------- scratch (device globals; no allocs) ----------------
__device__ float g_expert_in[(size_t)E_EXP * CAP * D_DIM];   // tf32-rounded
__device__ float g_h[(size_t)E_EXP * CAP * TWO_I];           // fp32
__device__ float g_act[(size_t)E_EXP * CAP * I_DIM];         // tf32-rounded
__device__ float g_eout[(size_t)E_EXP * CAP * D_DIM];
__device__ float g_wug_t[(size_t)E_EXP * TWO_I * D_DIM];     // tf32-rounded, [E][2I][D]
__device__ float g_wdn_t[(size_t)E_EXP * D_DIM * I_DIM];     // tf32-rounded, [E][D][I]
__device__ int   g_sel[TK_SLOTS];
__device__ float g_comb[TK_SLOTS];
__device__ int   g_poslocal[TK_SLOTS];
__device__ int   g_slot[TK_SLOTS];
__device__ int   g_blkCnt[NB][E_EXP];
__device__ int   g_blkOff[NB][E_EXP];
__device__ int   g_cnt[E_EXP];
__device__ float g_sumprobs[E_EXP];
__device__ float g_z2;

// ---------------- helpers ----------------
__device__ __forceinline__ uint32_t f2tf32(float f) {
    uint32_t r;
    asm("cvt.rna.tf32.f32 %0, %1;" : "=r"(r) : "f"(f));
    return r;
}
__device__ __forceinline__ float tf32r(float f) { return __uint_as_float(f2tf32(f)); }

__device__ __forceinline__ void mma_tf32(float* c,
                                         uint32_t a0, uint32_t a1, uint32_t a2, uint32_t a3,
                                         uint32_t b0, uint32_t b1) {
    asm volatile("mma.sync.aligned.m16n8k8.row.col.f32.tf32.tf32.f32 "
                 "{%0,%1,%2,%3}, {%4,%5,%6,%7}, {%8,%9}, {%0,%1,%2,%3};"
                 : "+f"(c[0]), "+f"(c[1]), "+f"(c[2]), "+f"(c[3])
                 : "r"(a0), "r"(a1), "r"(a2), "r"(a3), "r"(b0), "r"(b1));
}

// ---------------- stats zeroing ----------------
__global__ void zero_stats_kernel() {
    if (threadIdx.x < E_EXP) g_sumprobs[threadIdx.x] = 0.f;
    if (threadIdx.x == 0)    g_z2 = 0.f;
}

// ---------------- router: SMEM-cached weights, 32 tokens/block ----------------
#define R_PAD 20
#define R_SMEM_BYTES (D_DIM * R_PAD * 4)
__global__ __launch_bounds__(256) void router_kernel(const float* __restrict__ x,
                                                     const float* __restrict__ router) {
    extern __shared__ float rs[];          // [D_DIM][R_PAD]
    __shared__ float s_p[E_EXP];
    __shared__ float s_z2;
    const int tid  = threadIdx.x;
    const int wid  = tid >> 5;
    const int lane = tid & 31;
    if (tid < E_EXP) s_p[tid] = 0.f;
    if (tid == 0)    s_z2 = 0.f;
    for (int t = tid; t < D_DIM * E_EXP; t += 256)
        rs[(t >> 4) * R_PAD + (t & 15)] = router[t];
    __syncthreads();

    #pragma unroll
    for (int j = 0; j < 4; j++) {
        const int tok = blockIdx.x * 32 + wid * 4 + j;
        const float* xr = x + (size_t)tok * D_DIM;
        float acc[E_EXP];
        #pragma unroll
        for (int e = 0; e < E_EXP; e++) acc[e] = 0.f;
        for (int i = lane; i < D_DIM; i += 32) {
            const float xv = xr[i];
            const float4* rp = (const float4*)&rs[i * R_PAD];
            float4 r0 = rp[0], r1 = rp[1], r2 = rp[2], r3 = rp[3];
            acc[0]  += xv * r0.x; acc[1]  += xv * r0.y; acc[2]  += xv * r0.z; acc[3]  += xv * r0.w;
            acc[4]  += xv * r1.x; acc[5]  += xv * r1.y; acc[6]  += xv * r1.z; acc[7]  += xv * r1.w;
            acc[8]  += xv * r2.x; acc[9]  += xv * r2.y; acc[10] += xv * r2.z; acc[11] += xv * r2.w;
            acc[12] += xv * r3.x; acc[13] += xv * r3.y; acc[14] += xv * r3.z; acc[15] += xv * r3.w;
        }
        #pragma unroll
        for (int off = 16; off; off >>= 1) {
            #pragma unroll
            for (int e = 0; e < E_EXP; e++)
                acc[e] += __shfl_xor_sync(0xffffffffu, acc[e], off);
        }
        float m = acc[0];
        #pragma unroll
        for (int e = 1; e < E_EXP; e++) m = fmaxf(m, acc[e]);
        float se = 0.f;
        #pragma unroll
        for (int e = 0; e < E_EXP; e++) se += expf(acc[e] - m);
        const float z = m + logf(se);

        int i1 = 0; float l1 = acc[0];
        #pragma unroll
        for (int e = 1; e < E_EXP; e++) if (acc[e] > l1) { l1 = acc[e]; i1 = e; }
        int i2 = -1; float l2 = -1e30f;
        #pragma unroll
        for (int e = 0; e < E_EXP; e++)
            if (e != i1 && acc[e] > l2) { l2 = acc[e]; i2 = e; }

        const float q  = expf(l2 - l1);
        if (lane == 0) {
            g_sel[2 * tok]     = i1;
            g_sel[2 * tok + 1] = i2;
            g_comb[2 * tok]     = 1.f / (1.f + q);
            g_comb[2 * tok + 1] = q / (1.f + q);
            atomicAdd(&s_z2, z * z);
        }
        if (lane < E_EXP) atomicAdd(&s_p[lane], expf(acc[lane] - m) / se);
    }
    __syncthreads();
    if (tid < E_EXP) atomicAdd(&g_sumprobs[tid], s_p[tid]);
    if (tid == 0)    atomicAdd(&g_z2, s_z2);
}

// ---------------- ordered per-expert rank ----------------
__global__ void pos_kernel() {
    __shared__ int warpCnt[8][E_EXP];
    __shared__ int running[E_EXP];
    const int tid  = threadIdx.x;
    const int wid  = tid >> 5;
    const int lane = tid & 31;
    if (tid < E_EXP) running[tid] = 0;
    __syncthreads();

    const int base = blockIdx.x * SPB;
    for (int it = 0; it < SPB / 256; it++) {
        const int s = base + it * 256 + tid;
        const int e = g_sel[s];
        unsigned peers = __match_any_sync(0xffffffffu, e);
        const int rank = __popc(peers & ((1u << lane) - 1u));
        if (lane < E_EXP) warpCnt[wid][lane] = 0;
        __syncwarp();
        if (rank == 0) warpCnt[wid][e] = __popc(peers);
        __syncthreads();
        int off = running[e] + rank;
        for (int w = 0; w < wid; w++) off += warpCnt[w][e];
        g_poslocal[s] = off;
        __syncthreads();
        if (tid < E_EXP) {
            int tot = 0;
            #pragma unroll
            for (int w = 0; w < 8; w++) tot += warpCnt[w][tid];
            running[tid] += tot;
        }
        __syncthreads();
    }
    if (tid < E_EXP) g_blkCnt[blockIdx.x][tid] = running[tid];
}

__global__ void scan_kernel() {
    const int e = threadIdx.x;
    if (e >= E_EXP) return;
    int run = 0;
    for (int b = 0; b < NB; b++) {
        g_blkOff[b][e] = run;
        run += g_blkCnt[b][e];
    }
    g_cnt[e] = run;
}

// ---------------- scatter (pre-rounds x to tf32) ----------------
__global__ void scatter_kernel(const float* __restrict__ x) {
    const int gwarp = (blockIdx.x * blockDim.x + threadIdx.x) >> 5;
    const int lane  = threadIdx.x & 31;
    if (gwarp >= TK_SLOTS) return;
    const int e   = g_sel[gwarp];
    const int pos = g_poslocal[gwarp] + g_blkOff[gwarp / SPB][e];
    int slot = -1;
    if (pos < CAP) {
        slot = e * CAP + pos;
        const float4* src = (const float4*)(x + (size_t)(gwarp >> 1) * D_DIM);
        float4* dst = (float4*)(g_expert_in + (size_t)slot * D_DIM);
        #pragma unroll
        for (int i = 0; i < 8; i++) {
            float4 v = src[lane + 32 * i];
            dst[lane + 32 * i] = make_float4(tf32r(v.x), tf32r(v.y), tf32r(v.z), tf32r(v.w));
        }
    }
    if (lane == 0) g_slot[gwarp] = slot;
}

// ---------------- weight transpose + tf32 pre-round ----------------
__global__ void transpose_kernel(const float* __restrict__ src, float* __restrict__ dst,
                                 int R, int Cd) {
    __shared__ float tile[32][33];
    const size_t eoff = (size_t)blockIdx.z * R * Cd;
    const float* S = src + eoff;
    float* Dp = dst + eoff;
    const int c0 = blockIdx.x * 32, r0 = blockIdx.y * 32;
    const int tx = threadIdx.x, ty = threadIdx.y;
    #pragma unroll
    for (int i = 0; i < 32; i += 8)
        tile[ty + i][tx] = tf32r(S[(size_t)(r0 + ty + i) * Cd + (c0 + tx)]);
    __syncthreads();
    #pragma unroll
    for (int i = 0; i < 32; i += 8)
        Dp[(size_t)(c0 + ty + i) * R + (r0 + tx)] = tile[tx][ty + i];
}

// ---------------- tf32 mma.sync grouped GEMM (round-4 structure) ----------------
// C[m,n] = sum_k A[m,k] * Bt[n,k].  CTA tile 128x128, K-chunk 32.
// 8 warps: 2 (m) x 4 (n); warp tile 64x32; mma m16n8k8.
// Inputs are pre-rounded to tf32 -> staging is a pure float4 copy.
#define SM_STRIDE 36

template <int Kdim, int Ndim, int WHICH>
__global__ __launch_bounds__(256)
void mma_gemm_kernel(const float* __restrict__ Wt) {
    const int e   = blockIdx.z;
    const int cnt = g_cnt[e];
    const int m0  = blockIdx.y * 128;
    if (m0 >= cnt) return;
    const int n0  = blockIdx.x * 128;

    const float* __restrict__ Abase = (WHICH == 1) ? g_expert_in : g_act;
    float*       __restrict__ Cbase = (WHICH == 1) ? g_h : g_eout;
    const float* __restrict__ A = Abase + (size_t)e * CAP * Kdim + (size_t)m0 * Kdim;
    const float* __restrict__ B = Wt + (size_t)e * Ndim * Kdim + (size_t)n0 * Kdim;
    float*       __restrict__ C = Cbase + (size_t)e * CAP * Ndim + (size_t)m0 * Ndim + n0;

    __shared__ float As[128 * SM_STRIDE];
    __shared__ float Bs[128 * SM_STRIDE];

    const int tid  = threadIdx.x;
    const int lane = tid & 31;
    const int wid  = tid >> 5;
    const int warp_m = (wid >> 2) * 64;   // 0 or 64
    const int warp_n = (wid & 3) * 32;    // 0,32,64,96
    const int g  = lane >> 2;             // 0..7
    const int t4 = lane & 3;              // 0..3

    const int lrow = tid >> 3;            // 0..31
    const int lc4  = (tid & 7) * 4;       // 0..28

    float acc[4][4][4];
    #pragma unroll
    for (int i = 0; i < 4; i++)
        #pragma unroll
        for (int j = 0; j < 4; j++)
            #pragma unroll
            for (int q = 0; q < 4; q++) acc[i][j][q] = 0.f;

    float4 ra[4], rb[4];
    const int NC = Kdim / 32;

    // prologue: load chunk 0
    #pragma unroll
    for (int i = 0; i < 4; i++) {
        ra[i] = *(const float4*)(A + (size_t)(lrow + 32 * i) * Kdim + lc4);
        rb[i] = *(const float4*)(B + (size_t)(lrow + 32 * i) * Kdim + lc4);
    }
    #pragma unroll
    for (int i = 0; i < 4; i++) {
        *(float4*)&As[(lrow + 32 * i) * SM_STRIDE + lc4] = ra[i];
        *(float4*)&Bs[(lrow + 32 * i) * SM_STRIDE + lc4] = rb[i];
    }
    __syncthreads();

    for (int c = 0; c < NC; c++) {
        // prefetch next chunk to registers (overlaps with mma below)
        if (c + 1 < NC) {
            const int k0 = (c + 1) * 32;
            #pragma unroll
            for (int i = 0; i < 4; i++) {
                ra[i] = *(const float4*)(A + (size_t)(lrow + 32 * i) * Kdim + k0 + lc4);
                rb[i] = *(const float4*)(B + (size_t)(lrow + 32 * i) * Kdim + k0 + lc4);
            }
        }
        // mma over current chunk
        #pragma unroll
        for (int ks = 0; ks < 4; ks++) {
            uint32_t bf[4][2];
            #pragma unroll
            for (int nf = 0; nf < 4; nf++) {
                const int n = warp_n + nf * 8 + g;
                bf[nf][0] = __float_as_uint(Bs[n * SM_STRIDE + ks * 8 + t4]);
                bf[nf][1] = __float_as_uint(Bs[n * SM_STRIDE + ks * 8 + 4 + t4]);
            }
            #pragma unroll
            for (int mf = 0; mf < 4; mf++) {
                const int m = warp_m + mf * 16 + g;
                const uint32_t a0 = __float_as_uint(As[m * SM_STRIDE + ks * 8 + t4]);
                const uint32_t a1 = __float_as_uint(As[(m + 8) * SM_STRIDE + ks * 8 + t4]);
                const uint32_t a2 = __float_as_uint(As[m * SM_STRIDE + ks * 8 + 4 + t4]);
                const uint32_t a3 = __float_as_uint(As[(m + 8) * SM_STRIDE + ks * 8 + 4 + t4]);
                #pragma unroll
                for (int nf = 0; nf < 4; nf++)
                    mma_tf32(acc[mf][nf], a0, a1, a2, a3, bf[nf][0], bf[nf][1]);
            }
        }
        __syncthreads();
        if (c + 1 < NC) {
            #pragma unroll
            for (int i = 0; i < 4; i++) {
                *(float4*)&As[(lrow + 32 * i) * SM_STRIDE + lc4] = ra[i];
                *(float4*)&Bs[(lrow + 32 * i) * SM_STRIDE + lc4] = rb[i];
            }
            __syncthreads();
        }
    }

    // epilogue
    #pragma unroll
    for (int mf = 0; mf < 4; mf++) {
        const int row = warp_m + mf * 16 + g;
        #pragma unroll
        for (int nf = 0; nf < 4; nf++) {
            const int col = warp_n + nf * 8 + t4 * 2;
            *(float2*)(C + (size_t)row * Ndim + col) =
                make_float2(acc[mf][nf][0], acc[mf][nf][1]);
            *(float2*)(C + (size_t)(row + 8) * Ndim + col) =
                make_float2(acc[mf][nf][2], acc[mf][nf][3]);
        }
    }
}

// ---------------- SiLU(gate)*up (writes tf32-rounded activations) ----------------
__global__ void silu_kernel() {
    const int row = blockIdx.x;
    const int e = row / CAP;
    if ((row - e * CAP) >= g_cnt[e]) return;
    const float4* h = (const float4*)(g_h + (size_t)row * TWO_I);
    float4* a = (float4*)(g_act + (size_t)row * I_DIM);
    for (int i = threadIdx.x; i < I_DIM / 4; i += blockDim.x) {
        float4 g = h[i];
        float4 u = h[I_DIM / 4 + i];
        float4 o;
        o.x = tf32r(g.x / (1.f + expf(-g.x)) * u.x);
        o.y = tf32r(g.y / (1.f + expf(-g.y)) * u.y);
        o.z = tf32r(g.z / (1.f + expf(-g.z)) * u.z);
        o.w = tf32r(g.w / (1.f + expf(-g.w)) * u.w);
        a[i] = o;
    }
}

// ---------------- gather + combine ----------------
__global__ void gather_kernel(float* __restrict__ out) {
    const int t    = (blockIdx.x * blockDim.x + threadIdx.x) >> 5;
    const int lane = threadIdx.x & 31;
    if (t >= T_TOK) return;
    const int s0 = 2 * t, s1 = s0 + 1;
    const int sl0 = g_slot[s0], sl1 = g_slot[s1];
    const float w0 = g_comb[s0], w1 = g_comb[s1];
    const float4* r0 = (sl0 >= 0) ? (const float4*)(g_eout + (size_t)sl0 * D_DIM) : nullptr;
    const float4* r1 = (sl1 >= 0) ? (const float4*)(g_eout + (size_t)sl1 * D_DIM) : nullptr;
    float4* orow = (float4*)(out + (size_t)t * D_DIM);
    #pragma unroll
    for (int ii = 0; ii < 8; ii++) {
        const int i = lane + 32 * ii;
        float4 a = make_float4(0.f, 0.f, 0.f, 0.f);
        if (r0) { float4 v = r0[i]; a.x += w0 * v.x; a.y += w0 * v.y; a.z += w0 * v.z; a.w += w0 * v.w; }
        if (r1) { float4 v = r1[i]; a.x += w1 * v.x; a.y += w1 * v.y; a.z += w1 * v.z; a.w += w1 * v.w; }
        orow[i] = a;
    }
}

// ---------------- final scalars ----------------
__global__ void finalize_kernel(float* __restrict__ out) {
    __shared__ float cnts[E_EXP];
    const size_t base = (size_t)T_TOK * D_DIM;
    if (threadIdx.x < E_EXP) {
        float c = (float)g_cnt[threadIdx.x];
        cnts[threadIdx.x] = c;
        out[base + threadIdx.x] = c;
    }
    __syncthreads();
    if (threadIdx.x == 0) {
        float total = 0.f;
        #pragma unroll
        for (int e = 0; e < E_EXP; e++) total += cnts[e];
        total = fmaxf(total, 1.f);
        float ent = 0.f, lb = 0.f;
        #pragma unroll
        for (int e = 0; e < E_EXP; e++) {
            float f = cnts[e] / total;
            ent -= f * logf(f + 1e-6f);
            lb  += (f * 2.0f) * (g_sumprobs[e] / (float)T_TOK);
        }
        lb *= (float)E_EXP;
        out[base + 16] = ent;
        out[base + 17] = lb;
        out[base + 18] = g_z2 / (float)T_TOK;
    }
}

// ---------------- launch ----------------
extern "C" void kernel_launch(void* const* d_in, const int* in_sizes, int n_in,
                              void* d_out, int out_size) {
    const float* x      = (const float*)d_in[0];
    const float* router = (const float*)d_in[1];
    const float* w_ug   = (const float*)d_in[2];
    const float* w_dn   = (const float*)d_in[3];
    float* out = (float*)d_out;

    float *wug_t = nullptr, *wdn_t = nullptr;
    cudaGetSymbolAddress((void**)&wug_t, g_wug_t);
    cudaGetSymbolAddress((void**)&wdn_t, g_wdn_t);

    static bool attr_done = false;
    if (!attr_done) {
        cudaFuncSetAttribute(router_kernel, cudaFuncAttributeMaxDynamicSharedMemorySize, R_SMEM_BYTES);
        attr_done = true;
    }

    transpose_kernel<<<dim3(TWO_I / 32, D_DIM / 32, E_EXP), dim3(32, 8)>>>(w_ug, wug_t, D_DIM, TWO_I);
    transpose_kernel<<<dim3(D_DIM / 32, I_DIM / 32, E_EXP), dim3(32, 8)>>>(w_dn, wdn_t, I_DIM, D_DIM);

    zero_stats_kernel<<<1, 32>>>();
    router_kernel<<<T_TOK / 32, 256, R_SMEM_BYTES>>>(x, router);
    pos_kernel<<<NB, 256>>>();
    scan_kernel<<<1, 32>>>();
    scatter_kernel<<<TK_SLOTS / 8, 256>>>(x);

    mma_gemm_kernel<D_DIM, TWO_I, 1>
        <<<dim3(TWO_I / 128, CAP / 128, E_EXP), 256>>>(wug_t);
    silu_kernel<<<E_EXP * CAP, 256>>>();
    mma_gemm_kernel<I_DIM, D_DIM, 2>
        <<<dim3(D_DIM / 128, CAP / 128, E_EXP), 256>>>(wdn_t);

    gather_kernel<<<T_TOK / 8, 256>>>(out);
    finalize_kernel<<<1, 32>>>(out);
}

// round 7
// speedup vs baseline: 1.5292x; 1.1079x over previous
#include <cuda_runtime.h>
#include <cuda_fp16.h>
#include <math.h>
#include <stdint.h>

// ---------------- problem constants ----------------
#define T_TOK   32768
#define D_DIM   1024
#define E_EXP   16
#define I_DIM   2816
#define TWO_I   5632
#define TK_SLOTS 65536
#define CAP     5120
#define NB      64
#define SPB     1024

// ---------------- scratch (device globals; no allocs) ----------------
__device__ __half g_xh[(size_t)E_EXP * CAP * D_DIM];       // scattered tokens, fp16
__device__ float  g_h[(size_t)E_EXP * CAP * TWO_I];        // GEMM1 out, fp32
__device__ __half g_acth[(size_t)E_EXP * CAP * I_DIM];     // silu out, fp16
__device__ float  g_eout[(size_t)E_EXP * CAP * D_DIM];
__device__ __half g_wug_th[(size_t)E_EXP * TWO_I * D_DIM]; // [E][2I][D] fp16
__device__ __half g_wdn_th[(size_t)E_EXP * D_DIM * I_DIM]; // [E][D][I] fp16
__device__ int   g_sel[TK_SLOTS];
__device__ float g_comb[TK_SLOTS];
__device__ int   g_poslocal[TK_SLOTS];
__device__ int   g_slot[TK_SLOTS];
__device__ int   g_blkCnt[NB][E_EXP];
__device__ int   g_blkOff[NB][E_EXP];
__device__ int   g_cnt[E_EXP];
__device__ float g_sumprobs[E_EXP];
__device__ float g_z2;

// ---------------- helpers ----------------
__device__ __forceinline__ void mma_f16(float* c,
                                        uint32_t a0, uint32_t a1, uint32_t a2, uint32_t a3,
                                        uint32_t b0, uint32_t b1) {
    asm volatile("mma.sync.aligned.m16n8k16.row.col.f32.f16.f16.f32 "
                 "{%0,%1,%2,%3}, {%4,%5,%6,%7}, {%8,%9}, {%0,%1,%2,%3};"
                 : "+f"(c[0]), "+f"(c[1]), "+f"(c[2]), "+f"(c[3])
                 : "r"(a0), "r"(a1), "r"(a2), "r"(a3), "r"(b0), "r"(b1));
}
__device__ __forceinline__ uint32_t pack_h2(float a, float b) {
    __half2 h = __floats2half2_rn(a, b);
    return *reinterpret_cast<uint32_t*>(&h);
}

// ---------------- stats zeroing ----------------
__global__ void zero_stats_kernel() {
    if (threadIdx.x < E_EXP) g_sumprobs[threadIdx.x] = 0.f;
    if (threadIdx.x == 0)    g_z2 = 0.f;
}

// ---------------- router: SMEM-cached weights, 32 tokens/block ----------------
#define R_PAD 20
#define R_SMEM_BYTES (D_DIM * R_PAD * 4)
__global__ __launch_bounds__(256) void router_kernel(const float* __restrict__ x,
                                                     const float* __restrict__ router) {
    extern __shared__ float rs[];          // [D_DIM][R_PAD]
    __shared__ float s_p[E_EXP];
    __shared__ float s_z2;
    const int tid  = threadIdx.x;
    const int wid  = tid >> 5;
    const int lane = tid & 31;
    if (tid < E_EXP) s_p[tid] = 0.f;
    if (tid == 0)    s_z2 = 0.f;
    for (int t = tid; t < D_DIM * E_EXP; t += 256)
        rs[(t >> 4) * R_PAD + (t & 15)] = router[t];
    __syncthreads();

    #pragma unroll
    for (int j = 0; j < 4; j++) {
        const int tok = blockIdx.x * 32 + wid * 4 + j;
        const float* xr = x + (size_t)tok * D_DIM;
        float acc[E_EXP];
        #pragma unroll
        for (int e = 0; e < E_EXP; e++) acc[e] = 0.f;
        for (int i = lane; i < D_DIM; i += 32) {
            const float xv = xr[i];
            const float4* rp = (const float4*)&rs[i * R_PAD];
            float4 r0 = rp[0], r1 = rp[1], r2 = rp[2], r3 = rp[3];
            acc[0]  += xv * r0.x; acc[1]  += xv * r0.y; acc[2]  += xv * r0.z; acc[3]  += xv * r0.w;
            acc[4]  += xv * r1.x; acc[5]  += xv * r1.y; acc[6]  += xv * r1.z; acc[7]  += xv * r1.w;
            acc[8]  += xv * r2.x; acc[9]  += xv * r2.y; acc[10] += xv * r2.z; acc[11] += xv * r2.w;
            acc[12] += xv * r3.x; acc[13] += xv * r3.y; acc[14] += xv * r3.z; acc[15] += xv * r3.w;
        }
        #pragma unroll
        for (int off = 16; off; off >>= 1) {
            #pragma unroll
            for (int e = 0; e < E_EXP; e++)
                acc[e] += __shfl_xor_sync(0xffffffffu, acc[e], off);
        }
        float m = acc[0];
        #pragma unroll
        for (int e = 1; e < E_EXP; e++) m = fmaxf(m, acc[e]);
        float se = 0.f;
        #pragma unroll
        for (int e = 0; e < E_EXP; e++) se += expf(acc[e] - m);
        const float z = m + logf(se);

        int i1 = 0; float l1 = acc[0];
        #pragma unroll
        for (int e = 1; e < E_EXP; e++) if (acc[e] > l1) { l1 = acc[e]; i1 = e; }
        int i2 = -1; float l2 = -1e30f;
        #pragma unroll
        for (int e = 0; e < E_EXP; e++)
            if (e != i1 && acc[e] > l2) { l2 = acc[e]; i2 = e; }

        const float q  = expf(l2 - l1);
        if (lane == 0) {
            g_sel[2 * tok]     = i1;
            g_sel[2 * tok + 1] = i2;
            g_comb[2 * tok]     = 1.f / (1.f + q);
            g_comb[2 * tok + 1] = q / (1.f + q);
            atomicAdd(&s_z2, z * z);
        }
        if (lane < E_EXP) atomicAdd(&s_p[lane], expf(acc[lane] - m) / se);
    }
    __syncthreads();
    if (tid < E_EXP) atomicAdd(&g_sumprobs[tid], s_p[tid]);
    if (tid == 0)    atomicAdd(&g_z2, s_z2);
}

// ---------------- ordered per-expert rank ----------------
__global__ void pos_kernel() {
    __shared__ int warpCnt[8][E_EXP];
    __shared__ int running[E_EXP];
    const int tid  = threadIdx.x;
    const int wid  = tid >> 5;
    const int lane = tid & 31;
    if (tid < E_EXP) running[tid] = 0;
    __syncthreads();

    const int base = blockIdx.x * SPB;
    for (int it = 0; it < SPB / 256; it++) {
        const int s = base + it * 256 + tid;
        const int e = g_sel[s];
        unsigned peers = __match_any_sync(0xffffffffu, e);
        const int rank = __popc(peers & ((1u << lane) - 1u));
        if (lane < E_EXP) warpCnt[wid][lane] = 0;
        __syncwarp();
        if (rank == 0) warpCnt[wid][e] = __popc(peers);
        __syncthreads();
        int off = running[e] + rank;
        for (int w = 0; w < wid; w++) off += warpCnt[w][e];
        g_poslocal[s] = off;
        __syncthreads();
        if (tid < E_EXP) {
            int tot = 0;
            #pragma unroll
            for (int w = 0; w < 8; w++) tot += warpCnt[w][tid];
            running[tid] += tot;
        }
        __syncthreads();
    }
    if (tid < E_EXP) g_blkCnt[blockIdx.x][tid] = running[tid];
}

__global__ void scan_kernel() {
    const int e = threadIdx.x;
    if (e >= E_EXP) return;
    int run = 0;
    for (int b = 0; b < NB; b++) {
        g_blkOff[b][e] = run;
        run += g_blkCnt[b][e];
    }
    g_cnt[e] = run;
}

// ---------------- scatter (converts x to fp16) ----------------
__global__ void scatter_kernel(const float* __restrict__ x) {
    const int gwarp = (blockIdx.x * blockDim.x + threadIdx.x) >> 5;
    const int lane  = threadIdx.x & 31;
    if (gwarp >= TK_SLOTS) return;
    const int e   = g_sel[gwarp];
    const int pos = g_poslocal[gwarp] + g_blkOff[gwarp / SPB][e];
    int slot = -1;
    if (pos < CAP) {
        slot = e * CAP + pos;
        const float4* src = (const float4*)(x + (size_t)(gwarp >> 1) * D_DIM);
        uint2* dst = (uint2*)(g_xh + (size_t)slot * D_DIM);
        #pragma unroll
        for (int i = 0; i < 8; i++) {
            float4 v = src[lane + 32 * i];
            dst[lane + 32 * i] = make_uint2(pack_h2(v.x, v.y), pack_h2(v.z, v.w));
        }
    }
    if (lane == 0) g_slot[gwarp] = slot;
}

// ---------------- weight transpose + fp16 convert ----------------
__global__ void transpose_kernel(const float* __restrict__ src, __half* __restrict__ dst,
                                 int R, int Cd) {
    __shared__ float tile[32][33];
    const float* S = src + (size_t)blockIdx.z * R * Cd;
    __half* Dp = dst + (size_t)blockIdx.z * R * Cd;
    const int c0 = blockIdx.x * 32, r0 = blockIdx.y * 32;
    const int tx = threadIdx.x, ty = threadIdx.y;
    #pragma unroll
    for (int i = 0; i < 32; i += 8)
        tile[ty + i][tx] = S[(size_t)(r0 + ty + i) * Cd + (c0 + tx)];
    __syncthreads();
    #pragma unroll
    for (int i = 0; i < 32; i += 8)
        Dp[(size_t)(c0 + ty + i) * R + (r0 + tx)] = __float2half_rn(tile[tx][ty + i]);
}

// ---------------- fp16 mma.sync grouped GEMM ----------------
// C[m,n] = sum_k A[m,k] * Bt[n,k], fp32 accumulate.
// CTA tile 128x128, K-chunk 32 halves (16 u32). 8 warps 2(m)x4(n), warp 64x32.
// SMEM in u32 units, row stride 20 (16 data + 4 pad) -> conflict-free frag loads.
#define SU 20

template <int Kdim, int Ndim, int WHICH>
__global__ __launch_bounds__(256)
void hgemm_kernel(const __half* __restrict__ Wt) {
    const int e   = blockIdx.z;
    const int cnt = g_cnt[e];
    const int m0  = blockIdx.y * 128;
    if (m0 >= cnt) return;
    const int n0  = blockIdx.x * 128;

    const __half* __restrict__ Ah = ((WHICH == 1) ? g_xh : g_acth)
                                    + (size_t)e * CAP * Kdim + (size_t)m0 * Kdim;
    const __half* __restrict__ Bh = Wt + (size_t)e * Ndim * Kdim + (size_t)n0 * Kdim;
    float* __restrict__ C = ((WHICH == 1) ? g_h : g_eout)
                            + (size_t)e * CAP * Ndim + (size_t)m0 * Ndim + n0;

    __shared__ uint32_t As[128 * SU];
    __shared__ uint32_t Bs[128 * SU];

    const int tid  = threadIdx.x;
    const int lane = tid & 31;
    const int wid  = tid >> 5;
    const int warp_m = (wid >> 2) * 64;
    const int warp_n = (wid & 3) * 32;
    const int g  = lane >> 2;
    const int t4 = lane & 3;

    float acc[4][4][4];
    #pragma unroll
    for (int i = 0; i < 4; i++)
        #pragma unroll
        for (int j = 0; j < 4; j++)
            #pragma unroll
            for (int q = 0; q < 4; q++) acc[i][j][q] = 0.f;

    // per-thread staging map: 2 uint4 per tensor per chunk
    // idx = tid*2+i : row = idx>>2 (0..127), j = idx&3 (16B piece within 64B row-chunk)
    const int r0a = (tid * 2) >> 2;
    const int j0  = (tid * 2) & 3;
    const int r1a = (tid * 2 + 1) >> 2;
    const int j1  = (tid * 2 + 1) & 3;

    uint4 pa[2], pb[2];
    const int NC = Kdim / 32;

    #define HG_LOAD(k0_) do {                                                    \
        pa[0] = *(const uint4*)(Ah + (size_t)r0a * Kdim + (k0_) + j0 * 8);       \
        pa[1] = *(const uint4*)(Ah + (size_t)r1a * Kdim + (k0_) + j1 * 8);       \
        pb[0] = *(const uint4*)(Bh + (size_t)r0a * Kdim + (k0_) + j0 * 8);       \
        pb[1] = *(const uint4*)(Bh + (size_t)r1a * Kdim + (k0_) + j1 * 8);       \
    } while (0)

    #define HG_STORE() do {                                                      \
        *(uint4*)&As[r0a * SU + j0 * 4] = pa[0];                                 \
        *(uint4*)&As[r1a * SU + j1 * 4] = pa[1];                                 \
        *(uint4*)&Bs[r0a * SU + j0 * 4] = pb[0];                                 \
        *(uint4*)&Bs[r1a * SU + j1 * 4] = pb[1];                                 \
    } while (0)

    HG_LOAD(0);
    HG_STORE();
    __syncthreads();

    for (int c = 0; c < NC; c++) {
        if (c + 1 < NC) HG_LOAD((c + 1) * 32);
        #pragma unroll
        for (int ks = 0; ks < 2; ks++) {
            const int ko = ks * 8;
            uint32_t bf[4][2];
            #pragma unroll
            for (int nf = 0; nf < 4; nf++) {
                const int n = warp_n + nf * 8 + g;
                bf[nf][0] = Bs[n * SU + ko + t4];
                bf[nf][1] = Bs[n * SU + ko + 4 + t4];
            }
            #pragma unroll
            for (int mf = 0; mf < 4; mf++) {
                const int m = warp_m + mf * 16 + g;
                const uint32_t a0 = As[m * SU + ko + t4];
                const uint32_t a1 = As[(m + 8) * SU + ko + t4];
                const uint32_t a2 = As[m * SU + ko + 4 + t4];
                const uint32_t a3 = As[(m + 8) * SU + ko + 4 + t4];
                #pragma unroll
                for (int nf = 0; nf < 4; nf++)
                    mma_f16(acc[mf][nf], a0, a1, a2, a3, bf[nf][0], bf[nf][1]);
            }
        }
        __syncthreads();
        if (c + 1 < NC) {
            HG_STORE();
            __syncthreads();
        }
    }

    #pragma unroll
    for (int mf = 0; mf < 4; mf++) {
        const int row = warp_m + mf * 16 + g;
        #pragma unroll
        for (int nf = 0; nf < 4; nf++) {
            const int col = warp_n + nf * 8 + t4 * 2;
            *(float2*)(C + (size_t)row * Ndim + col) =
                make_float2(acc[mf][nf][0], acc[mf][nf][1]);
            *(float2*)(C + (size_t)(row + 8) * Ndim + col) =
                make_float2(acc[mf][nf][2], acc[mf][nf][3]);
        }
    }
}

// ---------------- SiLU(gate)*up -> fp16 ----------------
__global__ void silu_kernel() {
    const int row = blockIdx.x;
    const int e = row / CAP;
    if ((row - e * CAP) >= g_cnt[e]) return;
    const float4* h = (const float4*)(g_h + (size_t)row * TWO_I);
    uint2* a = (uint2*)(g_acth + (size_t)row * I_DIM);
    for (int i = threadIdx.x; i < I_DIM / 4; i += blockDim.x) {
        float4 g = h[i];
        float4 u = h[I_DIM / 4 + i];
        float ox = g.x / (1.f + expf(-g.x)) * u.x;
        float oy = g.y / (1.f + expf(-g.y)) * u.y;
        float oz = g.z / (1.f + expf(-g.z)) * u.z;
        float ow = g.w / (1.f + expf(-g.w)) * u.w;
        a[i] = make_uint2(pack_h2(ox, oy), pack_h2(oz, ow));
    }
}

// ---------------- gather + combine ----------------
__global__ void gather_kernel(float* __restrict__ out) {
    const int t    = (blockIdx.x * blockDim.x + threadIdx.x) >> 5;
    const int lane = threadIdx.x & 31;
    if (t >= T_TOK) return;
    const int s0 = 2 * t, s1 = s0 + 1;
    const int sl0 = g_slot[s0], sl1 = g_slot[s1];
    const float w0 = g_comb[s0], w1 = g_comb[s1];
    const float4* r0 = (sl0 >= 0) ? (const float4*)(g_eout + (size_t)sl0 * D_DIM) : nullptr;
    const float4* r1 = (sl1 >= 0) ? (const float4*)(g_eout + (size_t)sl1 * D_DIM) : nullptr;
    float4* orow = (float4*)(out + (size_t)t * D_DIM);
    #pragma unroll
    for (int ii = 0; ii < 8; ii++) {
        const int i = lane + 32 * ii;
        float4 a = make_float4(0.f, 0.f, 0.f, 0.f);
        if (r0) { float4 v = r0[i]; a.x += w0 * v.x; a.y += w0 * v.y; a.z += w0 * v.z; a.w += w0 * v.w; }
        if (r1) { float4 v = r1[i]; a.x += w1 * v.x; a.y += w1 * v.y; a.z += w1 * v.z; a.w += w1 * v.w; }
        orow[i] = a;
    }
}

// ---------------- final scalars ----------------
__global__ void finalize_kernel(float* __restrict__ out) {
    __shared__ float cnts[E_EXP];
    const size_t base = (size_t)T_TOK * D_DIM;
    if (threadIdx.x < E_EXP) {
        float c = (float)g_cnt[threadIdx.x];
        cnts[threadIdx.x] = c;
        out[base + threadIdx.x] = c;
    }
    __syncthreads();
    if (threadIdx.x == 0) {
        float total = 0.f;
        #pragma unroll
        for (int e = 0; e < E_EXP; e++) total += cnts[e];
        total = fmaxf(total, 1.f);
        float ent = 0.f, lb = 0.f;
        #pragma unroll
        for (int e = 0; e < E_EXP; e++) {
            float f = cnts[e] / total;
            ent -= f * logf(f + 1e-6f);
            lb  += (f * 2.0f) * (g_sumprobs[e] / (float)T_TOK);
        }
        lb *= (float)E_EXP;
        out[base + 16] = ent;
        out[base + 17] = lb;
        out[base + 18] = g_z2 / (float)T_TOK;
    }
}

// ---------------- launch ----------------
extern "C" void kernel_launch(void* const* d_in, const int* in_sizes, int n_in,
                              void* d_out, int out_size) {
    const float* x      = (const float*)d_in[0];
    const float* router = (const float*)d_in[1];
    const float* w_ug   = (const float*)d_in[2];
    const float* w_dn   = (const float*)d_in[3];
    float* out = (float*)d_out;

    __half *wug_t = nullptr, *wdn_t = nullptr;
    cudaGetSymbolAddress((void**)&wug_t, g_wug_th);
    cudaGetSymbolAddress((void**)&wdn_t, g_wdn_th);

    static bool attr_done = false;
    if (!attr_done) {
        cudaFuncSetAttribute(router_kernel, cudaFuncAttributeMaxDynamicSharedMemorySize, R_SMEM_BYTES);
        attr_done = true;
    }

    transpose_kernel<<<dim3(TWO_I / 32, D_DIM / 32, E_EXP), dim3(32, 8)>>>(w_ug, wug_t, D_DIM, TWO_I);
    transpose_kernel<<<dim3(D_DIM / 32, I_DIM / 32, E_EXP), dim3(32, 8)>>>(w_dn, wdn_t, I_DIM, D_DIM);

    zero_stats_kernel<<<1, 32>>>();
    router_kernel<<<T_TOK / 32, 256, R_SMEM_BYTES>>>(x, router);
    pos_kernel<<<NB, 256>>>();
    scan_kernel<<<1, 32>>>();
    scatter_kernel<<<TK_SLOTS / 8, 256>>>(x);

    hgemm_kernel<D_DIM, TWO_I, 1>
        <<<dim3(TWO_I / 128, CAP / 128, E_EXP), 256>>>(wug_t);
    silu_kernel<<<E_EXP * CAP, 256>>>();
    hgemm_kernel<I_DIM, D_DIM, 2>
        <<<dim3(D_DIM / 128, CAP / 128, E_EXP), 256>>>(wdn_t);

    gather_kernel<<<T_TOK / 8, 256>>>(out);
    finalize_kernel<<<1, 32>>>(out);
}

// round 8
// speedup vs baseline: 1.9047x; 1.2455x over previous
#include <cuda_runtime.h>
#include <cuda_fp16.h>
#include <math.h>
#include <stdint.h>

// ---------------- problem constants ----------------
#define T_TOK   32768
#define D_DIM   1024
#define E_EXP   16
#define I_DIM   2816
#define TWO_I   5632
#define TK_SLOTS 65536
#define CAP     5120
#define NB      64
#define SPB     1024

// ---------------- scratch (device globals; no allocs) ----------------
__device__ __half g_xh[(size_t)E_EXP * CAP * D_DIM];       // scattered tokens, fp16
__device__ float  g_h[(size_t)E_EXP * CAP * TWO_I];        // GEMM1 out, fp32
__device__ __half g_acth[(size_t)E_EXP * CAP * I_DIM];     // silu out, fp16
__device__ float  g_eout[(size_t)E_EXP * CAP * D_DIM];
__device__ __half g_wug_th[(size_t)E_EXP * TWO_I * D_DIM]; // [E][2I][D] fp16
__device__ __half g_wdn_th[(size_t)E_EXP * D_DIM * I_DIM]; // [E][D][I] fp16
__device__ int   g_sel[TK_SLOTS];
__device__ float g_comb[TK_SLOTS];
__device__ int   g_poslocal[TK_SLOTS];
__device__ int   g_slot[TK_SLOTS];
__device__ int   g_blkCnt[NB][E_EXP];
__device__ int   g_blkOff[NB][E_EXP];
__device__ int   g_cnt[E_EXP];
__device__ float g_sumprobs[E_EXP];
__device__ float g_z2;

// ---------------- helpers ----------------
__device__ __forceinline__ void mma_f16(float* c,
                                        uint32_t a0, uint32_t a1, uint32_t a2, uint32_t a3,
                                        uint32_t b0, uint32_t b1) {
    asm volatile("mma.sync.aligned.m16n8k16.row.col.f32.f16.f16.f32 "
                 "{%0,%1,%2,%3}, {%4,%5,%6,%7}, {%8,%9}, {%0,%1,%2,%3};"
                 : "+f"(c[0]), "+f"(c[1]), "+f"(c[2]), "+f"(c[3])
                 : "r"(a0), "r"(a1), "r"(a2), "r"(a3), "r"(b0), "r"(b1));
}
__device__ __forceinline__ uint32_t pack_h2(float a, float b) {
    __half2 h = __floats2half2_rn(a, b);
    return *reinterpret_cast<uint32_t*>(&h);
}
__device__ __forceinline__ uint32_t smem_u32(const void* p) {
    uint32_t a;
    asm("{ .reg .u64 t; cvta.to.shared.u64 t, %1; cvt.u32.u64 %0, t; }" : "=r"(a) : "l"(p));
    return a;
}
#define LDSM_X4(r0_, r1_, r2_, r3_, addr_) \
    asm volatile("ldmatrix.sync.aligned.m8n8.x4.shared.b16 {%0,%1,%2,%3}, [%4];" \
                 : "=r"(r0_), "=r"(r1_), "=r"(r2_), "=r"(r3_) : "r"(addr_))

// ---------------- stats zeroing ----------------
__global__ void zero_stats_kernel() {
    if (threadIdx.x < E_EXP) g_sumprobs[threadIdx.x] = 0.f;
    if (threadIdx.x == 0)    g_z2 = 0.f;
}

// ---------------- router: SMEM-cached weights, 32 tokens/block ----------------
#define R_PAD 20
#define R_SMEM_BYTES (D_DIM * R_PAD * 4)
__global__ __launch_bounds__(256) void router_kernel(const float* __restrict__ x,
                                                     const float* __restrict__ router) {
    extern __shared__ float rs[];          // [D_DIM][R_PAD]
    __shared__ float s_p[E_EXP];
    __shared__ float s_z2;
    const int tid  = threadIdx.x;
    const int wid  = tid >> 5;
    const int lane = tid & 31;
    if (tid < E_EXP) s_p[tid] = 0.f;
    if (tid == 0)    s_z2 = 0.f;
    for (int t = tid; t < D_DIM * E_EXP; t += 256)
        rs[(t >> 4) * R_PAD + (t & 15)] = router[t];
    __syncthreads();

    #pragma unroll
    for (int j = 0; j < 4; j++) {
        const int tok = blockIdx.x * 32 + wid * 4 + j;
        const float* xr = x + (size_t)tok * D_DIM;
        float acc[E_EXP];
        #pragma unroll
        for (int e = 0; e < E_EXP; e++) acc[e] = 0.f;
        for (int i = lane; i < D_DIM; i += 32) {
            const float xv = xr[i];
            const float4* rp = (const float4*)&rs[i * R_PAD];
            float4 r0 = rp[0], r1 = rp[1], r2 = rp[2], r3 = rp[3];
            acc[0]  += xv * r0.x; acc[1]  += xv * r0.y; acc[2]  += xv * r0.z; acc[3]  += xv * r0.w;
            acc[4]  += xv * r1.x; acc[5]  += xv * r1.y; acc[6]  += xv * r1.z; acc[7]  += xv * r1.w;
            acc[8]  += xv * r2.x; acc[9]  += xv * r2.y; acc[10] += xv * r2.z; acc[11] += xv * r2.w;
            acc[12] += xv * r3.x; acc[13] += xv * r3.y; acc[14] += xv * r3.z; acc[15] += xv * r3.w;
        }
        #pragma unroll
        for (int off = 16; off; off >>= 1) {
            #pragma unroll
            for (int e = 0; e < E_EXP; e++)
                acc[e] += __shfl_xor_sync(0xffffffffu, acc[e], off);
        }
        float m = acc[0];
        #pragma unroll
        for (int e = 1; e < E_EXP; e++) m = fmaxf(m, acc[e]);
        float se = 0.f;
        #pragma unroll
        for (int e = 0; e < E_EXP; e++) se += expf(acc[e] - m);
        const float z = m + logf(se);

        int i1 = 0; float l1 = acc[0];
        #pragma unroll
        for (int e = 1; e < E_EXP; e++) if (acc[e] > l1) { l1 = acc[e]; i1 = e; }
        int i2 = -1; float l2 = -1e30f;
        #pragma unroll
        for (int e = 0; e < E_EXP; e++)
            if (e != i1 && acc[e] > l2) { l2 = acc[e]; i2 = e; }

        const float q  = expf(l2 - l1);
        if (lane == 0) {
            g_sel[2 * tok]     = i1;
            g_sel[2 * tok + 1] = i2;
            g_comb[2 * tok]     = 1.f / (1.f + q);
            g_comb[2 * tok + 1] = q / (1.f + q);
            atomicAdd(&s_z2, z * z);
        }
        if (lane < E_EXP) atomicAdd(&s_p[lane], expf(acc[lane] - m) / se);
    }
    __syncthreads();
    if (tid < E_EXP) atomicAdd(&g_sumprobs[tid], s_p[tid]);
    if (tid == 0)    atomicAdd(&g_z2, s_z2);
}

// ---------------- ordered per-expert rank ----------------
__global__ void pos_kernel() {
    __shared__ int warpCnt[8][E_EXP];
    __shared__ int running[E_EXP];
    const int tid  = threadIdx.x;
    const int wid  = tid >> 5;
    const int lane = tid & 31;
    if (tid < E_EXP) running[tid] = 0;
    __syncthreads();

    const int base = blockIdx.x * SPB;
    for (int it = 0; it < SPB / 256; it++) {
        const int s = base + it * 256 + tid;
        const int e = g_sel[s];
        unsigned peers = __match_any_sync(0xffffffffu, e);
        const int rank = __popc(peers & ((1u << lane) - 1u));
        if (lane < E_EXP) warpCnt[wid][lane] = 0;
        __syncwarp();
        if (rank == 0) warpCnt[wid][e] = __popc(peers);
        __syncthreads();
        int off = running[e] + rank;
        for (int w = 0; w < wid; w++) off += warpCnt[w][e];
        g_poslocal[s] = off;
        __syncthreads();
        if (tid < E_EXP) {
            int tot = 0;
            #pragma unroll
            for (int w = 0; w < 8; w++) tot += warpCnt[w][tid];
            running[tid] += tot;
        }
        __syncthreads();
    }
    if (tid < E_EXP) g_blkCnt[blockIdx.x][tid] = running[tid];
}

__global__ void scan_kernel() {
    const int e = threadIdx.x;
    if (e >= E_EXP) return;
    int run = 0;
    for (int b = 0; b < NB; b++) {
        g_blkOff[b][e] = run;
        run += g_blkCnt[b][e];
    }
    g_cnt[e] = run;
}

// ---------------- scatter (converts x to fp16) ----------------
__global__ void scatter_kernel(const float* __restrict__ x) {
    const int gwarp = (blockIdx.x * blockDim.x + threadIdx.x) >> 5;
    const int lane  = threadIdx.x & 31;
    if (gwarp >= TK_SLOTS) return;
    const int e   = g_sel[gwarp];
    const int pos = g_poslocal[gwarp] + g_blkOff[gwarp / SPB][e];
    int slot = -1;
    if (pos < CAP) {
        slot = e * CAP + pos;
        const float4* src = (const float4*)(x + (size_t)(gwarp >> 1) * D_DIM);
        uint2* dst = (uint2*)(g_xh + (size_t)slot * D_DIM);
        #pragma unroll
        for (int i = 0; i < 8; i++) {
            float4 v = src[lane + 32 * i];
            dst[lane + 32 * i] = make_uint2(pack_h2(v.x, v.y), pack_h2(v.z, v.w));
        }
    }
    if (lane == 0) g_slot[gwarp] = slot;
}

// ---------------- weight transpose + fp16 convert ----------------
__global__ void transpose_kernel(const float* __restrict__ src, __half* __restrict__ dst,
                                 int R, int Cd) {
    __shared__ float tile[32][33];
    const float* S = src + (size_t)blockIdx.z * R * Cd;
    __half* Dp = dst + (size_t)blockIdx.z * R * Cd;
    const int c0 = blockIdx.x * 32, r0 = blockIdx.y * 32;
    const int tx = threadIdx.x, ty = threadIdx.y;
    #pragma unroll
    for (int i = 0; i < 32; i += 8)
        tile[ty + i][tx] = S[(size_t)(r0 + ty + i) * Cd + (c0 + tx)];
    __syncthreads();
    #pragma unroll
    for (int i = 0; i < 32; i += 8)
        Dp[(size_t)(c0 + ty + i) * R + (r0 + tx)] = __float2half_rn(tile[tx][ty + i]);
}

// ---------------- fp16 mma.sync grouped GEMM, ping-pong + ldmatrix ----------------
// C[m,n] = sum_k A[m,k] * Bt[n,k], fp32 accumulate.
// CTA 128x128, K-chunk 32 halves (16 u32 per row-chunk). 8 warps 2(m)x4(n), warp 64x32.
// SMEM double-buffered, row stride 20 u32; ONE __syncthreads per chunk.
#define SU 20

template <int Kdim, int Ndim, int WHICH>
__global__ __launch_bounds__(256, 2)
void hgemm_kernel(const __half* __restrict__ Wt) {
    const int e   = blockIdx.z;
    const int cnt = g_cnt[e];
    const int m0  = blockIdx.y * 128;
    if (m0 >= cnt) return;
    const int n0  = blockIdx.x * 128;

    const __half* __restrict__ Ah = ((WHICH == 1) ? g_xh : g_acth)
                                    + (size_t)e * CAP * Kdim + (size_t)m0 * Kdim;
    const __half* __restrict__ Bh = Wt + (size_t)e * Ndim * Kdim + (size_t)n0 * Kdim;
    float* __restrict__ C = ((WHICH == 1) ? g_h : g_eout)
                            + (size_t)e * CAP * Ndim + (size_t)m0 * Ndim + n0;

    __shared__ uint32_t As[2][128 * SU];
    __shared__ uint32_t Bs[2][128 * SU];

    const int tid  = threadIdx.x;
    const int lane = tid & 31;
    const int wid  = tid >> 5;
    const int warp_m = (wid >> 2) * 64;
    const int warp_n = (wid & 3) * 32;
    const int g  = lane >> 2;
    const int t4 = lane & 3;

    float acc[4][4][4];
    #pragma unroll
    for (int i = 0; i < 4; i++)
        #pragma unroll
        for (int j = 0; j < 4; j++)
            #pragma unroll
            for (int q = 0; q < 4; q++) acc[i][j][q] = 0.f;

    // staging map: 2 uint4 per tensor per chunk per thread
    const int r0a = (tid * 2) >> 2;
    const int j0  = (tid * 2) & 3;
    const int r1a = (tid * 2 + 1) >> 2;
    const int j1  = (tid * 2 + 1) & 3;

    // ldmatrix per-lane base addresses (bytes), per buffer
    // A: groups of 8 lanes -> rows (m + lane&15), col-half ko + 8*(lane>>4)
    const int aRow = warp_m + (lane & 15);
    const int aOff = 4 * (lane >> 4);                 // u32 offset within 16-u32 chunk row
    // B: rows n0w + 8*((lane>>4)&1) + (lane&7), col-half ko + 8*((lane>>3)&1)
    const int bRow = warp_n + 8 * ((lane >> 4) & 1) + (lane & 7);
    const int bOff = 4 * ((lane >> 3) & 1);
    uint32_t aAddr[2], bAddr[2];
    #pragma unroll
    for (int b = 0; b < 2; b++) {
        aAddr[b] = smem_u32(&As[b][0]) + (uint32_t)(aRow * SU + aOff) * 4u;
        bAddr[b] = smem_u32(&Bs[b][0]) + (uint32_t)(bRow * SU + bOff) * 4u;
    }

    uint4 pa[2], pb[2];
    const int NC = Kdim / 32;

    #define HG_LOAD(k0_) do {                                                    \
        pa[0] = *(const uint4*)(Ah + (size_t)r0a * Kdim + (k0_) + j0 * 8);       \
        pa[1] = *(const uint4*)(Ah + (size_t)r1a * Kdim + (k0_) + j1 * 8);       \
        pb[0] = *(const uint4*)(Bh + (size_t)r0a * Kdim + (k0_) + j0 * 8);       \
        pb[1] = *(const uint4*)(Bh + (size_t)r1a * Kdim + (k0_) + j1 * 8);       \
    } while (0)

    #define HG_STORE(b_) do {                                                    \
        *(uint4*)&As[b_][r0a * SU + j0 * 4] = pa[0];                             \
        *(uint4*)&As[b_][r1a * SU + j1 * 4] = pa[1];                             \
        *(uint4*)&Bs[b_][r0a * SU + j0 * 4] = pb[0];                             \
        *(uint4*)&Bs[b_][r1a * SU + j1 * 4] = pb[1];                             \
    } while (0)

    HG_LOAD(0);
    HG_STORE(0);
    __syncthreads();

    for (int c = 0; c < NC; c++) {
        const int buf = c & 1;
        if (c + 1 < NC) HG_LOAD((c + 1) * 32);

        #pragma unroll
        for (int ks = 0; ks < 2; ks++) {
            uint32_t bf[4][2];
            #pragma unroll
            for (int p = 0; p < 2; p++) {
                LDSM_X4(bf[2 * p][0], bf[2 * p][1], bf[2 * p + 1][0], bf[2 * p + 1][1],
                        bAddr[buf] + (uint32_t)(p * 16 * SU * 4 + ks * 32));
            }
            #pragma unroll
            for (int mf = 0; mf < 4; mf++) {
                uint32_t a0, a1, a2, a3;
                LDSM_X4(a0, a1, a2, a3,
                        aAddr[buf] + (uint32_t)(mf * 16 * SU * 4 + ks * 32));
                #pragma unroll
                for (int nf = 0; nf < 4; nf++)
                    mma_f16(acc[mf][nf], a0, a1, a2, a3, bf[nf][0], bf[nf][1]);
            }
        }
        if (c + 1 < NC) HG_STORE((c + 1) & 1);   // writes the idle buffer, overlaps mma
        __syncthreads();
    }

    #pragma unroll
    for (int mf = 0; mf < 4; mf++) {
        const int row = warp_m + mf * 16 + g;
        #pragma unroll
        for (int nf = 0; nf < 4; nf++) {
            const int col = warp_n + nf * 8 + t4 * 2;
            *(float2*)(C + (size_t)row * Ndim + col) =
                make_float2(acc[mf][nf][0], acc[mf][nf][1]);
            *(float2*)(C + (size_t)(row + 8) * Ndim + col) =
                make_float2(acc[mf][nf][2], acc[mf][nf][3]);
        }
    }
}

// ---------------- SiLU(gate)*up -> fp16 ----------------
__global__ void silu_kernel() {
    const int row = blockIdx.x;
    const int e = row / CAP;
    if ((row - e * CAP) >= g_cnt[e]) return;
    const float4* h = (const float4*)(g_h + (size_t)row * TWO_I);
    uint2* a = (uint2*)(g_acth + (size_t)row * I_DIM);
    for (int i = threadIdx.x; i < I_DIM / 4; i += blockDim.x) {
        float4 g = h[i];
        float4 u = h[I_DIM / 4 + i];
        float ox = g.x / (1.f + expf(-g.x)) * u.x;
        float oy = g.y / (1.f + expf(-g.y)) * u.y;
        float oz = g.z / (1.f + expf(-g.z)) * u.z;
        float ow = g.w / (1.f + expf(-g.w)) * u.w;
        a[i] = make_uint2(pack_h2(ox, oy), pack_h2(oz, ow));
    }
}

// ---------------- gather + combine ----------------
__global__ void gather_kernel(float* __restrict__ out) {
    const int t    = (blockIdx.x * blockDim.x + threadIdx.x) >> 5;
    const int lane = threadIdx.x & 31;
    if (t >= T_TOK) return;
    const int s0 = 2 * t, s1 = s0 + 1;
    const int sl0 = g_slot[s0], sl1 = g_slot[s1];
    const float w0 = g_comb[s0], w1 = g_comb[s1];
    const float4* r0 = (sl0 >= 0) ? (const float4*)(g_eout + (size_t)sl0 * D_DIM) : nullptr;
    const float4* r1 = (sl1 >= 0) ? (const float4*)(g_eout + (size_t)sl1 * D_DIM) : nullptr;
    float4* orow = (float4*)(out + (size_t)t * D_DIM);
    #pragma unroll
    for (int ii = 0; ii < 8; ii++) {
        const int i = lane + 32 * ii;
        float4 a = make_float4(0.f, 0.f, 0.f, 0.f);
        if (r0) { float4 v = r0[i]; a.x += w0 * v.x; a.y += w0 * v.y; a.z += w0 * v.z; a.w += w0 * v.w; }
        if (r1) { float4 v = r1[i]; a.x += w1 * v.x; a.y += w1 * v.y; a.z += w1 * v.z; a.w += w1 * v.w; }
        orow[i] = a;
    }
}

// ---------------- final scalars ----------------
__global__ void finalize_kernel(float* __restrict__ out) {
    __shared__ float cnts[E_EXP];
    const size_t base = (size_t)T_TOK * D_DIM;
    if (threadIdx.x < E_EXP) {
        float c = (float)g_cnt[threadIdx.x];
        cnts[threadIdx.x] = c;
        out[base + threadIdx.x] = c;
    }
    __syncthreads();
    if (threadIdx.x == 0) {
        float total = 0.f;
        #pragma unroll
        for (int e = 0; e < E_EXP; e++) total += cnts[e];
        total = fmaxf(total, 1.f);
        float ent = 0.f, lb = 0.f;
        #pragma unroll
        for (int e = 0; e < E_EXP; e++) {
            float f = cnts[e] / total;
            ent -= f * logf(f + 1e-6f);
            lb  += (f * 2.0f) * (g_sumprobs[e] / (float)T_TOK);
        }
        lb *= (float)E_EXP;
        out[base + 16] = ent;
        out[base + 17] = lb;
        out[base + 18] = g_z2 / (float)T_TOK;
    }
}

// ---------------- launch ----------------
extern "C" void kernel_launch(void* const* d_in, const int* in_sizes, int n_in,
                              void* d_out, int out_size) {
    const float* x      = (const float*)d_in[0];
    const float* router = (const float*)d_in[1];
    const float* w_ug   = (const float*)d_in[2];
    const float* w_dn   = (const float*)d_in[3];
    float* out = (float*)d_out;

    __half *wug_t = nullptr, *wdn_t = nullptr;
    cudaGetSymbolAddress((void**)&wug_t, g_wug_th);
    cudaGetSymbolAddress((void**)&wdn_t, g_wdn_th);

    static bool attr_done = false;
    if (!attr_done) {
        cudaFuncSetAttribute(router_kernel, cudaFuncAttributeMaxDynamicSharedMemorySize, R_SMEM_BYTES);
        attr_done = true;
    }

    transpose_kernel<<<dim3(TWO_I / 32, D_DIM / 32, E_EXP), dim3(32, 8)>>>(w_ug, wug_t, D_DIM, TWO_I);
    transpose_kernel<<<dim3(D_DIM / 32, I_DIM / 32, E_EXP), dim3(32, 8)>>>(w_dn, wdn_t, I_DIM, D_DIM);

    zero_stats_kernel<<<1, 32>>>();
    router_kernel<<<T_TOK / 32, 256, R_SMEM_BYTES>>>(x, router);
    pos_kernel<<<NB, 256>>>();
    scan_kernel<<<1, 32>>>();
    scatter_kernel<<<TK_SLOTS / 8, 256>>>(x);

    hgemm_kernel<D_DIM, TWO_I, 1>
        <<<dim3(TWO_I / 128, CAP / 128, E_EXP), 256>>>(wug_t);
    silu_kernel<<<E_EXP * CAP, 256>>>();
    hgemm_kernel<I_DIM, D_DIM, 2>
        <<<dim3(D_DIM / 128, CAP / 128, E_EXP), 256>>>(wdn_t);

    gather_kernel<<<T_TOK / 8, 256>>>(out);
    finalize_kernel<<<1, 32>>>(out);
}

// round 9
// speedup vs baseline: 1.9566x; 1.0273x over previous
#include <cuda_runtime.h>
#include <cuda_fp16.h>
#include <math.h>
#include <stdint.h>

// ---------------- problem constants ----------------
#define T_TOK   32768
#define D_DIM   1024
#define E_EXP   16
#define I_DIM   2816
#define TWO_I   5632
#define TK_SLOTS 65536
#define CAP     5120
#define NB      64
#define SPB     1024

// ---------------- scratch (device globals; no allocs) ----------------
__device__ __half g_xh[(size_t)E_EXP * CAP * D_DIM];       // scattered tokens, fp16
__device__ float  g_h[(size_t)E_EXP * CAP * TWO_I];        // GEMM1 out, fp32
__device__ __half g_acth[(size_t)E_EXP * CAP * I_DIM];     // silu out, fp16
__device__ float  g_eout[(size_t)E_EXP * CAP * D_DIM];
__device__ __half g_wug_th[(size_t)E_EXP * TWO_I * D_DIM]; // [E][2I][D] fp16
__device__ __half g_wdn_th[(size_t)E_EXP * D_DIM * I_DIM]; // [E][D][I] fp16
__device__ int   g_sel[TK_SLOTS];
__device__ float g_comb[TK_SLOTS];
__device__ int   g_poslocal[TK_SLOTS];
__device__ int   g_slot[TK_SLOTS];
__device__ int   g_blkCnt[NB][E_EXP];
__device__ int   g_blkOff[NB][E_EXP];
__device__ int   g_cnt[E_EXP];
__device__ float g_sumprobs[E_EXP];
__device__ float g_z2;

// ---------------- helpers ----------------
__device__ __forceinline__ void mma_f16(float* c,
                                        uint32_t a0, uint32_t a1, uint32_t a2, uint32_t a3,
                                        uint32_t b0, uint32_t b1) {
    asm volatile("mma.sync.aligned.m16n8k16.row.col.f32.f16.f16.f32 "
                 "{%0,%1,%2,%3}, {%4,%5,%6,%7}, {%8,%9}, {%0,%1,%2,%3};"
                 : "+f"(c[0]), "+f"(c[1]), "+f"(c[2]), "+f"(c[3])
                 : "r"(a0), "r"(a1), "r"(a2), "r"(a3), "r"(b0), "r"(b1));
}
__device__ __forceinline__ uint32_t pack_h2(float a, float b) {
    __half2 h = __floats2half2_rn(a, b);
    return *reinterpret_cast<uint32_t*>(&h);
}
__device__ __forceinline__ uint32_t smem_u32(const void* p) {
    uint32_t a;
    asm("{ .reg .u64 t; cvta.to.shared.u64 t, %1; cvt.u32.u64 %0, t; }" : "=r"(a) : "l"(p));
    return a;
}
#define LDSM_X4(r0_, r1_, r2_, r3_, addr_) \
    asm volatile("ldmatrix.sync.aligned.m8n8.x4.shared.b16 {%0,%1,%2,%3}, [%4];" \
                 : "=r"(r0_), "=r"(r1_), "=r"(r2_), "=r"(r3_) : "r"(addr_))
#define CP_ASYNC16(dst_u32, src_ptr) \
    asm volatile("cp.async.cg.shared.global [%0], [%1], 16;" :: "r"(dst_u32), "l"(src_ptr))
#define CP_COMMIT()  asm volatile("cp.async.commit_group;")
#define CP_WAIT0()   asm volatile("cp.async.wait_group 0;")

// ---------------- stats zeroing ----------------
__global__ void zero_stats_kernel() {
    if (threadIdx.x < E_EXP) g_sumprobs[threadIdx.x] = 0.f;
    if (threadIdx.x == 0)    g_z2 = 0.f;
}

// ---------------- router: SMEM-cached weights, 32 tokens/block ----------------
#define R_PAD 20
#define R_SMEM_BYTES (D_DIM * R_PAD * 4)
__global__ __launch_bounds__(256) void router_kernel(const float* __restrict__ x,
                                                     const float* __restrict__ router) {
    extern __shared__ float rs[];          // [D_DIM][R_PAD]
    __shared__ float s_p[E_EXP];
    __shared__ float s_z2;
    const int tid  = threadIdx.x;
    const int wid  = tid >> 5;
    const int lane = tid & 31;
    if (tid < E_EXP) s_p[tid] = 0.f;
    if (tid == 0)    s_z2 = 0.f;
    for (int t = tid; t < D_DIM * E_EXP; t += 256)
        rs[(t >> 4) * R_PAD + (t & 15)] = router[t];
    __syncthreads();

    #pragma unroll
    for (int j = 0; j < 4; j++) {
        const int tok = blockIdx.x * 32 + wid * 4 + j;
        const float* xr = x + (size_t)tok * D_DIM;
        float acc[E_EXP];
        #pragma unroll
        for (int e = 0; e < E_EXP; e++) acc[e] = 0.f;
        for (int i = lane; i < D_DIM; i += 32) {
            const float xv = xr[i];
            const float4* rp = (const float4*)&rs[i * R_PAD];
            float4 r0 = rp[0], r1 = rp[1], r2 = rp[2], r3 = rp[3];
            acc[0]  += xv * r0.x; acc[1]  += xv * r0.y; acc[2]  += xv * r0.z; acc[3]  += xv * r0.w;
            acc[4]  += xv * r1.x; acc[5]  += xv * r1.y; acc[6]  += xv * r1.z; acc[7]  += xv * r1.w;
            acc[8]  += xv * r2.x; acc[9]  += xv * r2.y; acc[10] += xv * r2.z; acc[11] += xv * r2.w;
            acc[12] += xv * r3.x; acc[13] += xv * r3.y; acc[14] += xv * r3.z; acc[15] += xv * r3.w;
        }
        #pragma unroll
        for (int off = 16; off; off >>= 1) {
            #pragma unroll
            for (int e = 0; e < E_EXP; e++)
                acc[e] += __shfl_xor_sync(0xffffffffu, acc[e], off);
        }
        float m = acc[0];
        #pragma unroll
        for (int e = 1; e < E_EXP; e++) m = fmaxf(m, acc[e]);
        float se = 0.f;
        #pragma unroll
        for (int e = 0; e < E_EXP; e++) se += expf(acc[e] - m);
        const float z = m + logf(se);

        int i1 = 0; float l1 = acc[0];
        #pragma unroll
        for (int e = 1; e < E_EXP; e++) if (acc[e] > l1) { l1 = acc[e]; i1 = e; }
        int i2 = -1; float l2 = -1e30f;
        #pragma unroll
        for (int e = 0; e < E_EXP; e++)
            if (e != i1 && acc[e] > l2) { l2 = acc[e]; i2 = e; }

        const float q  = expf(l2 - l1);
        if (lane == 0) {
            g_sel[2 * tok]     = i1;
            g_sel[2 * tok + 1] = i2;
            g_comb[2 * tok]     = 1.f / (1.f + q);
            g_comb[2 * tok + 1] = q / (1.f + q);
            atomicAdd(&s_z2, z * z);
        }
        if (lane < E_EXP) atomicAdd(&s_p[lane], expf(acc[lane] - m) / se);
    }
    __syncthreads();
    if (tid < E_EXP) atomicAdd(&g_sumprobs[tid], s_p[tid]);
    if (tid == 0)    atomicAdd(&g_z2, s_z2);
}

// ---------------- ordered per-expert rank ----------------
__global__ void pos_kernel() {
    __shared__ int warpCnt[8][E_EXP];
    __shared__ int running[E_EXP];
    const int tid  = threadIdx.x;
    const int wid  = tid >> 5;
    const int lane = tid & 31;
    if (tid < E_EXP) running[tid] = 0;
    __syncthreads();

    const int base = blockIdx.x * SPB;
    for (int it = 0; it < SPB / 256; it++) {
        const int s = base + it * 256 + tid;
        const int e = g_sel[s];
        unsigned peers = __match_any_sync(0xffffffffu, e);
        const int rank = __popc(peers & ((1u << lane) - 1u));
        if (lane < E_EXP) warpCnt[wid][lane] = 0;
        __syncwarp();
        if (rank == 0) warpCnt[wid][e] = __popc(peers);
        __syncthreads();
        int off = running[e] + rank;
        for (int w = 0; w < wid; w++) off += warpCnt[w][e];
        g_poslocal[s] = off;
        __syncthreads();
        if (tid < E_EXP) {
            int tot = 0;
            #pragma unroll
            for (int w = 0; w < 8; w++) tot += warpCnt[w][tid];
            running[tid] += tot;
        }
        __syncthreads();
    }
    if (tid < E_EXP) g_blkCnt[blockIdx.x][tid] = running[tid];
}

__global__ void scan_kernel() {
    const int e = threadIdx.x;
    if (e >= E_EXP) return;
    int run = 0;
    for (int b = 0; b < NB; b++) {
        g_blkOff[b][e] = run;
        run += g_blkCnt[b][e];
    }
    g_cnt[e] = run;
}

// ---------------- scatter (converts x to fp16) ----------------
__global__ void scatter_kernel(const float* __restrict__ x) {
    const int gwarp = (blockIdx.x * blockDim.x + threadIdx.x) >> 5;
    const int lane  = threadIdx.x & 31;
    if (gwarp >= TK_SLOTS) return;
    const int e   = g_sel[gwarp];
    const int pos = g_poslocal[gwarp] + g_blkOff[gwarp / SPB][e];
    int slot = -1;
    if (pos < CAP) {
        slot = e * CAP + pos;
        const float4* src = (const float4*)(x + (size_t)(gwarp >> 1) * D_DIM);
        uint2* dst = (uint2*)(g_xh + (size_t)slot * D_DIM);
        #pragma unroll
        for (int i = 0; i < 8; i++) {
            float4 v = src[lane + 32 * i];
            dst[lane + 32 * i] = make_uint2(pack_h2(v.x, v.y), pack_h2(v.z, v.w));
        }
    }
    if (lane == 0) g_slot[gwarp] = slot;
}

// ---------------- weight transpose + fp16 convert ----------------
__global__ void transpose_kernel(const float* __restrict__ src, __half* __restrict__ dst,
                                 int R, int Cd) {
    __shared__ float tile[32][33];
    const float* S = src + (size_t)blockIdx.z * R * Cd;
    __half* Dp = dst + (size_t)blockIdx.z * R * Cd;
    const int c0 = blockIdx.x * 32, r0 = blockIdx.y * 32;
    const int tx = threadIdx.x, ty = threadIdx.y;
    #pragma unroll
    for (int i = 0; i < 32; i += 8)
        tile[ty + i][tx] = S[(size_t)(r0 + ty + i) * Cd + (c0 + tx)];
    __syncthreads();
    #pragma unroll
    for (int i = 0; i < 32; i += 8)
        Dp[(size_t)(c0 + ty + i) * R + (r0 + tx)] = __float2half_rn(tile[tx][ty + i]);
}

// ---------------- fp16 mma.sync grouped GEMM: cp.async 2-stage, K-chunk 64 ----------------
// C[m,n] = sum_k A[m,k] * Bt[n,k], fp32 accumulate.
// CTA 128x128, K-chunk 64 halves (32 u32 per row-chunk). 8 warps 2(m)x4(n), warp 64x32.
// SMEM: 2 buffers x (A tile + B tile), row stride 36 u32; one __syncthreads per chunk;
// loads go global->smem via cp.async, fully overlapped with mma on the other buffer.
#define SU 36
#define TILE_U (128 * SU)                 // 4608 u32 per tile
#define BUF_U  (2 * TILE_U)               // A + B per buffer
#define HG_SMEM (2 * BUF_U * 4)           // 73728 bytes

template <int Kdim, int Ndim, int WHICH>
__global__ __launch_bounds__(256, 2)
void hgemm_kernel(const __half* __restrict__ Wt) {
    const int e   = blockIdx.z;
    const int cnt = g_cnt[e];
    const int m0  = blockIdx.y * 128;
    if (m0 >= cnt) return;
    const int n0  = blockIdx.x * 128;

    const __half* __restrict__ Ah = ((WHICH == 1) ? g_xh : g_acth)
                                    + (size_t)e * CAP * Kdim + (size_t)m0 * Kdim;
    const __half* __restrict__ Bh = Wt + (size_t)e * Ndim * Kdim + (size_t)n0 * Kdim;
    float* __restrict__ C = ((WHICH == 1) ? g_h : g_eout)
                            + (size_t)e * CAP * Ndim + (size_t)m0 * Ndim + n0;

    extern __shared__ uint32_t smem[];
    const uint32_t smem_base = smem_u32(smem);

    const int tid  = threadIdx.x;
    const int lane = tid & 31;
    const int wid  = tid >> 5;
    const int warp_m = (wid >> 2) * 64;
    const int warp_n = (wid & 3) * 32;
    const int g  = lane >> 2;
    const int t4 = lane & 3;

    float acc[4][4][4];
    #pragma unroll
    for (int i = 0; i < 4; i++)
        #pragma unroll
        for (int j = 0; j < 4; j++)
            #pragma unroll
            for (int q = 0; q < 4; q++) acc[i][j][q] = 0.f;

    // cp.async staging map: thread covers 4 of 8 16B-pieces of row tid>>1
    const int sRow  = tid >> 1;            // 0..127
    const int jBase = (tid & 1) * 4;       // 0 or 4

    // ldmatrix per-lane base addresses
    const int aRow = warp_m + (lane & 15);
    const int aOff = 4 * (lane >> 4);
    const int bRow = warp_n + 8 * ((lane >> 4) & 1) + (lane & 7);
    const int bOff = 4 * ((lane >> 3) & 1);
    uint32_t aAddr[2], bAddr[2];
    #pragma unroll
    for (int b = 0; b < 2; b++) {
        aAddr[b] = smem_base + (uint32_t)(b * BUF_U + aRow * SU + aOff) * 4u;
        bAddr[b] = smem_base + (uint32_t)(b * BUF_U + TILE_U + bRow * SU + bOff) * 4u;
    }

    const int NC = Kdim / 64;

    #define HG_ISSUE(c_) do {                                                     \
        const uint32_t dstA = smem_base + (uint32_t)(((c_) & 1) * BUF_U) * 4u;    \
        const uint32_t dstB = dstA + (uint32_t)TILE_U * 4u;                       \
        const int k0_ = (c_) * 64;                                                \
        _Pragma("unroll")                                                         \
        for (int i_ = 0; i_ < 4; i_++) {                                          \
            const int j_ = jBase + i_;                                            \
            const uint32_t so = (uint32_t)(sRow * SU + j_ * 4) * 4u;              \
            CP_ASYNC16(dstA + so, Ah + (size_t)sRow * Kdim + k0_ + j_ * 8);       \
            CP_ASYNC16(dstB + so, Bh + (size_t)sRow * Kdim + k0_ + j_ * 8);       \
        }                                                                         \
        CP_COMMIT();                                                              \
    } while (0)

    HG_ISSUE(0);

    for (int c = 0; c < NC; c++) {
        const int buf = c & 1;
        CP_WAIT0();
        __syncthreads();                   // chunk c visible to all; prev compute done
        if (c + 1 < NC) HG_ISSUE(c + 1);   // DMA into idle buffer, overlaps mma below

        #pragma unroll
        for (int ks = 0; ks < 4; ks++) {
            uint32_t bf[4][2];
            #pragma unroll
            for (int p = 0; p < 2; p++) {
                LDSM_X4(bf[2 * p][0], bf[2 * p][1], bf[2 * p + 1][0], bf[2 * p + 1][1],
                        bAddr[buf] + (uint32_t)(p * 16 * SU * 4 + ks * 32));
            }
            #pragma unroll
            for (int mf = 0; mf < 4; mf++) {
                uint32_t a0, a1, a2, a3;
                LDSM_X4(a0, a1, a2, a3,
                        aAddr[buf] + (uint32_t)(mf * 16 * SU * 4 + ks * 32));
                #pragma unroll
                for (int nf = 0; nf < 4; nf++)
                    mma_f16(acc[mf][nf], a0, a1, a2, a3, bf[nf][0], bf[nf][1]);
            }
        }
    }

    #pragma unroll
    for (int mf = 0; mf < 4; mf++) {
        const int row = warp_m + mf * 16 + g;
        #pragma unroll
        for (int nf = 0; nf < 4; nf++) {
            const int col = warp_n + nf * 8 + t4 * 2;
            *(float2*)(C + (size_t)row * Ndim + col) =
                make_float2(acc[mf][nf][0], acc[mf][nf][1]);
            *(float2*)(C + (size_t)(row + 8) * Ndim + col) =
                make_float2(acc[mf][nf][2], acc[mf][nf][3]);
        }
    }
}

// ---------------- SiLU(gate)*up -> fp16 ----------------
__global__ void silu_kernel() {
    const int row = blockIdx.x;
    const int e = row / CAP;
    if ((row - e * CAP) >= g_cnt[e]) return;
    const float4* h = (const float4*)(g_h + (size_t)row * TWO_I);
    uint2* a = (uint2*)(g_acth + (size_t)row * I_DIM);
    for (int i = threadIdx.x; i < I_DIM / 4; i += blockDim.x) {
        float4 g = h[i];
        float4 u = h[I_DIM / 4 + i];
        float ox = g.x / (1.f + expf(-g.x)) * u.x;
        float oy = g.y / (1.f + expf(-g.y)) * u.y;
        float oz = g.z / (1.f + expf(-g.z)) * u.z;
        float ow = g.w / (1.f + expf(-g.w)) * u.w;
        a[i] = make_uint2(pack_h2(ox, oy), pack_h2(oz, ow));
    }
}

// ---------------- gather + combine ----------------
__global__ void gather_kernel(float* __restrict__ out) {
    const int t    = (blockIdx.x * blockDim.x + threadIdx.x) >> 5;
    const int lane = threadIdx.x & 31;
    if (t >= T_TOK) return;
    const int s0 = 2 * t, s1 = s0 + 1;
    const int sl0 = g_slot[s0], sl1 = g_slot[s1];
    const float w0 = g_comb[s0], w1 = g_comb[s1];
    const float4* r0 = (sl0 >= 0) ? (const float4*)(g_eout + (size_t)sl0 * D_DIM) : nullptr;
    const float4* r1 = (sl1 >= 0) ? (const float4*)(g_eout + (size_t)sl1 * D_DIM) : nullptr;
    float4* orow = (float4*)(out + (size_t)t * D_DIM);
    #pragma unroll
    for (int ii = 0; ii < 8; ii++) {
        const int i = lane + 32 * ii;
        float4 a = make_float4(0.f, 0.f, 0.f, 0.f);
        if (r0) { float4 v = r0[i]; a.x += w0 * v.x; a.y += w0 * v.y; a.z += w0 * v.z; a.w += w0 * v.w; }
        if (r1) { float4 v = r1[i]; a.x += w1 * v.x; a.y += w1 * v.y; a.z += w1 * v.z; a.w += w1 * v.w; }
        orow[i] = a;
    }
}

// ---------------- final scalars ----------------
__global__ void finalize_kernel(float* __restrict__ out) {
    __shared__ float cnts[E_EXP];
    const size_t base = (size_t)T_TOK * D_DIM;
    if (threadIdx.x < E_EXP) {
        float c = (float)g_cnt[threadIdx.x];
        cnts[threadIdx.x] = c;
        out[base + threadIdx.x] = c;
    }
    __syncthreads();
    if (threadIdx.x == 0) {
        float total = 0.f;
        #pragma unroll
        for (int e = 0; e < E_EXP; e++) total += cnts[e];
        total = fmaxf(total, 1.f);
        float ent = 0.f, lb = 0.f;
        #pragma unroll
        for (int e = 0; e < E_EXP; e++) {
            float f = cnts[e] / total;
            ent -= f * logf(f + 1e-6f);
            lb  += (f * 2.0f) * (g_sumprobs[e] / (float)T_TOK);
        }
        lb *= (float)E_EXP;
        out[base + 16] = ent;
        out[base + 17] = lb;
        out[base + 18] = g_z2 / (float)T_TOK;
    }
}

// ---------------- launch ----------------
extern "C" void kernel_launch(void* const* d_in, const int* in_sizes, int n_in,
                              void* d_out, int out_size) {
    const float* x      = (const float*)d_in[0];
    const float* router = (const float*)d_in[1];
    const float* w_ug   = (const float*)d_in[2];
    const float* w_dn   = (const float*)d_in[3];
    float* out = (float*)d_out;

    __half *wug_t = nullptr, *wdn_t = nullptr;
    cudaGetSymbolAddress((void**)&wug_t, g_wug_th);
    cudaGetSymbolAddress((void**)&wdn_t, g_wdn_th);

    static bool attr_done = false;
    if (!attr_done) {
        cudaFuncSetAttribute(router_kernel, cudaFuncAttributeMaxDynamicSharedMemorySize, R_SMEM_BYTES);
        cudaFuncSetAttribute(hgemm_kernel<D_DIM, TWO_I, 1>,
                             cudaFuncAttributeMaxDynamicSharedMemorySize, HG_SMEM);
        cudaFuncSetAttribute(hgemm_kernel<I_DIM, D_DIM, 2>,
                             cudaFuncAttributeMaxDynamicSharedMemorySize, HG_SMEM);
        attr_done = true;
    }

    transpose_kernel<<<dim3(TWO_I / 32, D_DIM / 32, E_EXP), dim3(32, 8)>>>(w_ug, wug_t, D_DIM, TWO_I);
    transpose_kernel<<<dim3(D_DIM / 32, I_DIM / 32, E_EXP), dim3(32, 8)>>>(w_dn, wdn_t, I_DIM, D_DIM);

    zero_stats_kernel<<<1, 32>>>();
    router_kernel<<<T_TOK / 32, 256, R_SMEM_BYTES>>>(x, router);
    pos_kernel<<<NB, 256>>>();
    scan_kernel<<<1, 32>>>();
    scatter_kernel<<<TK_SLOTS / 8, 256>>>(x);

    hgemm_kernel<D_DIM, TWO_I, 1>
        <<<dim3(TWO_I / 128, CAP / 128, E_EXP), 256, HG_SMEM>>>(wug_t);
    silu_kernel<<<E_EXP * CAP, 256>>>();
    hgemm_kernel<I_DIM, D_DIM, 2>
        <<<dim3(D_DIM / 128, CAP / 128, E_EXP), 256, HG_SMEM>>>(wdn_t);

    gather_kernel<<<T_TOK / 8, 256>>>(out);
    finalize_kernel<<<1, 32>>>(out);
}

// round 10
// speedup vs baseline: 2.0148x; 1.0297x over previous
#include <cuda_runtime.h>
#include <cuda_fp16.h>
#include <math.h>
#include <stdint.h>

// ---------------- problem constants ----------------
#define T_TOK   32768
#define D_DIM   1024
#define E_EXP   16
#define I_DIM   2816
#define TWO_I   5632
#define TK_SLOTS 65536
#define CAP     5120
#define NB      64
#define SPB     1024

// ---------------- scratch (device globals; no allocs) ----------------
__device__ __half g_xh[(size_t)E_EXP * CAP * D_DIM];       // scattered tokens, fp16
__device__ __half g_acth[(size_t)E_EXP * CAP * I_DIM];     // fused silu out, fp16
__device__ float  g_eout[(size_t)E_EXP * CAP * D_DIM];
__device__ __half g_wug_th[(size_t)E_EXP * TWO_I * D_DIM]; // [E][2I permuted][D] fp16
__device__ __half g_wdn_th[(size_t)E_EXP * D_DIM * I_DIM]; // [E][D][I] fp16
__device__ int   g_sel[TK_SLOTS];
__device__ float g_comb[TK_SLOTS];
__device__ int   g_poslocal[TK_SLOTS];
__device__ int   g_slot[TK_SLOTS];
__device__ int   g_blkCnt[NB][E_EXP];
__device__ int   g_blkOff[NB][E_EXP];
__device__ int   g_cnt[E_EXP];
__device__ float g_sumprobs[E_EXP];
__device__ float g_z2;

// ---------------- helpers ----------------
__device__ __forceinline__ void mma_f16(float* c,
                                        uint32_t a0, uint32_t a1, uint32_t a2, uint32_t a3,
                                        uint32_t b0, uint32_t b1) {
    asm volatile("mma.sync.aligned.m16n8k16.row.col.f32.f16.f16.f32 "
                 "{%0,%1,%2,%3}, {%4,%5,%6,%7}, {%8,%9}, {%0,%1,%2,%3};"
                 : "+f"(c[0]), "+f"(c[1]), "+f"(c[2]), "+f"(c[3])
                 : "r"(a0), "r"(a1), "r"(a2), "r"(a3), "r"(b0), "r"(b1));
}
__device__ __forceinline__ uint32_t pack_h2(float a, float b) {
    __half2 h = __floats2half2_rn(a, b);
    return *reinterpret_cast<uint32_t*>(&h);
}
__device__ __forceinline__ uint32_t smem_u32(const void* p) {
    uint32_t a;
    asm("{ .reg .u64 t; cvta.to.shared.u64 t, %1; cvt.u32.u64 %0, t; }" : "=r"(a) : "l"(p));
    return a;
}
#define LDSM_X4(r0_, r1_, r2_, r3_, addr_) \
    asm volatile("ldmatrix.sync.aligned.m8n8.x4.shared.b16 {%0,%1,%2,%3}, [%4];" \
                 : "=r"(r0_), "=r"(r1_), "=r"(r2_), "=r"(r3_) : "r"(addr_))
#define CP_ASYNC16(dst_u32, src_ptr) \
    asm volatile("cp.async.cg.shared.global [%0], [%1], 16;" :: "r"(dst_u32), "l"(src_ptr))
#define CP_COMMIT()  asm volatile("cp.async.commit_group;")
#define CP_WAIT0()   asm volatile("cp.async.wait_group 0;")

// ---------------- stats zeroing ----------------
__global__ void zero_stats_kernel() {
    if (threadIdx.x < E_EXP) g_sumprobs[threadIdx.x] = 0.f;
    if (threadIdx.x == 0)    g_z2 = 0.f;
}

// ---------------- router: SMEM-cached weights, 32 tokens/block ----------------
#define R_PAD 20
#define R_SMEM_BYTES (D_DIM * R_PAD * 4)
__global__ __launch_bounds__(256) void router_kernel(const float* __restrict__ x,
                                                     const float* __restrict__ router) {
    extern __shared__ float rs[];          // [D_DIM][R_PAD]
    __shared__ float s_p[E_EXP];
    __shared__ float s_z2;
    const int tid  = threadIdx.x;
    const int wid  = tid >> 5;
    const int lane = tid & 31;
    if (tid < E_EXP) s_p[tid] = 0.f;
    if (tid == 0)    s_z2 = 0.f;
    for (int t = tid; t < D_DIM * E_EXP; t += 256)
        rs[(t >> 4) * R_PAD + (t & 15)] = router[t];
    __syncthreads();

    #pragma unroll
    for (int j = 0; j < 4; j++) {
        const int tok = blockIdx.x * 32 + wid * 4 + j;
        const float* xr = x + (size_t)tok * D_DIM;
        float acc[E_EXP];
        #pragma unroll
        for (int e = 0; e < E_EXP; e++) acc[e] = 0.f;
        for (int i = lane; i < D_DIM; i += 32) {
            const float xv = xr[i];
            const float4* rp = (const float4*)&rs[i * R_PAD];
            float4 r0 = rp[0], r1 = rp[1], r2 = rp[2], r3 = rp[3];
            acc[0]  += xv * r0.x; acc[1]  += xv * r0.y; acc[2]  += xv * r0.z; acc[3]  += xv * r0.w;
            acc[4]  += xv * r1.x; acc[5]  += xv * r1.y; acc[6]  += xv * r1.z; acc[7]  += xv * r1.w;
            acc[8]  += xv * r2.x; acc[9]  += xv * r2.y; acc[10] += xv * r2.z; acc[11] += xv * r2.w;
            acc[12] += xv * r3.x; acc[13] += xv * r3.y; acc[14] += xv * r3.z; acc[15] += xv * r3.w;
        }
        #pragma unroll
        for (int off = 16; off; off >>= 1) {
            #pragma unroll
            for (int e = 0; e < E_EXP; e++)
                acc[e] += __shfl_xor_sync(0xffffffffu, acc[e], off);
        }
        float m = acc[0];
        #pragma unroll
        for (int e = 1; e < E_EXP; e++) m = fmaxf(m, acc[e]);
        float se = 0.f;
        #pragma unroll
        for (int e = 0; e < E_EXP; e++) se += expf(acc[e] - m);
        const float z = m + logf(se);

        int i1 = 0; float l1 = acc[0];
        #pragma unroll
        for (int e = 1; e < E_EXP; e++) if (acc[e] > l1) { l1 = acc[e]; i1 = e; }
        int i2 = -1; float l2 = -1e30f;
        #pragma unroll
        for (int e = 0; e < E_EXP; e++)
            if (e != i1 && acc[e] > l2) { l2 = acc[e]; i2 = e; }

        const float q  = expf(l2 - l1);
        if (lane == 0) {
            g_sel[2 * tok]     = i1;
            g_sel[2 * tok + 1] = i2;
            g_comb[2 * tok]     = 1.f / (1.f + q);
            g_comb[2 * tok + 1] = q / (1.f + q);
            atomicAdd(&s_z2, z * z);
        }
        if (lane < E_EXP) atomicAdd(&s_p[lane], expf(acc[lane] - m) / se);
    }
    __syncthreads();
    if (tid < E_EXP) atomicAdd(&g_sumprobs[tid], s_p[tid]);
    if (tid == 0)    atomicAdd(&g_z2, s_z2);
}

// ---------------- ordered per-expert rank ----------------
__global__ void pos_kernel() {
    __shared__ int warpCnt[8][E_EXP];
    __shared__ int running[E_EXP];
    const int tid  = threadIdx.x;
    const int wid  = tid >> 5;
    const int lane = tid & 31;
    if (tid < E_EXP) running[tid] = 0;
    __syncthreads();

    const int base = blockIdx.x * SPB;
    for (int it = 0; it < SPB / 256; it++) {
        const int s = base + it * 256 + tid;
        const int e = g_sel[s];
        unsigned peers = __match_any_sync(0xffffffffu, e);
        const int rank = __popc(peers & ((1u << lane) - 1u));
        if (lane < E_EXP) warpCnt[wid][lane] = 0;
        __syncwarp();
        if (rank == 0) warpCnt[wid][e] = __popc(peers);
        __syncthreads();
        int off = running[e] + rank;
        for (int w = 0; w < wid; w++) off += warpCnt[w][e];
        g_poslocal[s] = off;
        __syncthreads();
        if (tid < E_EXP) {
            int tot = 0;
            #pragma unroll
            for (int w = 0; w < 8; w++) tot += warpCnt[w][tid];
            running[tid] += tot;
        }
        __syncthreads();
    }
    if (tid < E_EXP) g_blkCnt[blockIdx.x][tid] = running[tid];
}

__global__ void scan_kernel() {
    const int e = threadIdx.x;
    if (e >= E_EXP) return;
    int run = 0;
    for (int b = 0; b < NB; b++) {
        g_blkOff[b][e] = run;
        run += g_blkCnt[b][e];
    }
    g_cnt[e] = run;
}

// ---------------- scatter (converts x to fp16) ----------------
__global__ void scatter_kernel(const float* __restrict__ x) {
    const int gwarp = (blockIdx.x * blockDim.x + threadIdx.x) >> 5;
    const int lane  = threadIdx.x & 31;
    if (gwarp >= TK_SLOTS) return;
    const int e   = g_sel[gwarp];
    const int pos = g_poslocal[gwarp] + g_blkOff[gwarp / SPB][e];
    int slot = -1;
    if (pos < CAP) {
        slot = e * CAP + pos;
        const float4* src = (const float4*)(x + (size_t)(gwarp >> 1) * D_DIM);
        uint2* dst = (uint2*)(g_xh + (size_t)slot * D_DIM);
        #pragma unroll
        for (int i = 0; i < 8; i++) {
            float4 v = src[lane + 32 * i];
            dst[lane + 32 * i] = make_uint2(pack_h2(v.x, v.y), pack_h2(v.z, v.w));
        }
    }
    if (lane == 0) g_slot[gwarp] = slot;
}

// ---------------- w_down transpose + fp16 (unchanged layout) ----------------
__global__ void transpose_kernel(const float* __restrict__ src, __half* __restrict__ dst,
                                 int R, int Cd) {
    __shared__ float tile[32][33];
    const float* S = src + (size_t)blockIdx.z * R * Cd;
    __half* Dp = dst + (size_t)blockIdx.z * R * Cd;
    const int c0 = blockIdx.x * 32, r0 = blockIdx.y * 32;
    const int tx = threadIdx.x, ty = threadIdx.y;
    #pragma unroll
    for (int i = 0; i < 32; i += 8)
        tile[ty + i][tx] = S[(size_t)(r0 + ty + i) * Cd + (c0 + tx)];
    __syncthreads();
    #pragma unroll
    for (int i = 0; i < 32; i += 8)
        Dp[(size_t)(c0 + ty + i) * R + (r0 + tx)] = __float2half_rn(tile[tx][ty + i]);
}

// ---------------- w_up_gate transpose with gate/up 8-col interleave ----------------
// src [D][2I]: cols 0..I-1 = gate, I..2I-1 = up.
// dst rows (pcol): gate j -> 16*(j/8) + (j%8); up j -> 16*(j/8) + 8 + (j%8).
__global__ void transpose_ug_kernel(const float* __restrict__ src, __half* __restrict__ dst) {
    __shared__ float tile[32][33];
    const float* S = src + (size_t)blockIdx.z * D_DIM * TWO_I;
    __half* Dp = dst + (size_t)blockIdx.z * TWO_I * D_DIM;
    const int c0 = blockIdx.x * 32, r0 = blockIdx.y * 32;
    const int tx = threadIdx.x, ty = threadIdx.y;
    #pragma unroll
    for (int i = 0; i < 32; i += 8)
        tile[ty + i][tx] = S[(size_t)(r0 + ty + i) * TWO_I + (c0 + tx)];
    __syncthreads();
    #pragma unroll
    for (int i = 0; i < 32; i += 8) {
        const int c = c0 + ty + i;                 // source column
        int pcol;
        if (c < I_DIM) pcol = 16 * (c >> 3) + (c & 7);
        else { const int j = c - I_DIM; pcol = 16 * (j >> 3) + 8 + (j & 7); }
        Dp[(size_t)pcol * D_DIM + (r0 + tx)] = __float2half_rn(tile[tx][ty + i]);
    }
}

// ---------------- fp16 mma.sync grouped GEMM: cp.async 2-stage, K-chunk 64 ----------------
// WHICH==1: A=g_xh, B=wug_t (interleaved), epilogue fuses silu(gate)*up -> g_acth (fp16)
// WHICH==2: A=g_acth, B=wdn_t, C=g_eout (fp32)
#define SU 36
#define TILE_U (128 * SU)
#define BUF_U  (2 * TILE_U)
#define HG_SMEM (2 * BUF_U * 4)           // 73728 bytes

template <int Kdim, int Ndim, int WHICH>
__global__ __launch_bounds__(256, 2)
void hgemm_kernel(const __half* __restrict__ Wt) {
    const int e   = blockIdx.z;
    const int cnt = g_cnt[e];
    const int m0  = blockIdx.y * 128;
    if (m0 >= cnt) return;
    const int n0  = blockIdx.x * 128;

    const __half* __restrict__ Ah = ((WHICH == 1) ? g_xh : g_acth)
                                    + (size_t)e * CAP * Kdim + (size_t)m0 * Kdim;
    const __half* __restrict__ Bh = Wt + (size_t)e * Ndim * Kdim + (size_t)n0 * Kdim;

    extern __shared__ uint32_t smem[];
    const uint32_t smem_base = smem_u32(smem);

    const int tid  = threadIdx.x;
    const int lane = tid & 31;
    const int wid  = tid >> 5;
    const int warp_m = (wid >> 2) * 64;
    const int warp_n = (wid & 3) * 32;
    const int g  = lane >> 2;
    const int t4 = lane & 3;

    float acc[4][4][4];
    #pragma unroll
    for (int i = 0; i < 4; i++)
        #pragma unroll
        for (int j = 0; j < 4; j++)
            #pragma unroll
            for (int q = 0; q < 4; q++) acc[i][j][q] = 0.f;

    const int sRow  = tid >> 1;
    const int jBase = (tid & 1) * 4;

    const int aRow = warp_m + (lane & 15);
    const int aOff = 4 * (lane >> 4);
    const int bRow = warp_n + 8 * ((lane >> 4) & 1) + (lane & 7);
    const int bOff = 4 * ((lane >> 3) & 1);
    uint32_t aAddr[2], bAddr[2];
    #pragma unroll
    for (int b = 0; b < 2; b++) {
        aAddr[b] = smem_base + (uint32_t)(b * BUF_U + aRow * SU + aOff) * 4u;
        bAddr[b] = smem_base + (uint32_t)(b * BUF_U + TILE_U + bRow * SU + bOff) * 4u;
    }

    const int NC = Kdim / 64;

    #define HG_ISSUE(c_) do {                                                     \
        const uint32_t dstA = smem_base + (uint32_t)(((c_) & 1) * BUF_U) * 4u;    \
        const uint32_t dstB = dstA + (uint32_t)TILE_U * 4u;                       \
        const int k0_ = (c_) * 64;                                                \
        _Pragma("unroll")                                                         \
        for (int i_ = 0; i_ < 4; i_++) {                                          \
            const int j_ = jBase + i_;                                            \
            const uint32_t so = (uint32_t)(sRow * SU + j_ * 4) * 4u;              \
            CP_ASYNC16(dstA + so, Ah + (size_t)sRow * Kdim + k0_ + j_ * 8);       \
            CP_ASYNC16(dstB + so, Bh + (size_t)sRow * Kdim + k0_ + j_ * 8);       \
        }                                                                         \
        CP_COMMIT();                                                              \
    } while (0)

    HG_ISSUE(0);

    for (int c = 0; c < NC; c++) {
        const int buf = c & 1;
        CP_WAIT0();
        __syncthreads();
        if (c + 1 < NC) HG_ISSUE(c + 1);

        #pragma unroll
        for (int ks = 0; ks < 4; ks++) {
            uint32_t bf[4][2];
            #pragma unroll
            for (int p = 0; p < 2; p++) {
                LDSM_X4(bf[2 * p][0], bf[2 * p][1], bf[2 * p + 1][0], bf[2 * p + 1][1],
                        bAddr[buf] + (uint32_t)(p * 16 * SU * 4 + ks * 32));
            }
            #pragma unroll
            for (int mf = 0; mf < 4; mf++) {
                uint32_t a0, a1, a2, a3;
                LDSM_X4(a0, a1, a2, a3,
                        aAddr[buf] + (uint32_t)(mf * 16 * SU * 4 + ks * 32));
                #pragma unroll
                for (int nf = 0; nf < 4; nf++)
                    mma_f16(acc[mf][nf], a0, a1, a2, a3, bf[nf][0], bf[nf][1]);
            }
        }
    }

    if (WHICH == 1) {
        // fused silu(gate)*up -> g_acth fp16; nf even = gate, nf odd = up (same cols)
        __half* Ao = g_acth + (size_t)(e * CAP + m0) * I_DIM;
        #pragma unroll
        for (int mf = 0; mf < 4; mf++) {
            const int row = warp_m + mf * 16 + g;
            #pragma unroll
            for (int pr = 0; pr < 2; pr++) {
                const int j = n0 / 2 + ((wid & 3) * 2 + pr) * 8 + t4 * 2;
                const float* gg = acc[mf][2 * pr];
                const float* uu = acc[mf][2 * pr + 1];
                const float a0 = gg[0] / (1.f + expf(-gg[0])) * uu[0];
                const float a1 = gg[1] / (1.f + expf(-gg[1])) * uu[1];
                const float a2 = gg[2] / (1.f + expf(-gg[2])) * uu[2];
                const float a3 = gg[3] / (1.f + expf(-gg[3])) * uu[3];
                *(uint32_t*)(Ao + (size_t)row * I_DIM + j)       = pack_h2(a0, a1);
                *(uint32_t*)(Ao + (size_t)(row + 8) * I_DIM + j) = pack_h2(a2, a3);
            }
        }
    } else {
        float* C = g_eout + (size_t)(e * CAP + m0) * Ndim + n0;
        #pragma unroll
        for (int mf = 0; mf < 4; mf++) {
            const int row = warp_m + mf * 16 + g;
            #pragma unroll
            for (int nf = 0; nf < 4; nf++) {
                const int col = warp_n + nf * 8 + t4 * 2;
                *(float2*)(C + (size_t)row * Ndim + col) =
                    make_float2(acc[mf][nf][0], acc[mf][nf][1]);
                *(float2*)(C + (size_t)(row + 8) * Ndim + col) =
                    make_float2(acc[mf][nf][2], acc[mf][nf][3]);
            }
        }
    }
}

// ---------------- gather + combine ----------------
__global__ void gather_kernel(float* __restrict__ out) {
    const int t    = (blockIdx.x * blockDim.x + threadIdx.x) >> 5;
    const int lane = threadIdx.x & 31;
    if (t >= T_TOK) return;
    const int s0 = 2 * t, s1 = s0 + 1;
    const int sl0 = g_slot[s0], sl1 = g_slot[s1];
    const float w0 = g_comb[s0], w1 = g_comb[s1];
    const float4* r0 = (sl0 >= 0) ? (const float4*)(g_eout + (size_t)sl0 * D_DIM) : nullptr;
    const float4* r1 = (sl1 >= 0) ? (const float4*)(g_eout + (size_t)sl1 * D_DIM) : nullptr;
    float4* orow = (float4*)(out + (size_t)t * D_DIM);
    #pragma unroll
    for (int ii = 0; ii < 8; ii++) {
        const int i = lane + 32 * ii;
        float4 a = make_float4(0.f, 0.f, 0.f, 0.f);
        if (r0) { float4 v = r0[i]; a.x += w0 * v.x; a.y += w0 * v.y; a.z += w0 * v.z; a.w += w0 * v.w; }
        if (r1) { float4 v = r1[i]; a.x += w1 * v.x; a.y += w1 * v.y; a.z += w1 * v.z; a.w += w1 * v.w; }
        orow[i] = a;
    }
}

// ---------------- final scalars ----------------
__global__ void finalize_kernel(float* __restrict__ out) {
    __shared__ float cnts[E_EXP];
    const size_t base = (size_t)T_TOK * D_DIM;
    if (threadIdx.x < E_EXP) {
        float c = (float)g_cnt[threadIdx.x];
        cnts[threadIdx.x] = c;
        out[base + threadIdx.x] = c;
    }
    __syncthreads();
    if (threadIdx.x == 0) {
        float total = 0.f;
        #pragma unroll
        for (int e = 0; e < E_EXP; e++) total += cnts[e];
        total = fmaxf(total, 1.f);
        float ent = 0.f, lb = 0.f;
        #pragma unroll
        for (int e = 0; e < E_EXP; e++) {
            float f = cnts[e] / total;
            ent -= f * logf(f + 1e-6f);
            lb  += (f * 2.0f) * (g_sumprobs[e] / (float)T_TOK);
        }
        lb *= (float)E_EXP;
        out[base + 16] = ent;
        out[base + 17] = lb;
        out[base + 18] = g_z2 / (float)T_TOK;
    }
}

// ---------------- launch ----------------
extern "C" void kernel_launch(void* const* d_in, const int* in_sizes, int n_in,
                              void* d_out, int out_size) {
    const float* x      = (const float*)d_in[0];
    const float* router = (const float*)d_in[1];
    const float* w_ug   = (const float*)d_in[2];
    const float* w_dn   = (const float*)d_in[3];
    float* out = (float*)d_out;

    __half *wug_t = nullptr, *wdn_t = nullptr;
    cudaGetSymbolAddress((void**)&wug_t, g_wug_th);
    cudaGetSymbolAddress((void**)&wdn_t, g_wdn_th);

    static bool attr_done = false;
    if (!attr_done) {
        cudaFuncSetAttribute(router_kernel, cudaFuncAttributeMaxDynamicSharedMemorySize, R_SMEM_BYTES);
        cudaFuncSetAttribute(hgemm_kernel<D_DIM, TWO_I, 1>,
                             cudaFuncAttributeMaxDynamicSharedMemorySize, HG_SMEM);
        cudaFuncSetAttribute(hgemm_kernel<I_DIM, D_DIM, 2>,
                             cudaFuncAttributeMaxDynamicSharedMemorySize, HG_SMEM);
        attr_done = true;
    }

    transpose_ug_kernel<<<dim3(TWO_I / 32, D_DIM / 32, E_EXP), dim3(32, 8)>>>(w_ug, wug_t);
    transpose_kernel<<<dim3(D_DIM / 32, I_DIM / 32, E_EXP), dim3(32, 8)>>>(w_dn, wdn_t, I_DIM, D_DIM);

    zero_stats_kernel<<<1, 32>>>();
    router_kernel<<<T_TOK / 32, 256, R_SMEM_BYTES>>>(x, router);
    pos_kernel<<<NB, 256>>>();
    scan_kernel<<<1, 32>>>();
    scatter_kernel<<<TK_SLOTS / 8, 256>>>(x);

    hgemm_kernel<D_DIM, TWO_I, 1>
        <<<dim3(TWO_I / 128, CAP / 128, E_EXP), 256, HG_SMEM>>>(wug_t);
    hgemm_kernel<I_DIM, D_DIM, 2>
        <<<dim3(D_DIM / 128, CAP / 128, E_EXP), 256, HG_SMEM>>>(wdn_t);

    gather_kernel<<<T_TOK / 8, 256>>>(out);
    finalize_kernel<<<1, 32>>>(out);
}

// round 11
// speedup vs baseline: 2.0699x; 1.0273x over previous
#include <cuda_runtime.h>
#include <cuda_fp16.h>
#include <math.h>
#include <stdint.h>

// ---------------- problem constants ----------------
#define T_TOK   32768
#define D_DIM   1024
#define E_EXP   16
#define I_DIM   2816
#define TWO_I   5632
#define TK_SLOTS 65536
#define CAP     5120
#define NB      64
#define SPB     1024
#define RBLK    1024        // router grid blocks (T_TOK/32)

// ---------------- scratch (device globals; no allocs) ----------------
__device__ __half g_xh[(size_t)E_EXP * CAP * D_DIM];       // scattered tokens, fp16
__device__ __half g_acth[(size_t)E_EXP * CAP * I_DIM];     // fused silu out, fp16
__device__ float  g_eout[(size_t)E_EXP * CAP * D_DIM];
__device__ __half g_wug_th[(size_t)E_EXP * TWO_I * D_DIM]; // [E][2I permuted][D] fp16
__device__ __half g_wdn_th[(size_t)E_EXP * D_DIM * I_DIM]; // [E][D][I] fp16
__device__ int   g_sel[TK_SLOTS];
__device__ float g_comb[TK_SLOTS];
__device__ int   g_poslocal[TK_SLOTS];
__device__ int   g_slot[TK_SLOTS];
__device__ int   g_blkCnt[NB][E_EXP];
__device__ int   g_blkOff[NB][E_EXP];
__device__ int   g_cnt[E_EXP];
__device__ float g_rp[RBLK][E_EXP];   // per-router-block prob partials (written, not accumulated)
__device__ float g_rz[RBLK];          // per-router-block z^2 partials
__device__ int   g_posDone;           // last-block-done flag (self-resetting)

// ---------------- helpers ----------------
__device__ __forceinline__ void mma_f16(float* c,
                                        uint32_t a0, uint32_t a1, uint32_t a2, uint32_t a3,
                                        uint32_t b0, uint32_t b1) {
    asm volatile("mma.sync.aligned.m16n8k16.row.col.f32.f16.f16.f32 "
                 "{%0,%1,%2,%3}, {%4,%5,%6,%7}, {%8,%9}, {%0,%1,%2,%3};"
                 : "+f"(c[0]), "+f"(c[1]), "+f"(c[2]), "+f"(c[3])
                 : "r"(a0), "r"(a1), "r"(a2), "r"(a3), "r"(b0), "r"(b1));
}
__device__ __forceinline__ uint32_t pack_h2(float a, float b) {
    __half2 h = __floats2half2_rn(a, b);
    return *reinterpret_cast<uint32_t*>(&h);
}
__device__ __forceinline__ uint32_t smem_u32(const void* p) {
    uint32_t a;
    asm("{ .reg .u64 t; cvta.to.shared.u64 t, %1; cvt.u32.u64 %0, t; }" : "=r"(a) : "l"(p));
    return a;
}
#define LDSM_X4(r0_, r1_, r2_, r3_, addr_) \
    asm volatile("ldmatrix.sync.aligned.m8n8.x4.shared.b16 {%0,%1,%2,%3}, [%4];" \
                 : "=r"(r0_), "=r"(r1_), "=r"(r2_), "=r"(r3_) : "r"(addr_))
#define CP_ASYNC16(dst_u32, src_ptr) \
    asm volatile("cp.async.cg.shared.global [%0], [%1], 16;" :: "r"(dst_u32), "l"(src_ptr))
#define CP_COMMIT()  asm volatile("cp.async.commit_group;")
#define CP_WAIT0()   asm volatile("cp.async.wait_group 0;")

// ---------------- router: SMEM-cached weights; per-block stat partials ----------------
#define R_PAD 20
#define R_SMEM_BYTES (D_DIM * R_PAD * 4)
__global__ __launch_bounds__(256) void router_kernel(const float* __restrict__ x,
                                                     const float* __restrict__ router) {
    extern __shared__ float rs[];          // [D_DIM][R_PAD]
    __shared__ float s_p[E_EXP];
    __shared__ float s_z2;
    const int tid  = threadIdx.x;
    const int wid  = tid >> 5;
    const int lane = tid & 31;
    if (tid < E_EXP) s_p[tid] = 0.f;
    if (tid == 0)    s_z2 = 0.f;
    for (int t = tid; t < D_DIM * E_EXP; t += 256)
        rs[(t >> 4) * R_PAD + (t & 15)] = router[t];
    __syncthreads();

    #pragma unroll
    for (int j = 0; j < 4; j++) {
        const int tok = blockIdx.x * 32 + wid * 4 + j;
        const float* xr = x + (size_t)tok * D_DIM;
        float acc[E_EXP];
        #pragma unroll
        for (int e = 0; e < E_EXP; e++) acc[e] = 0.f;
        for (int i = lane; i < D_DIM; i += 32) {
            const float xv = xr[i];
            const float4* rp = (const float4*)&rs[i * R_PAD];
            float4 r0 = rp[0], r1 = rp[1], r2 = rp[2], r3 = rp[3];
            acc[0]  += xv * r0.x; acc[1]  += xv * r0.y; acc[2]  += xv * r0.z; acc[3]  += xv * r0.w;
            acc[4]  += xv * r1.x; acc[5]  += xv * r1.y; acc[6]  += xv * r1.z; acc[7]  += xv * r1.w;
            acc[8]  += xv * r2.x; acc[9]  += xv * r2.y; acc[10] += xv * r2.z; acc[11] += xv * r2.w;
            acc[12] += xv * r3.x; acc[13] += xv * r3.y; acc[14] += xv * r3.z; acc[15] += xv * r3.w;
        }
        #pragma unroll
        for (int off = 16; off; off >>= 1) {
            #pragma unroll
            for (int e = 0; e < E_EXP; e++)
                acc[e] += __shfl_xor_sync(0xffffffffu, acc[e], off);
        }
        float m = acc[0];
        #pragma unroll
        for (int e = 1; e < E_EXP; e++) m = fmaxf(m, acc[e]);
        float se = 0.f;
        #pragma unroll
        for (int e = 0; e < E_EXP; e++) se += expf(acc[e] - m);
        const float z = m + logf(se);

        int i1 = 0; float l1 = acc[0];
        #pragma unroll
        for (int e = 1; e < E_EXP; e++) if (acc[e] > l1) { l1 = acc[e]; i1 = e; }
        int i2 = -1; float l2 = -1e30f;
        #pragma unroll
        for (int e = 0; e < E_EXP; e++)
            if (e != i1 && acc[e] > l2) { l2 = acc[e]; i2 = e; }

        const float q  = expf(l2 - l1);
        if (lane == 0) {
            g_sel[2 * tok]     = i1;
            g_sel[2 * tok + 1] = i2;
            g_comb[2 * tok]     = 1.f / (1.f + q);
            g_comb[2 * tok + 1] = q / (1.f + q);
            atomicAdd(&s_z2, z * z);
        }
        if (lane < E_EXP) atomicAdd(&s_p[lane], expf(acc[lane] - m) / se);
    }
    __syncthreads();
    if (tid < E_EXP) g_rp[blockIdx.x][tid] = s_p[tid];
    if (tid == 0)    g_rz[blockIdx.x] = s_z2;
}

// ---------------- ordered per-expert rank + fused last-block scan ----------------
__global__ void pos_kernel() {
    __shared__ int warpCnt[8][E_EXP];
    __shared__ int running[E_EXP];
    __shared__ int s_last;
    const int tid  = threadIdx.x;
    const int wid  = tid >> 5;
    const int lane = tid & 31;
    if (tid < E_EXP) running[tid] = 0;
    __syncthreads();

    const int base = blockIdx.x * SPB;
    for (int it = 0; it < SPB / 256; it++) {
        const int s = base + it * 256 + tid;
        const int e = g_sel[s];
        unsigned peers = __match_any_sync(0xffffffffu, e);
        const int rank = __popc(peers & ((1u << lane) - 1u));
        if (lane < E_EXP) warpCnt[wid][lane] = 0;
        __syncwarp();
        if (rank == 0) warpCnt[wid][e] = __popc(peers);
        __syncthreads();
        int off = running[e] + rank;
        for (int w = 0; w < wid; w++) off += warpCnt[w][e];
        g_poslocal[s] = off;
        __syncthreads();
        if (tid < E_EXP) {
            int tot = 0;
            #pragma unroll
            for (int w = 0; w < 8; w++) tot += warpCnt[w][tid];
            running[tid] += tot;
        }
        __syncthreads();
    }
    if (tid < E_EXP) g_blkCnt[blockIdx.x][tid] = running[tid];
    __syncthreads();
    if (tid == 0) {
        __threadfence();
        s_last = (atomicAdd(&g_posDone, 1) == NB - 1) ? 1 : 0;
    }
    __syncthreads();
    if (s_last) {
        if (tid < E_EXP) {
            int run = 0;
            for (int b = 0; b < NB; b++) {
                g_blkOff[b][tid] = run;
                run += g_blkCnt[b][tid];
            }
            g_cnt[tid] = run;
        }
        __syncthreads();
        if (tid == 0) { g_posDone = 0; __threadfence(); }
    }
}

// ---------------- prep: scatter + both weight transposes, one heterogeneous grid ----------------
#define SC_BLOCKS 8192                        // TK_SLOTS / 8 warps
#define UG_BX (TWO_I / 32)                    // 176
#define UG_BY (D_DIM / 32)                    // 32
#define UG_BLOCKS (UG_BX * UG_BY * E_EXP)     // 90112
#define DN_BX (D_DIM / 32)                    // 32
#define DN_BY (I_DIM / 32)                    // 88
#define DN_BLOCKS (DN_BX * DN_BY * E_EXP)     // 45056
#define PREP_BLOCKS (SC_BLOCKS + UG_BLOCKS + DN_BLOCKS)

__global__ __launch_bounds__(256) void prep_kernel(const float* __restrict__ x,
                                                   const float* __restrict__ w_ug,
                                                   const float* __restrict__ w_dn) {
    __shared__ float tile[32][33];
    const int bid = blockIdx.x;
    const int tid = threadIdx.x;

    if (bid < SC_BLOCKS) {
        // ---- scatter (converts x to fp16) ----
        const int gwarp = (bid * 256 + tid) >> 5;
        const int lane  = tid & 31;
        const int e   = g_sel[gwarp];
        const int pos = g_poslocal[gwarp] + g_blkOff[gwarp / SPB][e];
        int slot = -1;
        if (pos < CAP) {
            slot = e * CAP + pos;
            const float4* src = (const float4*)(x + (size_t)(gwarp >> 1) * D_DIM);
            uint2* dst = (uint2*)(g_xh + (size_t)slot * D_DIM);
            #pragma unroll
            for (int i = 0; i < 8; i++) {
                float4 v = src[lane + 32 * i];
                dst[lane + 32 * i] = make_uint2(pack_h2(v.x, v.y), pack_h2(v.z, v.w));
            }
        }
        if (lane == 0) g_slot[gwarp] = slot;
        return;
    }

    const int tx = tid & 31, ty = tid >> 5;
    if (bid < SC_BLOCKS + UG_BLOCKS) {
        // ---- w_up_gate transpose with gate/up 8-col interleave ----
        const int t = bid - SC_BLOCKS;
        const int z = t / (UG_BX * UG_BY);
        const int rem = t % (UG_BX * UG_BY);
        const int bx = rem % UG_BX, by = rem / UG_BX;
        const float* S = w_ug + (size_t)z * D_DIM * TWO_I;
        __half* Dp = g_wug_th + (size_t)z * TWO_I * D_DIM;
        const int c0 = bx * 32, r0 = by * 32;
        #pragma unroll
        for (int i = 0; i < 32; i += 8)
            tile[ty + i][tx] = S[(size_t)(r0 + ty + i) * TWO_I + (c0 + tx)];
        __syncthreads();
        #pragma unroll
        for (int i = 0; i < 32; i += 8) {
            const int c = c0 + ty + i;
            int pcol;
            if (c < I_DIM) pcol = 16 * (c >> 3) + (c & 7);
            else { const int j = c - I_DIM; pcol = 16 * (j >> 3) + 8 + (j & 7); }
            Dp[(size_t)pcol * D_DIM + (r0 + tx)] = __float2half_rn(tile[tx][ty + i]);
        }
    } else {
        // ---- w_down transpose (plain) ----
        const int t = bid - SC_BLOCKS - UG_BLOCKS;
        const int z = t / (DN_BX * DN_BY);
        const int rem = t % (DN_BX * DN_BY);
        const int bx = rem % DN_BX, by = rem / DN_BX;
        const float* S = w_dn + (size_t)z * I_DIM * D_DIM;
        __half* Dp = g_wdn_th + (size_t)z * D_DIM * I_DIM;
        const int c0 = bx * 32, r0 = by * 32;
        #pragma unroll
        for (int i = 0; i < 32; i += 8)
            tile[ty + i][tx] = S[(size_t)(r0 + ty + i) * D_DIM + (c0 + tx)];
        __syncthreads();
        #pragma unroll
        for (int i = 0; i < 32; i += 8)
            Dp[(size_t)(c0 + ty + i) * I_DIM + (r0 + tx)] = __float2half_rn(tile[tx][ty + i]);
    }
}

// ---------------- fp16 mma.sync grouped GEMM: cp.async 2-stage, K-chunk 64 ----------------
// WHICH==1: A=g_xh, B=wug_t (interleaved), epilogue fuses silu(gate)*up -> g_acth (fp16)
// WHICH==2: A=g_acth, B=wdn_t, C=g_eout (fp32)
#define SU 36
#define TILE_U (128 * SU)
#define BUF_U  (2 * TILE_U)
#define HG_SMEM (2 * BUF_U * 4)           // 73728 bytes

template <int Kdim, int Ndim, int WHICH>
__global__ __launch_bounds__(256, 2)
void hgemm_kernel(const __half* __restrict__ Wt) {
    const int e   = blockIdx.z;
    const int cnt = g_cnt[e];
    const int m0  = blockIdx.y * 128;
    if (m0 >= cnt) return;
    const int n0  = blockIdx.x * 128;

    const __half* __restrict__ Ah = ((WHICH == 1) ? g_xh : g_acth)
                                    + (size_t)e * CAP * Kdim + (size_t)m0 * Kdim;
    const __half* __restrict__ Bh = Wt + (size_t)e * Ndim * Kdim + (size_t)n0 * Kdim;

    extern __shared__ uint32_t smem[];
    const uint32_t smem_base = smem_u32(smem);

    const int tid  = threadIdx.x;
    const int lane = tid & 31;
    const int wid  = tid >> 5;
    const int warp_m = (wid >> 2) * 64;
    const int warp_n = (wid & 3) * 32;
    const int g  = lane >> 2;
    const int t4 = lane & 3;

    float acc[4][4][4];
    #pragma unroll
    for (int i = 0; i < 4; i++)
        #pragma unroll
        for (int j = 0; j < 4; j++)
            #pragma unroll
            for (int q = 0; q < 4; q++) acc[i][j][q] = 0.f;

    const int sRow  = tid >> 1;
    const int jBase = (tid & 1) * 4;

    const int aRow = warp_m + (lane & 15);
    const int aOff = 4 * (lane >> 4);
    const int bRow = warp_n + 8 * ((lane >> 4) & 1) + (lane & 7);
    const int bOff = 4 * ((lane >> 3) & 1);
    uint32_t aAddr[2], bAddr[2];
    #pragma unroll
    for (int b = 0; b < 2; b++) {
        aAddr[b] = smem_base + (uint32_t)(b * BUF_U + aRow * SU + aOff) * 4u;
        bAddr[b] = smem_base + (uint32_t)(b * BUF_U + TILE_U + bRow * SU + bOff) * 4u;
    }

    const int NC = Kdim / 64;

    #define HG_ISSUE(c_) do {                                                     \
        const uint32_t dstA = smem_base + (uint32_t)(((c_) & 1) * BUF_U) * 4u;    \
        const uint32_t dstB = dstA + (uint32_t)TILE_U * 4u;                       \
        const int k0_ = (c_) * 64;                                                \
        _Pragma("unroll")                                                         \
        for (int i_ = 0; i_ < 4; i_++) {                                          \
            const int j_ = jBase + i_;                                            \
            const uint32_t so = (uint32_t)(sRow * SU + j_ * 4) * 4u;              \
            CP_ASYNC16(dstA + so, Ah + (size_t)sRow * Kdim + k0_ + j_ * 8);       \
            CP_ASYNC16(dstB + so, Bh + (size_t)sRow * Kdim + k0_ + j_ * 8);       \
        }                                                                         \
        CP_COMMIT();                                                              \
    } while (0)

    HG_ISSUE(0);

    for (int c = 0; c < NC; c++) {
        const int buf = c & 1;
        CP_WAIT0();
        __syncthreads();
        if (c + 1 < NC) HG_ISSUE(c + 1);

        #pragma unroll
        for (int ks = 0; ks < 4; ks++) {
            uint32_t bf[4][2];
            #pragma unroll
            for (int p = 0; p < 2; p++) {
                LDSM_X4(bf[2 * p][0], bf[2 * p][1], bf[2 * p + 1][0], bf[2 * p + 1][1],
                        bAddr[buf] + (uint32_t)(p * 16 * SU * 4 + ks * 32));
            }
            #pragma unroll
            for (int mf = 0; mf < 4; mf++) {
                uint32_t a0, a1, a2, a3;
                LDSM_X4(a0, a1, a2, a3,
                        aAddr[buf] + (uint32_t)(mf * 16 * SU * 4 + ks * 32));
                #pragma unroll
                for (int nf = 0; nf < 4; nf++)
                    mma_f16(acc[mf][nf], a0, a1, a2, a3, bf[nf][0], bf[nf][1]);
            }
        }
    }

    if (WHICH == 1) {
        __half* Ao = g_acth + (size_t)(e * CAP + m0) * I_DIM;
        #pragma unroll
        for (int mf = 0; mf < 4; mf++) {
            const int row = warp_m + mf * 16 + g;
            #pragma unroll
            for (int pr = 0; pr < 2; pr++) {
                const int j = n0 / 2 + ((wid & 3) * 2 + pr) * 8 + t4 * 2;
                const float* gg = acc[mf][2 * pr];
                const float* uu = acc[mf][2 * pr + 1];
                const float a0 = gg[0] / (1.f + expf(-gg[0])) * uu[0];
                const float a1 = gg[1] / (1.f + expf(-gg[1])) * uu[1];
                const float a2 = gg[2] / (1.f + expf(-gg[2])) * uu[2];
                const float a3 = gg[3] / (1.f + expf(-gg[3])) * uu[3];
                *(uint32_t*)(Ao + (size_t)row * I_DIM + j)       = pack_h2(a0, a1);
                *(uint32_t*)(Ao + (size_t)(row + 8) * I_DIM + j) = pack_h2(a2, a3);
            }
        }
    } else {
        float* C = g_eout + (size_t)(e * CAP + m0) * Ndim + n0;
        #pragma unroll
        for (int mf = 0; mf < 4; mf++) {
            const int row = warp_m + mf * 16 + g;
            #pragma unroll
            for (int nf = 0; nf < 4; nf++) {
                const int col = warp_n + nf * 8 + t4 * 2;
                *(float2*)(C + (size_t)row * Ndim + col) =
                    make_float2(acc[mf][nf][0], acc[mf][nf][1]);
                *(float2*)(C + (size_t)(row + 8) * Ndim + col) =
                    make_float2(acc[mf][nf][2], acc[mf][nf][3]);
            }
        }
    }
}

// ---------------- gather + combine ----------------
__global__ void gather_kernel(float* __restrict__ out) {
    const int t    = (blockIdx.x * blockDim.x + threadIdx.x) >> 5;
    const int lane = threadIdx.x & 31;
    if (t >= T_TOK) return;
    const int s0 = 2 * t, s1 = s0 + 1;
    const int sl0 = g_slot[s0], sl1 = g_slot[s1];
    const float w0 = g_comb[s0], w1 = g_comb[s1];
    const float4* r0 = (sl0 >= 0) ? (const float4*)(g_eout + (size_t)sl0 * D_DIM) : nullptr;
    const float4* r1 = (sl1 >= 0) ? (const float4*)(g_eout + (size_t)sl1 * D_DIM) : nullptr;
    float4* orow = (float4*)(out + (size_t)t * D_DIM);
    #pragma unroll
    for (int ii = 0; ii < 8; ii++) {
        const int i = lane + 32 * ii;
        float4 a = make_float4(0.f, 0.f, 0.f, 0.f);
        if (r0) { float4 v = r0[i]; a.x += w0 * v.x; a.y += w0 * v.y; a.z += w0 * v.z; a.w += w0 * v.w; }
        if (r1) { float4 v = r1[i]; a.x += w1 * v.x; a.y += w1 * v.y; a.z += w1 * v.z; a.w += w1 * v.w; }
        orow[i] = a;
    }
}

// ---------------- final scalars (sums router partials; no atomics anywhere) ----------------
__global__ __launch_bounds__(256) void finalize_kernel(float* __restrict__ out) {
    __shared__ float sp[16][E_EXP];   // [part][expert]
    __shared__ float sz[256];
    __shared__ float s_sum[E_EXP];
    const int tid = threadIdx.x;
    const int e = tid & 15, p = tid >> 4;

    float s = 0.f;
    for (int b = p; b < RBLK; b += 16) s += g_rp[b][e];
    sp[p][e] = s;
    float zz = 0.f;
    for (int b = tid; b < RBLK; b += 256) zz += g_rz[b];
    sz[tid] = zz;
    __syncthreads();

    if (tid < E_EXP) {
        float tsum = 0.f;
        #pragma unroll
        for (int p2 = 0; p2 < 16; p2++) tsum += sp[p2][tid];
        s_sum[tid] = tsum;
    }
    if (tid == 16) {
        float t = 0.f;
        for (int i = 0; i < 256; i++) t += sz[i];
        sz[0] = t;
    }
    __syncthreads();

    const size_t base = (size_t)T_TOK * D_DIM;
    if (tid < E_EXP) out[base + tid] = (float)g_cnt[tid];
    if (tid == 0) {
        float total = 0.f;
        #pragma unroll
        for (int ee = 0; ee < E_EXP; ee++) total += (float)g_cnt[ee];
        total = fmaxf(total, 1.f);
        float ent = 0.f, lb = 0.f;
        #pragma unroll
        for (int ee = 0; ee < E_EXP; ee++) {
            float f = (float)g_cnt[ee] / total;
            ent -= f * logf(f + 1e-6f);
            lb  += (f * 2.0f) * (s_sum[ee] / (float)T_TOK);
        }
        lb *= (float)E_EXP;
        out[base + 16] = ent;
        out[base + 17] = lb;
        out[base + 18] = sz[0] / (float)T_TOK;
    }
}

// ---------------- launch ----------------
extern "C" void kernel_launch(void* const* d_in, const int* in_sizes, int n_in,
                              void* d_out, int out_size) {
    const float* x      = (const float*)d_in[0];
    const float* router = (const float*)d_in[1];
    const float* w_ug   = (const float*)d_in[2];
    const float* w_dn   = (const float*)d_in[3];
    float* out = (float*)d_out;

    __half *wug_t = nullptr, *wdn_t = nullptr;
    cudaGetSymbolAddress((void**)&wug_t, g_wug_th);
    cudaGetSymbolAddress((void**)&wdn_t, g_wdn_th);

    static bool attr_done = false;
    if (!attr_done) {
        cudaFuncSetAttribute(router_kernel, cudaFuncAttributeMaxDynamicSharedMemorySize, R_SMEM_BYTES);
        cudaFuncSetAttribute(hgemm_kernel<D_DIM, TWO_I, 1>,
                             cudaFuncAttributeMaxDynamicSharedMemorySize, HG_SMEM);
        cudaFuncSetAttribute(hgemm_kernel<I_DIM, D_DIM, 2>,
                             cudaFuncAttributeMaxDynamicSharedMemorySize, HG_SMEM);
        attr_done = true;
    }

    // launch index:                                   0
    router_kernel<<<RBLK, 256, R_SMEM_BYTES>>>(x, router);
    // 1: pos + fused scan
    pos_kernel<<<NB, 256>>>();
    // 2: scatter + both weight transposes
    prep_kernel<<<PREP_BLOCKS, 256>>>(x, w_ug, w_dn);
    // 3: GEMM1  <-- ncu capture lands here
    hgemm_kernel<D_DIM, TWO_I, 1>
        <<<dim3(TWO_I / 128, CAP / 128, E_EXP), 256, HG_SMEM>>>(wug_t);
    // 4: GEMM2
    hgemm_kernel<I_DIM, D_DIM, 2>
        <<<dim3(D_DIM / 128, CAP / 128, E_EXP), 256, HG_SMEM>>>(wdn_t);
    // 5: gather, 6: finalize
    gather_kernel<<<T_TOK / 8, 256>>>(out);
    finalize_kernel<<<1, 256>>>(out);
}

// round 12
// speedup vs baseline: 2.1655x; 1.0462x over previous
#include <cuda_runtime.h>
#include <cuda_fp16.h>
#include <math.h>
#include <stdint.h>

// ---------------- problem constants ----------------
#define T_TOK   32768
#define D_DIM   1024
#define E_EXP   16
#define I_DIM   2816
#define TWO_I   5632
#define TK_SLOTS 65536
#define CAP     5120
#define NB      64
#define SPB     1024
#define RBLK    1024

// ---------------- scratch (device globals; no allocs) ----------------
__device__ __half g_xh[(size_t)E_EXP * CAP * D_DIM];
__device__ __half g_acth[(size_t)E_EXP * CAP * I_DIM];
__device__ float  g_eout[(size_t)E_EXP * CAP * D_DIM];
__device__ __half g_wug_th[(size_t)E_EXP * TWO_I * D_DIM];
__device__ __half g_wdn_th[(size_t)E_EXP * D_DIM * I_DIM];
__device__ int   g_sel[TK_SLOTS];
__device__ float g_comb[TK_SLOTS];
__device__ int   g_poslocal[TK_SLOTS];
__device__ int   g_slot[TK_SLOTS];
__device__ int   g_blkCnt[NB][E_EXP];
__device__ int   g_blkOff[NB][E_EXP];
__device__ int   g_cnt[E_EXP];
__device__ float g_rp[RBLK][E_EXP];
__device__ float g_rz[RBLK];
__device__ int   g_posDone;

// ---------------- helpers ----------------
__device__ __forceinline__ void mma_f16(float* c,
                                        uint32_t a0, uint32_t a1, uint32_t a2, uint32_t a3,
                                        uint32_t b0, uint32_t b1) {
    asm volatile("mma.sync.aligned.m16n8k16.row.col.f32.f16.f16.f32 "
                 "{%0,%1,%2,%3}, {%4,%5,%6,%7}, {%8,%9}, {%0,%1,%2,%3};"
                 : "+f"(c[0]), "+f"(c[1]), "+f"(c[2]), "+f"(c[3])
                 : "r"(a0), "r"(a1), "r"(a2), "r"(a3), "r"(b0), "r"(b1));
}
__device__ __forceinline__ uint32_t pack_h2(float a, float b) {
    __half2 h = __floats2half2_rn(a, b);
    return *reinterpret_cast<uint32_t*>(&h);
}
__device__ __forceinline__ uint32_t smem_u32(const void* p) {
    uint32_t a;
    asm("{ .reg .u64 t; cvta.to.shared.u64 t, %1; cvt.u32.u64 %0, t; }" : "=r"(a) : "l"(p));
    return a;
}
#define LDSM_X4(r0_, r1_, r2_, r3_, addr_) \
    asm volatile("ldmatrix.sync.aligned.m8n8.x4.shared.b16 {%0,%1,%2,%3}, [%4];" \
                 : "=r"(r0_), "=r"(r1_), "=r"(r2_), "=r"(r3_) : "r"(addr_))
#define CP_ASYNC16(dst_u32, src_ptr) \
    asm volatile("cp.async.cg.shared.global [%0], [%1], 16;" :: "r"(dst_u32), "l"(src_ptr))
#define CP_COMMIT()  asm volatile("cp.async.commit_group;")
#define CP_WAIT0()   asm volatile("cp.async.wait_group 0;")

// ---------------- router ----------------
#define R_PAD 20
#define R_SMEM_BYTES (D_DIM * R_PAD * 4)
__global__ __launch_bounds__(256) void router_kernel(const float* __restrict__ x,
                                                     const float* __restrict__ router) {
    extern __shared__ float rs[];
    __shared__ float s_p[E_EXP];
    __shared__ float s_z2;
    const int tid  = threadIdx.x;
    const int wid  = tid >> 5;
    const int lane = tid & 31;
    if (tid < E_EXP) s_p[tid] = 0.f;
    if (tid == 0)    s_z2 = 0.f;
    for (int t = tid; t < D_DIM * E_EXP; t += 256)
        rs[(t >> 4) * R_PAD + (t & 15)] = router[t];
    __syncthreads();

    #pragma unroll
    for (int j = 0; j < 4; j++) {
        const int tok = blockIdx.x * 32 + wid * 4 + j;
        const float* xr = x + (size_t)tok * D_DIM;
        float acc[E_EXP];
        #pragma unroll
        for (int e = 0; e < E_EXP; e++) acc[e] = 0.f;
        for (int i = lane; i < D_DIM; i += 32) {
            const float xv = xr[i];
            const float4* rp = (const float4*)&rs[i * R_PAD];
            float4 r0 = rp[0], r1 = rp[1], r2 = rp[2], r3 = rp[3];
            acc[0]  += xv * r0.x; acc[1]  += xv * r0.y; acc[2]  += xv * r0.z; acc[3]  += xv * r0.w;
            acc[4]  += xv * r1.x; acc[5]  += xv * r1.y; acc[6]  += xv * r1.z; acc[7]  += xv * r1.w;
            acc[8]  += xv * r2.x; acc[9]  += xv * r2.y; acc[10] += xv * r2.z; acc[11] += xv * r2.w;
            acc[12] += xv * r3.x; acc[13] += xv * r3.y; acc[14] += xv * r3.z; acc[15] += xv * r3.w;
        }
        #pragma unroll
        for (int off = 16; off; off >>= 1) {
            #pragma unroll
            for (int e = 0; e < E_EXP; e++)
                acc[e] += __shfl_xor_sync(0xffffffffu, acc[e], off);
        }
        float m = acc[0];
        #pragma unroll
        for (int e = 1; e < E_EXP; e++) m = fmaxf(m, acc[e]);
        float se = 0.f;
        #pragma unroll
        for (int e = 0; e < E_EXP; e++) se += expf(acc[e] - m);
        const float z = m + logf(se);

        int i1 = 0; float l1 = acc[0];
        #pragma unroll
        for (int e = 1; e < E_EXP; e++) if (acc[e] > l1) { l1 = acc[e]; i1 = e; }
        int i2 = -1; float l2 = -1e30f;
        #pragma unroll
        for (int e = 0; e < E_EXP; e++)
            if (e != i1 && acc[e] > l2) { l2 = acc[e]; i2 = e; }

        const float q  = expf(l2 - l1);
        if (lane == 0) {
            g_sel[2 * tok]     = i1;
            g_sel[2 * tok + 1] = i2;
            g_comb[2 * tok]     = 1.f / (1.f + q);
            g_comb[2 * tok + 1] = q / (1.f + q);
            atomicAdd(&s_z2, z * z);
        }
        if (lane < E_EXP) atomicAdd(&s_p[lane], expf(acc[lane] - m) / se);
    }
    __syncthreads();
    if (tid < E_EXP) g_rp[blockIdx.x][tid] = s_p[tid];
    if (tid == 0)    g_rz[blockIdx.x] = s_z2;
}

// ---------------- ordered per-expert rank + fused last-block scan ----------------
__global__ void pos_kernel() {
    __shared__ int warpCnt[8][E_EXP];
    __shared__ int running[E_EXP];
    __shared__ int s_last;
    const int tid  = threadIdx.x;
    const int wid  = tid >> 5;
    const int lane = tid & 31;
    if (tid < E_EXP) running[tid] = 0;
    __syncthreads();

    const int base = blockIdx.x * SPB;
    for (int it = 0; it < SPB / 256; it++) {
        const int s = base + it * 256 + tid;
        const int e = g_sel[s];
        unsigned peers = __match_any_sync(0xffffffffu, e);
        const int rank = __popc(peers & ((1u << lane) - 1u));
        if (lane < E_EXP) warpCnt[wid][lane] = 0;
        __syncwarp();
        if (rank == 0) warpCnt[wid][e] = __popc(peers);
        __syncthreads();
        int off = running[e] + rank;
        for (int w = 0; w < wid; w++) off += warpCnt[w][e];
        g_poslocal[s] = off;
        __syncthreads();
        if (tid < E_EXP) {
            int tot = 0;
            #pragma unroll
            for (int w = 0; w < 8; w++) tot += warpCnt[w][tid];
            running[tid] += tot;
        }
        __syncthreads();
    }
    if (tid < E_EXP) g_blkCnt[blockIdx.x][tid] = running[tid];
    __syncthreads();
    if (tid == 0) {
        __threadfence();
        s_last = (atomicAdd(&g_posDone, 1) == NB - 1) ? 1 : 0;
    }
    __syncthreads();
    if (s_last) {
        if (tid < E_EXP) {
            int run = 0;
            for (int b = 0; b < NB; b++) {
                g_blkOff[b][tid] = run;
                run += g_blkCnt[b][tid];
            }
            g_cnt[tid] = run;
        }
        __syncthreads();
        if (tid == 0) { g_posDone = 0; __threadfence(); }
    }
}

// ---------------- prep: scatter + both weight transposes ----------------
#define SC_BLOCKS 8192
#define UG_BX (TWO_I / 32)
#define UG_BY (D_DIM / 32)
#define UG_BLOCKS (UG_BX * UG_BY * E_EXP)
#define DN_BX (D_DIM / 32)
#define DN_BY (I_DIM / 32)
#define DN_BLOCKS (DN_BX * DN_BY * E_EXP)
#define PREP_BLOCKS (SC_BLOCKS + UG_BLOCKS + DN_BLOCKS)

__global__ __launch_bounds__(256) void prep_kernel(const float* __restrict__ x,
                                                   const float* __restrict__ w_ug,
                                                   const float* __restrict__ w_dn) {
    __shared__ float tile[32][33];
    const int bid = blockIdx.x;
    const int tid = threadIdx.x;

    if (bid < SC_BLOCKS) {
        const int gwarp = (bid * 256 + tid) >> 5;
        const int lane  = tid & 31;
        const int e   = g_sel[gwarp];
        const int pos = g_poslocal[gwarp] + g_blkOff[gwarp / SPB][e];
        int slot = -1;
        if (pos < CAP) {
            slot = e * CAP + pos;
            const float4* src = (const float4*)(x + (size_t)(gwarp >> 1) * D_DIM);
            uint2* dst = (uint2*)(g_xh + (size_t)slot * D_DIM);
            #pragma unroll
            for (int i = 0; i < 8; i++) {
                float4 v = src[lane + 32 * i];
                dst[lane + 32 * i] = make_uint2(pack_h2(v.x, v.y), pack_h2(v.z, v.w));
            }
        }
        if (lane == 0) g_slot[gwarp] = slot;
        return;
    }

    const int tx = tid & 31, ty = tid >> 5;
    if (bid < SC_BLOCKS + UG_BLOCKS) {
        const int t = bid - SC_BLOCKS;
        const int z = t / (UG_BX * UG_BY);
        const int rem = t % (UG_BX * UG_BY);
        const int bx = rem % UG_BX, by = rem / UG_BX;
        const float* S = w_ug + (size_t)z * D_DIM * TWO_I;
        __half* Dp = g_wug_th + (size_t)z * TWO_I * D_DIM;
        const int c0 = bx * 32, r0 = by * 32;
        #pragma unroll
        for (int i = 0; i < 32; i += 8)
            tile[ty + i][tx] = S[(size_t)(r0 + ty + i) * TWO_I + (c0 + tx)];
        __syncthreads();
        #pragma unroll
        for (int i = 0; i < 32; i += 8) {
            const int c = c0 + ty + i;
            int pcol;
            if (c < I_DIM) pcol = 16 * (c >> 3) + (c & 7);
            else { const int j = c - I_DIM; pcol = 16 * (j >> 3) + 8 + (j & 7); }
            Dp[(size_t)pcol * D_DIM + (r0 + tx)] = __float2half_rn(tile[tx][ty + i]);
        }
    } else {
        const int t = bid - SC_BLOCKS - UG_BLOCKS;
        const int z = t / (DN_BX * DN_BY);
        const int rem = t % (DN_BX * DN_BY);
        const int bx = rem % DN_BX, by = rem / DN_BX;
        const float* S = w_dn + (size_t)z * I_DIM * D_DIM;
        __half* Dp = g_wdn_th + (size_t)z * D_DIM * I_DIM;
        const int c0 = bx * 32, r0 = by * 32;
        #pragma unroll
        for (int i = 0; i < 32; i += 8)
            tile[ty + i][tx] = S[(size_t)(r0 + ty + i) * D_DIM + (c0 + tx)];
        __syncthreads();
        #pragma unroll
        for (int i = 0; i < 32; i += 8)
            Dp[(size_t)(c0 + ty + i) * I_DIM + (r0 + tx)] = __float2half_rn(tile[tx][ty + i]);
    }
}

// ---------------- fp16 mma GEMM: CTA 256x128, 512 threads, cp.async 2-stage, K-chunk 64 ----
// 16 warps: 4(m) x 4(n); warp tile 64x32 (same per-thread work as before).
// A tile 256 rows, B tile 128 rows; SU=36 u32 row stride.
#define SU 36
#define A_TILE_U (256 * SU)
#define B_TILE_U (128 * SU)
#define BUF_U  (A_TILE_U + B_TILE_U)
#define HG_SMEM (2 * BUF_U * 4)           // 110592 bytes

template <int Kdim, int Ndim, int WHICH>
__global__ __launch_bounds__(512, 1)
void hgemm_kernel(const __half* __restrict__ Wt) {
    const int e   = blockIdx.z;
    const int cnt = g_cnt[e];
    const int m0  = blockIdx.y * 256;
    if (m0 >= cnt) return;
    const int n0  = blockIdx.x * 128;

    const __half* __restrict__ Ah = ((WHICH == 1) ? g_xh : g_acth)
                                    + (size_t)e * CAP * Kdim + (size_t)m0 * Kdim;
    const __half* __restrict__ Bh = Wt + (size_t)e * Ndim * Kdim + (size_t)n0 * Kdim;

    extern __shared__ uint32_t smem[];
    const uint32_t smem_base = smem_u32(smem);

    const int tid  = threadIdx.x;
    const int lane = tid & 31;
    const int wid  = tid >> 5;                // 0..15
    const int warp_m = (wid >> 2) * 64;       // 0,64,128,192
    const int warp_n = (wid & 3) * 32;        // 0,32,64,96
    const int g  = lane >> 2;
    const int t4 = lane & 3;

    float acc[4][4][4];
    #pragma unroll
    for (int i = 0; i < 4; i++)
        #pragma unroll
        for (int j = 0; j < 4; j++)
            #pragma unroll
            for (int q = 0; q < 4; q++) acc[i][j][q] = 0.f;

    // cp.async maps: A rows 0..255 (4 pieces/thread), B rows 0..127 (2 pieces/thread)
    const int aSRow = tid >> 1;               // 0..255
    const int aJ0   = (tid & 1) * 4;          // 0 or 4
    const int bSRow = tid >> 2;               // 0..127
    const int bJ0   = (tid & 3) * 2;          // 0,2,4,6

    const int aRow = warp_m + (lane & 15);
    const int aOff = 4 * (lane >> 4);
    const int bRow = warp_n + 8 * ((lane >> 4) & 1) + (lane & 7);
    const int bOff = 4 * ((lane >> 3) & 1);
    uint32_t aAddr[2], bAddr[2];
    #pragma unroll
    for (int b = 0; b < 2; b++) {
        aAddr[b] = smem_base + (uint32_t)(b * BUF_U + aRow * SU + aOff) * 4u;
        bAddr[b] = smem_base + (uint32_t)(b * BUF_U + A_TILE_U + bRow * SU + bOff) * 4u;
    }

    const int NC = Kdim / 64;

    #define HG_ISSUE(c_) do {                                                     \
        const uint32_t dstA = smem_base + (uint32_t)(((c_) & 1) * BUF_U) * 4u;    \
        const uint32_t dstB = dstA + (uint32_t)A_TILE_U * 4u;                     \
        const int k0_ = (c_) * 64;                                                \
        _Pragma("unroll")                                                         \
        for (int i_ = 0; i_ < 4; i_++) {                                          \
            const int j_ = aJ0 + i_;                                              \
            CP_ASYNC16(dstA + (uint32_t)(aSRow * SU + j_ * 4) * 4u,               \
                       Ah + (size_t)aSRow * Kdim + k0_ + j_ * 8);                 \
        }                                                                         \
        _Pragma("unroll")                                                         \
        for (int i_ = 0; i_ < 2; i_++) {                                          \
            const int j_ = bJ0 + i_;                                              \
            CP_ASYNC16(dstB + (uint32_t)(bSRow * SU + j_ * 4) * 4u,               \
                       Bh + (size_t)bSRow * Kdim + k0_ + j_ * 8);                 \
        }                                                                         \
        CP_COMMIT();                                                              \
    } while (0)

    HG_ISSUE(0);

    for (int c = 0; c < NC; c++) {
        const int buf = c & 1;
        CP_WAIT0();
        __syncthreads();
        if (c + 1 < NC) HG_ISSUE(c + 1);

        #pragma unroll
        for (int ks = 0; ks < 4; ks++) {
            uint32_t bf[4][2];
            #pragma unroll
            for (int p = 0; p < 2; p++) {
                LDSM_X4(bf[2 * p][0], bf[2 * p][1], bf[2 * p + 1][0], bf[2 * p + 1][1],
                        bAddr[buf] + (uint32_t)(p * 16 * SU * 4 + ks * 32));
            }
            #pragma unroll
            for (int mf = 0; mf < 4; mf++) {
                uint32_t a0, a1, a2, a3;
                LDSM_X4(a0, a1, a2, a3,
                        aAddr[buf] + (uint32_t)(mf * 16 * SU * 4 + ks * 32));
                #pragma unroll
                for (int nf = 0; nf < 4; nf++)
                    mma_f16(acc[mf][nf], a0, a1, a2, a3, bf[nf][0], bf[nf][1]);
            }
        }
    }

    if (WHICH == 1) {
        __half* Ao = g_acth + (size_t)(e * CAP + m0) * I_DIM;
        #pragma unroll
        for (int mf = 0; mf < 4; mf++) {
            const int row = warp_m + mf * 16 + g;
            #pragma unroll
            for (int pr = 0; pr < 2; pr++) {
                const int j = n0 / 2 + ((wid & 3) * 2 + pr) * 8 + t4 * 2;
                const float* gg = acc[mf][2 * pr];
                const float* uu = acc[mf][2 * pr + 1];
                const float a0 = gg[0] / (1.f + expf(-gg[0])) * uu[0];
                const float a1 = gg[1] / (1.f + expf(-gg[1])) * uu[1];
                const float a2 = gg[2] / (1.f + expf(-gg[2])) * uu[2];
                const float a3 = gg[3] / (1.f + expf(-gg[3])) * uu[3];
                *(uint32_t*)(Ao + (size_t)row * I_DIM + j)       = pack_h2(a0, a1);
                *(uint32_t*)(Ao + (size_t)(row + 8) * I_DIM + j) = pack_h2(a2, a3);
            }
        }
    } else {
        float* C = g_eout + (size_t)(e * CAP + m0) * Ndim + n0;
        #pragma unroll
        for (int mf = 0; mf < 4; mf++) {
            const int row = warp_m + mf * 16 + g;
            #pragma unroll
            for (int nf = 0; nf < 4; nf++) {
                const int col = warp_n + nf * 8 + t4 * 2;
                *(float2*)(C + (size_t)row * Ndim + col) =
                    make_float2(acc[mf][nf][0], acc[mf][nf][1]);
                *(float2*)(C + (size_t)(row + 8) * Ndim + col) =
                    make_float2(acc[mf][nf][2], acc[mf][nf][3]);
            }
        }
    }
}

// ---------------- gather + combine ----------------
__global__ void gather_kernel(float* __restrict__ out) {
    const int t    = (blockIdx.x * blockDim.x + threadIdx.x) >> 5;
    const int lane = threadIdx.x & 31;
    if (t >= T_TOK) return;
    const int s0 = 2 * t, s1 = s0 + 1;
    const int sl0 = g_slot[s0], sl1 = g_slot[s1];
    const float w0 = g_comb[s0], w1 = g_comb[s1];
    const float4* r0 = (sl0 >= 0) ? (const float4*)(g_eout + (size_t)sl0 * D_DIM) : nullptr;
    const float4* r1 = (sl1 >= 0) ? (const float4*)(g_eout + (size_t)sl1 * D_DIM) : nullptr;
    float4* orow = (float4*)(out + (size_t)t * D_DIM);
    #pragma unroll
    for (int ii = 0; ii < 8; ii++) {
        const int i = lane + 32 * ii;
        float4 a = make_float4(0.f, 0.f, 0.f, 0.f);
        if (r0) { float4 v = r0[i]; a.x += w0 * v.x; a.y += w0 * v.y; a.z += w0 * v.z; a.w += w0 * v.w; }
        if (r1) { float4 v = r1[i]; a.x += w1 * v.x; a.y += w1 * v.y; a.z += w1 * v.z; a.w += w1 * v.w; }
        orow[i] = a;
    }
}

// ---------------- final scalars ----------------
__global__ __launch_bounds__(256) void finalize_kernel(float* __restrict__ out) {
    __shared__ float sp[16][E_EXP];
    __shared__ float sz[256];
    __shared__ float s_sum[E_EXP];
    const int tid = threadIdx.x;
    const int e = tid & 15, p = tid >> 4;

    float s = 0.f;
    for (int b = p; b < RBLK; b += 16) s += g_rp[b][e];
    sp[p][e] = s;
    float zz = 0.f;
    for (int b = tid; b < RBLK; b += 256) zz += g_rz[b];
    sz[tid] = zz;
    __syncthreads();

    if (tid < E_EXP) {
        float tsum = 0.f;
        #pragma unroll
        for (int p2 = 0; p2 < 16; p2++) tsum += sp[p2][tid];
        s_sum[tid] = tsum;
    }
    if (tid == 16) {
        float t = 0.f;
        for (int i = 0; i < 256; i++) t += sz[i];
        sz[0] = t;
    }
    __syncthreads();

    const size_t base = (size_t)T_TOK * D_DIM;
    if (tid < E_EXP) out[base + tid] = (float)g_cnt[tid];
    if (tid == 0) {
        float total = 0.f;
        #pragma unroll
        for (int ee = 0; ee < E_EXP; ee++) total += (float)g_cnt[ee];
        total = fmaxf(total, 1.f);
        float ent = 0.f, lb = 0.f;
        #pragma unroll
        for (int ee = 0; ee < E_EXP; ee++) {
            float f = (float)g_cnt[ee] / total;
            ent -= f * logf(f + 1e-6f);
            lb  += (f * 2.0f) * (s_sum[ee] / (float)T_TOK);
        }
        lb *= (float)E_EXP;
        out[base + 16] = ent;
        out[base + 17] = lb;
        out[base + 18] = sz[0] / (float)T_TOK;
    }
}

// ---------------- launch ----------------
extern "C" void kernel_launch(void* const* d_in, const int* in_sizes, int n_in,
                              void* d_out, int out_size) {
    const float* x      = (const float*)d_in[0];
    const float* router = (const float*)d_in[1];
    const float* w_ug   = (const float*)d_in[2];
    const float* w_dn   = (const float*)d_in[3];
    float* out = (float*)d_out;

    __half *wug_t = nullptr, *wdn_t = nullptr;
    cudaGetSymbolAddress((void**)&wug_t, g_wug_th);
    cudaGetSymbolAddress((void**)&wdn_t, g_wdn_th);

    static bool attr_done = false;
    if (!attr_done) {
        cudaFuncSetAttribute(router_kernel, cudaFuncAttributeMaxDynamicSharedMemorySize, R_SMEM_BYTES);
        cudaFuncSetAttribute(hgemm_kernel<D_DIM, TWO_I, 1>,
                             cudaFuncAttributeMaxDynamicSharedMemorySize, HG_SMEM);
        cudaFuncSetAttribute(hgemm_kernel<I_DIM, D_DIM, 2>,
                             cudaFuncAttributeMaxDynamicSharedMemorySize, HG_SMEM);
        attr_done = true;
    }

    router_kernel<<<RBLK, 256, R_SMEM_BYTES>>>(x, router);          // 0
    pos_kernel<<<NB, 256>>>();                                      // 1
    prep_kernel<<<PREP_BLOCKS, 256>>>(x, w_ug, w_dn);               // 2
    hgemm_kernel<D_DIM, TWO_I, 1>                                   // 3 (ncu)
        <<<dim3(TWO_I / 128, CAP / 256, E_EXP), 512, HG_SMEM>>>(wug_t);
    hgemm_kernel<I_DIM, D_DIM, 2>                                   // 4
        <<<dim3(D_DIM / 128, CAP / 256, E_EXP), 512, HG_SMEM>>>(wdn_t);
    gather_kernel<<<T_TOK / 8, 256>>>(out);                         // 5
    finalize_kernel<<<1, 256>>>(out);                               // 6
}

// round 13
// speedup vs baseline: 2.1680x; 1.0012x over previous
#include <cuda_runtime.h>
#include <cuda_fp16.h>
#include <math.h>
#include <stdint.h>

// ---------------- problem constants ----------------
#define T_TOK   32768
#define D_DIM   1024
#define E_EXP   16
#define I_DIM   2816
#define TWO_I   5632
#define TK_SLOTS 65536
#define CAP     5120
#define NB      64
#define SPB     1024
#define RBLK    1024

// ---------------- scratch (device globals; no allocs) ----------------
__device__ __half g_xh[(size_t)E_EXP * CAP * D_DIM];
__device__ __half g_acth[(size_t)E_EXP * CAP * I_DIM];
__device__ __half g_eouth[(size_t)E_EXP * CAP * D_DIM];    // fp16 expert output
__device__ __half g_wug_th[(size_t)E_EXP * TWO_I * D_DIM];
__device__ __half g_wdn_th[(size_t)E_EXP * D_DIM * I_DIM];
__device__ int   g_sel[TK_SLOTS];
__device__ float g_comb[TK_SLOTS];
__device__ int   g_poslocal[TK_SLOTS];
__device__ int   g_slot[TK_SLOTS];
__device__ int   g_blkCnt[NB][E_EXP];
__device__ int   g_blkOff[NB][E_EXP];
__device__ int   g_cnt[E_EXP];
__device__ float g_rp[RBLK][E_EXP];
__device__ float g_rz[RBLK];
__device__ int   g_posDone;

// ---------------- helpers ----------------
__device__ __forceinline__ void mma_f16(float* c,
                                        uint32_t a0, uint32_t a1, uint32_t a2, uint32_t a3,
                                        uint32_t b0, uint32_t b1) {
    asm volatile("mma.sync.aligned.m16n8k16.row.col.f32.f16.f16.f32 "
                 "{%0,%1,%2,%3}, {%4,%5,%6,%7}, {%8,%9}, {%0,%1,%2,%3};"
                 : "+f"(c[0]), "+f"(c[1]), "+f"(c[2]), "+f"(c[3])
                 : "r"(a0), "r"(a1), "r"(a2), "r"(a3), "r"(b0), "r"(b1));
}
__device__ __forceinline__ uint32_t pack_h2(float a, float b) {
    __half2 h = __floats2half2_rn(a, b);
    return *reinterpret_cast<uint32_t*>(&h);
}
__device__ __forceinline__ uint32_t smem_u32(const void* p) {
    uint32_t a;
    asm("{ .reg .u64 t; cvta.to.shared.u64 t, %1; cvt.u32.u64 %0, t; }" : "=r"(a) : "l"(p));
    return a;
}
#define LDSM_X4(r0_, r1_, r2_, r3_, addr_) \
    asm volatile("ldmatrix.sync.aligned.m8n8.x4.shared.b16 {%0,%1,%2,%3}, [%4];" \
                 : "=r"(r0_), "=r"(r1_), "=r"(r2_), "=r"(r3_) : "r"(addr_))
#define CP_ASYNC16(dst_u32, src_ptr) \
    asm volatile("cp.async.cg.shared.global [%0], [%1], 16;" :: "r"(dst_u32), "l"(src_ptr))
#define CP_COMMIT()  asm volatile("cp.async.commit_group;")
#define CP_WAIT1()   asm volatile("cp.async.wait_group 1;")

// ---------------- router ----------------
#define R_PAD 20
#define R_SMEM_BYTES (D_DIM * R_PAD * 4)
__global__ __launch_bounds__(256) void router_kernel(const float* __restrict__ x,
                                                     const float* __restrict__ router) {
    extern __shared__ float rs[];
    __shared__ float s_p[E_EXP];
    __shared__ float s_z2;
    const int tid  = threadIdx.x;
    const int wid  = tid >> 5;
    const int lane = tid & 31;
    if (tid < E_EXP) s_p[tid] = 0.f;
    if (tid == 0)    s_z2 = 0.f;
    for (int t = tid; t < D_DIM * E_EXP; t += 256)
        rs[(t >> 4) * R_PAD + (t & 15)] = router[t];
    __syncthreads();

    #pragma unroll
    for (int j = 0; j < 4; j++) {
        const int tok = blockIdx.x * 32 + wid * 4 + j;
        const float* xr = x + (size_t)tok * D_DIM;
        float acc[E_EXP];
        #pragma unroll
        for (int e = 0; e < E_EXP; e++) acc[e] = 0.f;
        for (int i = lane; i < D_DIM; i += 32) {
            const float xv = xr[i];
            const float4* rp = (const float4*)&rs[i * R_PAD];
            float4 r0 = rp[0], r1 = rp[1], r2 = rp[2], r3 = rp[3];
            acc[0]  += xv * r0.x; acc[1]  += xv * r0.y; acc[2]  += xv * r0.z; acc[3]  += xv * r0.w;
            acc[4]  += xv * r1.x; acc[5]  += xv * r1.y; acc[6]  += xv * r1.z; acc[7]  += xv * r1.w;
            acc[8]  += xv * r2.x; acc[9]  += xv * r2.y; acc[10] += xv * r2.z; acc[11] += xv * r2.w;
            acc[12] += xv * r3.x; acc[13] += xv * r3.y; acc[14] += xv * r3.z; acc[15] += xv * r3.w;
        }
        #pragma unroll
        for (int off = 16; off; off >>= 1) {
            #pragma unroll
            for (int e = 0; e < E_EXP; e++)
                acc[e] += __shfl_xor_sync(0xffffffffu, acc[e], off);
        }
        float m = acc[0];
        #pragma unroll
        for (int e = 1; e < E_EXP; e++) m = fmaxf(m, acc[e]);
        float se = 0.f;
        #pragma unroll
        for (int e = 0; e < E_EXP; e++) se += expf(acc[e] - m);
        const float z = m + logf(se);

        int i1 = 0; float l1 = acc[0];
        #pragma unroll
        for (int e = 1; e < E_EXP; e++) if (acc[e] > l1) { l1 = acc[e]; i1 = e; }
        int i2 = -1; float l2 = -1e30f;
        #pragma unroll
        for (int e = 0; e < E_EXP; e++)
            if (e != i1 && acc[e] > l2) { l2 = acc[e]; i2 = e; }

        const float q  = expf(l2 - l1);
        if (lane == 0) {
            g_sel[2 * tok]     = i1;
            g_sel[2 * tok + 1] = i2;
            g_comb[2 * tok]     = 1.f / (1.f + q);
            g_comb[2 * tok + 1] = q / (1.f + q);
            atomicAdd(&s_z2, z * z);
        }
        if (lane < E_EXP) atomicAdd(&s_p[lane], expf(acc[lane] - m) / se);
    }
    __syncthreads();
    if (tid < E_EXP) g_rp[blockIdx.x][tid] = s_p[tid];
    if (tid == 0)    g_rz[blockIdx.x] = s_z2;
}

// ---------------- ordered per-expert rank + fused last-block scan ----------------
__global__ void pos_kernel() {
    __shared__ int warpCnt[8][E_EXP];
    __shared__ int running[E_EXP];
    __shared__ int s_last;
    const int tid  = threadIdx.x;
    const int wid  = tid >> 5;
    const int lane = tid & 31;
    if (tid < E_EXP) running[tid] = 0;
    __syncthreads();

    const int base = blockIdx.x * SPB;
    for (int it = 0; it < SPB / 256; it++) {
        const int s = base + it * 256 + tid;
        const int e = g_sel[s];
        unsigned peers = __match_any_sync(0xffffffffu, e);
        const int rank = __popc(peers & ((1u << lane) - 1u));
        if (lane < E_EXP) warpCnt[wid][lane] = 0;
        __syncwarp();
        if (rank == 0) warpCnt[wid][e] = __popc(peers);
        __syncthreads();
        int off = running[e] + rank;
        for (int w = 0; w < wid; w++) off += warpCnt[w][e];
        g_poslocal[s] = off;
        __syncthreads();
        if (tid < E_EXP) {
            int tot = 0;
            #pragma unroll
            for (int w = 0; w < 8; w++) tot += warpCnt[w][tid];
            running[tid] += tot;
        }
        __syncthreads();
    }
    if (tid < E_EXP) g_blkCnt[blockIdx.x][tid] = running[tid];
    __syncthreads();
    if (tid == 0) {
        __threadfence();
        s_last = (atomicAdd(&g_posDone, 1) == NB - 1) ? 1 : 0;
    }
    __syncthreads();
    if (s_last) {
        if (tid < E_EXP) {
            int run = 0;
            for (int b = 0; b < NB; b++) {
                g_blkOff[b][tid] = run;
                run += g_blkCnt[b][tid];
            }
            g_cnt[tid] = run;
        }
        __syncthreads();
        if (tid == 0) { g_posDone = 0; __threadfence(); }
    }
}

// ---------------- prep: scatter + both weight transposes ----------------
#define SC_BLOCKS 8192
#define UG_BX (TWO_I / 32)
#define UG_BY (D_DIM / 32)
#define UG_BLOCKS (UG_BX * UG_BY * E_EXP)
#define DN_BX (D_DIM / 32)
#define DN_BY (I_DIM / 32)
#define DN_BLOCKS (DN_BX * DN_BY * E_EXP)
#define PREP_BLOCKS (SC_BLOCKS + UG_BLOCKS + DN_BLOCKS)

__global__ __launch_bounds__(256) void prep_kernel(const float* __restrict__ x,
                                                   const float* __restrict__ w_ug,
                                                   const float* __restrict__ w_dn) {
    __shared__ float tile[32][33];
    const int bid = blockIdx.x;
    const int tid = threadIdx.x;

    if (bid < SC_BLOCKS) {
        const int gwarp = (bid * 256 + tid) >> 5;
        const int lane  = tid & 31;
        const int e   = g_sel[gwarp];
        const int pos = g_poslocal[gwarp] + g_blkOff[gwarp / SPB][e];
        int slot = -1;
        if (pos < CAP) {
            slot = e * CAP + pos;
            const float4* src = (const float4*)(x + (size_t)(gwarp >> 1) * D_DIM);
            uint2* dst = (uint2*)(g_xh + (size_t)slot * D_DIM);
            #pragma unroll
            for (int i = 0; i < 8; i++) {
                float4 v = src[lane + 32 * i];
                dst[lane + 32 * i] = make_uint2(pack_h2(v.x, v.y), pack_h2(v.z, v.w));
            }
        }
        if (lane == 0) g_slot[gwarp] = slot;
        return;
    }

    const int tx = tid & 31, ty = tid >> 5;
    if (bid < SC_BLOCKS + UG_BLOCKS) {
        const int t = bid - SC_BLOCKS;
        const int z = t / (UG_BX * UG_BY);
        const int rem = t % (UG_BX * UG_BY);
        const int bx = rem % UG_BX, by = rem / UG_BX;
        const float* S = w_ug + (size_t)z * D_DIM * TWO_I;
        __half* Dp = g_wug_th + (size_t)z * TWO_I * D_DIM;
        const int c0 = bx * 32, r0 = by * 32;
        #pragma unroll
        for (int i = 0; i < 32; i += 8)
            tile[ty + i][tx] = S[(size_t)(r0 + ty + i) * TWO_I + (c0 + tx)];
        __syncthreads();
        #pragma unroll
        for (int i = 0; i < 32; i += 8) {
            const int c = c0 + ty + i;
            int pcol;
            if (c < I_DIM) pcol = 16 * (c >> 3) + (c & 7);
            else { const int j = c - I_DIM; pcol = 16 * (j >> 3) + 8 + (j & 7); }
            Dp[(size_t)pcol * D_DIM + (r0 + tx)] = __float2half_rn(tile[tx][ty + i]);
        }
    } else {
        const int t = bid - SC_BLOCKS - UG_BLOCKS;
        const int z = t / (DN_BX * DN_BY);
        const int rem = t % (DN_BX * DN_BY);
        const int bx = rem % DN_BX, by = rem / DN_BX;
        const float* S = w_dn + (size_t)z * I_DIM * D_DIM;
        __half* Dp = g_wdn_th + (size_t)z * D_DIM * I_DIM;
        const int c0 = bx * 32, r0 = by * 32;
        #pragma unroll
        for (int i = 0; i < 32; i += 8)
            tile[ty + i][tx] = S[(size_t)(r0 + ty + i) * D_DIM + (c0 + tx)];
        __syncthreads();
        #pragma unroll
        for (int i = 0; i < 32; i += 8)
            Dp[(size_t)(c0 + ty + i) * I_DIM + (r0 + tx)] = __float2half_rn(tile[tx][ty + i]);
    }
}

// ---------------- fp16 mma GEMM: CTA 256x128, 512 threads, cp.async 3-stage, K-chunk 64 ----
#define SU 36
#define A_TILE_U (256 * SU)
#define B_TILE_U (128 * SU)
#define BUF_U  (A_TILE_U + B_TILE_U)
#define HG_SMEM (3 * BUF_U * 4)           // 165888 bytes

template <int Kdim, int Ndim, int WHICH>
__global__ __launch_bounds__(512, 1)
void hgemm_kernel(const __half* __restrict__ Wt) {
    const int e   = blockIdx.z;
    const int cnt = g_cnt[e];
    const int m0  = blockIdx.y * 256;
    if (m0 >= cnt) return;
    const int n0  = blockIdx.x * 128;

    const __half* __restrict__ Ah = ((WHICH == 1) ? g_xh : g_acth)
                                    + (size_t)e * CAP * Kdim + (size_t)m0 * Kdim;
    const __half* __restrict__ Bh = Wt + (size_t)e * Ndim * Kdim + (size_t)n0 * Kdim;

    extern __shared__ uint32_t smem[];
    const uint32_t smem_base = smem_u32(smem);

    const int tid  = threadIdx.x;
    const int lane = tid & 31;
    const int wid  = tid >> 5;
    const int warp_m = (wid >> 2) * 64;
    const int warp_n = (wid & 3) * 32;
    const int g  = lane >> 2;
    const int t4 = lane & 3;

    float acc[4][4][4];
    #pragma unroll
    for (int i = 0; i < 4; i++)
        #pragma unroll
        for (int j = 0; j < 4; j++)
            #pragma unroll
            for (int q = 0; q < 4; q++) acc[i][j][q] = 0.f;

    const int aSRow = tid >> 1;
    const int aJ0   = (tid & 1) * 4;
    const int bSRow = tid >> 2;
    const int bJ0   = (tid & 3) * 2;

    const int aRow = warp_m + (lane & 15);
    const int aOff = 4 * (lane >> 4);
    const int bRow = warp_n + 8 * ((lane >> 4) & 1) + (lane & 7);
    const int bOff = 4 * ((lane >> 3) & 1);
    const uint32_t aBase = smem_base + (uint32_t)(aRow * SU + aOff) * 4u;
    const uint32_t bBase = smem_base + (uint32_t)(A_TILE_U + bRow * SU + bOff) * 4u;

    const int NC = Kdim / 64;

    // issues chunk c_ into stage c_%3 (guarded), ALWAYS commits a group
    #define HG_ISSUE(c_) do {                                                     \
        if ((c_) < NC) {                                                          \
            const uint32_t dstA = smem_base + (uint32_t)(((c_) % 3) * BUF_U) * 4u;\
            const uint32_t dstB = dstA + (uint32_t)A_TILE_U * 4u;                 \
            const int k0_ = (c_) * 64;                                            \
            _Pragma("unroll")                                                     \
            for (int i_ = 0; i_ < 4; i_++) {                                      \
                const int j_ = aJ0 + i_;                                          \
                CP_ASYNC16(dstA + (uint32_t)(aSRow * SU + j_ * 4) * 4u,           \
                           Ah + (size_t)aSRow * Kdim + k0_ + j_ * 8);             \
            }                                                                     \
            _Pragma("unroll")                                                     \
            for (int i_ = 0; i_ < 2; i_++) {                                      \
                const int j_ = bJ0 + i_;                                          \
                CP_ASYNC16(dstB + (uint32_t)(bSRow * SU + j_ * 4) * 4u,           \
                           Bh + (size_t)bSRow * Kdim + k0_ + j_ * 8);             \
            }                                                                     \
        }                                                                         \
        CP_COMMIT();                                                              \
    } while (0)

    HG_ISSUE(0);
    HG_ISSUE(1);

    for (int c = 0; c < NC; c++) {
        CP_WAIT1();                       // group c complete (c+1 may be in flight)
        __syncthreads();
        HG_ISSUE(c + 2);                  // into stage (c+2)%3 = (c-1)%3 (compute done)
        const uint32_t bufOff = (uint32_t)((c % 3) * BUF_U) * 4u;

        #pragma unroll
        for (int ks = 0; ks < 4; ks++) {
            uint32_t bf[4][2];
            #pragma unroll
            for (int p = 0; p < 2; p++) {
                LDSM_X4(bf[2 * p][0], bf[2 * p][1], bf[2 * p + 1][0], bf[2 * p + 1][1],
                        bBase + bufOff + (uint32_t)(p * 16 * SU * 4 + ks * 32));
            }
            #pragma unroll
            for (int mf = 0; mf < 4; mf++) {
                uint32_t a0, a1, a2, a3;
                LDSM_X4(a0, a1, a2, a3,
                        aBase + bufOff + (uint32_t)(mf * 16 * SU * 4 + ks * 32));
                #pragma unroll
                for (int nf = 0; nf < 4; nf++)
                    mma_f16(acc[mf][nf], a0, a1, a2, a3, bf[nf][0], bf[nf][1]);
            }
        }
    }

    if (WHICH == 1) {
        __half* Ao = g_acth + (size_t)(e * CAP + m0) * I_DIM;
        #pragma unroll
        for (int mf = 0; mf < 4; mf++) {
            const int row = warp_m + mf * 16 + g;
            #pragma unroll
            for (int pr = 0; pr < 2; pr++) {
                const int j = n0 / 2 + ((wid & 3) * 2 + pr) * 8 + t4 * 2;
                const float* gg = acc[mf][2 * pr];
                const float* uu = acc[mf][2 * pr + 1];
                const float a0 = gg[0] / (1.f + expf(-gg[0])) * uu[0];
                const float a1 = gg[1] / (1.f + expf(-gg[1])) * uu[1];
                const float a2 = gg[2] / (1.f + expf(-gg[2])) * uu[2];
                const float a3 = gg[3] / (1.f + expf(-gg[3])) * uu[3];
                *(uint32_t*)(Ao + (size_t)row * I_DIM + j)       = pack_h2(a0, a1);
                *(uint32_t*)(Ao + (size_t)(row + 8) * I_DIM + j) = pack_h2(a2, a3);
            }
        }
    } else {
        __half* Co = g_eouth + (size_t)(e * CAP + m0) * Ndim + n0;
        #pragma unroll
        for (int mf = 0; mf < 4; mf++) {
            const int row = warp_m + mf * 16 + g;
            #pragma unroll
            for (int nf = 0; nf < 4; nf++) {
                const int col = warp_n + nf * 8 + t4 * 2;
                *(uint32_t*)(Co + (size_t)row * Ndim + col) =
                    pack_h2(acc[mf][nf][0], acc[mf][nf][1]);
                *(uint32_t*)(Co + (size_t)(row + 8) * Ndim + col) =
                    pack_h2(acc[mf][nf][2], acc[mf][nf][3]);
            }
        }
    }
}

// ---------------- gather + combine (fp16 expert outputs) ----------------
__global__ void gather_kernel(float* __restrict__ out) {
    const int t    = (blockIdx.x * blockDim.x + threadIdx.x) >> 5;
    const int lane = threadIdx.x & 31;
    if (t >= T_TOK) return;
    const int s0 = 2 * t, s1 = s0 + 1;
    const int sl0 = g_slot[s0], sl1 = g_slot[s1];
    const float w0 = g_comb[s0], w1 = g_comb[s1];
    const uint2* r0 = (sl0 >= 0) ? (const uint2*)(g_eouth + (size_t)sl0 * D_DIM) : nullptr;
    const uint2* r1 = (sl1 >= 0) ? (const uint2*)(g_eouth + (size_t)sl1 * D_DIM) : nullptr;
    float4* orow = (float4*)(out + (size_t)t * D_DIM);
    #pragma unroll
    for (int ii = 0; ii < 8; ii++) {
        const int i = lane + 32 * ii;
        float4 a = make_float4(0.f, 0.f, 0.f, 0.f);
        if (r0) {
            uint2 v = r0[i];
            float2 p0 = __half22float2(*(__half2*)&v.x);
            float2 p1 = __half22float2(*(__half2*)&v.y);
            a.x += w0 * p0.x; a.y += w0 * p0.y; a.z += w0 * p1.x; a.w += w0 * p1.y;
        }
        if (r1) {
            uint2 v = r1[i];
            float2 p0 = __half22float2(*(__half2*)&v.x);
            float2 p1 = __half22float2(*(__half2*)&v.y);
            a.x += w1 * p0.x; a.y += w1 * p0.y; a.z += w1 * p1.x; a.w += w1 * p1.y;
        }
        orow[i] = a;
    }
}

// ---------------- final scalars ----------------
__global__ __launch_bounds__(256) void finalize_kernel(float* __restrict__ out) {
    __shared__ float sp[16][E_EXP];
    __shared__ float sz[256];
    __shared__ float s_sum[E_EXP];
    const int tid = threadIdx.x;
    const int e = tid & 15, p = tid >> 4;

    float s = 0.f;
    for (int b = p; b < RBLK; b += 16) s += g_rp[b][e];
    sp[p][e] = s;
    float zz = 0.f;
    for (int b = tid; b < RBLK; b += 256) zz += g_rz[b];
    sz[tid] = zz;
    __syncthreads();

    if (tid < E_EXP) {
        float tsum = 0.f;
        #pragma unroll
        for (int p2 = 0; p2 < 16; p2++) tsum += sp[p2][tid];
        s_sum[tid] = tsum;
    }
    if (tid == 16) {
        float t = 0.f;
        for (int i = 0; i < 256; i++) t += sz[i];
        sz[0] = t;
    }
    __syncthreads();

    const size_t base = (size_t)T_TOK * D_DIM;
    if (tid < E_EXP) out[base + tid] = (float)g_cnt[tid];
    if (tid == 0) {
        float total = 0.f;
        #pragma unroll
        for (int ee = 0; ee < E_EXP; ee++) total += (float)g_cnt[ee];
        total = fmaxf(total, 1.f);
        float ent = 0.f, lb = 0.f;
        #pragma unroll
        for (int ee = 0; ee < E_EXP; ee++) {
            float f = (float)g_cnt[ee] / total;
            ent -= f * logf(f + 1e-6f);
            lb  += (f * 2.0f) * (s_sum[ee] / (float)T_TOK);
        }
        lb *= (float)E_EXP;
        out[base + 16] = ent;
        out[base + 17] = lb;
        out[base + 18] = sz[0] / (float)T_TOK;
    }
}

// ---------------- launch ----------------
extern "C" void kernel_launch(void* const* d_in, const int* in_sizes, int n_in,
                              void* d_out, int out_size) {
    const float* x      = (const float*)d_in[0];
    const float* router = (const float*)d_in[1];
    const float* w_ug   = (const float*)d_in[2];
    const float* w_dn   = (const float*)d_in[3];
    float* out = (float*)d_out;

    __half *wug_t = nullptr, *wdn_t = nullptr;
    cudaGetSymbolAddress((void**)&wug_t, g_wug_th);
    cudaGetSymbolAddress((void**)&wdn_t, g_wdn_th);

    static bool attr_done = false;
    if (!attr_done) {
        cudaFuncSetAttribute(router_kernel, cudaFuncAttributeMaxDynamicSharedMemorySize, R_SMEM_BYTES);
        cudaFuncSetAttribute(hgemm_kernel<D_DIM, TWO_I, 1>,
                             cudaFuncAttributeMaxDynamicSharedMemorySize, HG_SMEM);
        cudaFuncSetAttribute(hgemm_kernel<I_DIM, D_DIM, 2>,
                             cudaFuncAttributeMaxDynamicSharedMemorySize, HG_SMEM);
        attr_done = true;
    }

    router_kernel<<<RBLK, 256, R_SMEM_BYTES>>>(x, router);          // 0
    pos_kernel<<<NB, 256>>>();                                      // 1
    prep_kernel<<<PREP_BLOCKS, 256>>>(x, w_ug, w_dn);               // 2
    hgemm_kernel<D_DIM, TWO_I, 1>                                   // 3 (ncu)
        <<<dim3(TWO_I / 128, CAP / 256, E_EXP), 512, HG_SMEM>>>(wug_t);
    hgemm_kernel<I_DIM, D_DIM, 2>                                   // 4
        <<<dim3(D_DIM / 128, CAP / 256, E_EXP), 512, HG_SMEM>>>(wdn_t);
    gather_kernel<<<T_TOK / 8, 256>>>(out);                         // 5
    finalize_kernel<<<1, 256>>>(out);                               // 6
}